// round 8
// baseline (speedup 1.0000x reference)
#include <cuda_runtime.h>
#include <math.h>

#define Nn 10000
#define Ee 160000
#define ETOT (Ee + Nn)
#define IND 512
#define Cc 128
#define NCc 40
#define NLAY 4
#define HE 8
#define GR 16
#define KT 16
#define DKk 16

// ------------------------- scratch (device globals; no allocations) ---------
__device__ float g_xall[Nn * 5 * Cc];   // x_all levels 0..4
__device__ float g_q[Nn * Cc];
__device__ float g_k[Nn * 4 * Cc];      // levels 0..3
__device__ float g_v[Nn * 4 * Cc];
__device__ int   g_cnt[Nn];             // in-degree incl self loop
__device__ float g_dinv[Nn];
__device__ float g_norm[ETOT];
__device__ int   g_off[Nn + 1];
__device__ int   g_cur[Nn];
__device__ int   g_eid[ETOT];
__device__ float g_en[Nn * Cc];
__device__ float g_plc[Nn * NCc];
__device__ float g_tval[Nn * KT];
__device__ int   g_tidx[Nn * KT];

// ------------------------- 1) h0 = relu(x @ W1 + b1) ------------------------
__global__ __launch_bounds__(256) void gemm1_relu_kernel(
    const float* __restrict__ x, const float* __restrict__ W1,
    const float* __restrict__ b1) {
  __shared__ float xs[32][65];    // xs[k][m], 64 rows
  __shared__ float ws[32][128];
  int m0 = blockIdx.x * 64;
  int tid = threadIdx.x;
  int tc = tid & 15;   // 16 col-groups of 8
  int tr = tid >> 4;   // 16 row-groups of 4
  float acc[4][8];
#pragma unroll
  for (int r = 0; r < 4; r++)
#pragma unroll
    for (int c = 0; c < 8; c++) acc[r][c] = 0.f;

  for (int k0 = 0; k0 < IND; k0 += 32) {
    for (int i = tid; i < 64 * 32; i += 256) {
      int m = i >> 5, k = i & 31;
      int row = m0 + m;
      xs[k][m] = (row < Nn) ? x[row * IND + k0 + k] : 0.f;
    }
    for (int i = tid; i < 32 * 128; i += 256) {
      int k = i >> 7, c = i & 127;
      ws[k][c] = W1[(k0 + k) * Cc + c];
    }
    __syncthreads();
#pragma unroll
    for (int k = 0; k < 32; k++) {
      float xv[4], wv[8];
#pragma unroll
      for (int r = 0; r < 4; r++) xv[r] = xs[k][tr * 4 + r];
#pragma unroll
      for (int c = 0; c < 8; c++) wv[c] = ws[k][tc * 8 + c];
#pragma unroll
      for (int r = 0; r < 4; r++)
#pragma unroll
        for (int c = 0; c < 8; c++) acc[r][c] = fmaf(xv[r], wv[c], acc[r][c]);
    }
    __syncthreads();
  }
#pragma unroll
  for (int r = 0; r < 4; r++) {
    int row = m0 + tr * 4 + r;
    if (row < Nn) {
#pragma unroll
      for (int c = 0; c < 8; c++) {
        int col = tc * 8 + c;
        float v = acc[r][c] + b1[col];
        g_xall[row * 5 * Cc + col] = v > 0.f ? v : 0.f;   // level 0
      }
    }
  }
}

// ------------------------- 2) gcn_norm + CSR build (deterministic) ----------
__global__ void count_kernel(const int* __restrict__ coli) {
  int e = blockIdx.x * blockDim.x + threadIdx.x;
  if (e >= ETOT) return;
  int c = (e < Ee) ? coli[e] : (e - Ee);
  atomicAdd(&g_cnt[c], 1);
}

__global__ void dinv_kernel() {
  int n = blockIdx.x * blockDim.x + threadIdx.x;
  if (n < Nn) g_dinv[n] = 1.0f / sqrtf((float)g_cnt[n]);
}

__global__ void norm_kernel(const int* __restrict__ rowi,
                            const int* __restrict__ coli) {
  int e = blockIdx.x * blockDim.x + threadIdx.x;
  if (e >= ETOT) return;
  if (e < Ee) g_norm[e] = g_dinv[rowi[e]] * g_dinv[coli[e]];
  else { float d = g_dinv[e - Ee]; g_norm[e] = d * d; }
}

// single-block exclusive scan of g_cnt -> g_off (1024 threads, 10 elems each)
__global__ __launch_bounds__(1024) void scan_kernel() {
  __shared__ int ssum[1024];
  int t = threadIdx.x;
  int base = t * 10;
  int loc[10];
  int s = 0;
#pragma unroll
  for (int i = 0; i < 10; i++) {
    int idx = base + i;
    int v = (idx < Nn) ? g_cnt[idx] : 0;
    loc[i] = s;
    s += v;
  }
  ssum[t] = s;
  __syncthreads();
  for (int off = 1; off < 1024; off <<= 1) {
    int v = (t >= off) ? ssum[t - off] : 0;
    __syncthreads();
    ssum[t] += v;
    __syncthreads();
  }
  int pre = (t > 0) ? ssum[t - 1] : 0;
#pragma unroll
  for (int i = 0; i < 10; i++) {
    int idx = base + i;
    if (idx < Nn) g_off[idx] = pre + loc[i];
  }
  if (t == 1023) g_off[Nn] = ssum[1023];
}

__global__ void place_kernel(const int* __restrict__ coli) {
  int e = blockIdx.x * blockDim.x + threadIdx.x;
  if (e >= ETOT) return;
  int c = (e < Ee) ? coli[e] : (e - Ee);
  int pos = atomicAdd(&g_cur[c], 1);
  g_eid[g_off[c] + pos] = e;
}

// canonicalize bucket order: insertion-sort each bucket ascending by edge id.
// Buckets <= 64 staged in shared memory (column-major: conflict-free, ~35 cyc
// per op vs ~234 in L2); rare larger buckets fall back to the global path.
#define SB(i) sbuf[(i) * 128 + tid]
__global__ __launch_bounds__(128) void sort_bucket_kernel() {
  __shared__ int sbuf[64 * 128];
  int tid = threadIdx.x;
  int n = blockIdx.x * 128 + tid;
  if (n >= Nn) return;
  int s = g_off[n], e2 = g_off[n + 1];
  int len = e2 - s;
  if (len <= 64) {
    for (int i = 0; i < len; i++) SB(i) = g_eid[s + i];
    for (int i = 1; i < len; i++) {
      int key = SB(i);
      int j = i - 1;
      while (j >= 0) {
        int v = SB(j);
        if (v <= key) break;
        SB(j + 1) = v;
        j--;
      }
      SB(j + 1) = key;
    }
    for (int i = 0; i < len; i++) g_eid[s + i] = SB(i);
  } else {
    for (int i = s + 1; i < e2; i++) {
      int key = g_eid[i];
      int j = i - 1;
      while (j >= s && g_eid[j] > key) { g_eid[j + 1] = g_eid[j]; j--; }
      g_eid[j + 1] = key;
    }
  }
}

// ------------------------- 3a) grouped q/k/v per layer ---------------------
__global__ __launch_bounds__(128) void qkv_kernel(
    const float* __restrict__ Wq, const float* __restrict__ bq,
    const float* __restrict__ Wk, const float* __restrict__ bk,
    const float* __restrict__ Wv, const float* __restrict__ bv, int l) {
  int n = blockIdx.x;
  int c = threadIdx.x;
  int g = c >> 3, o = c & 7;
  __shared__ float xs[Cc];
  float wq[8], wk[8], wv[8];
  int base = ((l * GR + g) * 8) * 8 + o;
#pragma unroll
  for (int i = 0; i < 8; i++) {
    wq[i] = Wq[base + i * 8];
    wk[i] = Wk[base + i * 8];
    wv[i] = Wv[base + i * 8];
  }
  float bqv = bq[l * Cc + c], bkv = bk[l * Cc + c], bvv = bv[l * Cc + c];
  for (int lev = 0; lev <= l; lev++) {
    __syncthreads();
    xs[c] = g_xall[(n * 5 + lev) * Cc + c];
    __syncthreads();
    float xg[8];
#pragma unroll
    for (int i = 0; i < 8; i++) xg[i] = xs[g * 8 + i];
    float sk = bkv, sv = bvv;
#pragma unroll
    for (int i = 0; i < 8; i++) {
      sk = fmaf(xg[i], wk[i], sk);
      sv = fmaf(xg[i], wv[i], sv);
    }
    g_k[(n * 4 + lev) * Cc + c] = sk;
    g_v[(n * 4 + lev) * Cc + c] = sv;
    if (lev == l) {
      float sq = bqv;
#pragma unroll
      for (int i = 0; i < 8; i++) sq = fmaf(xg[i], wq[i], sq);
      g_q[n * Cc + c] = sq;
    }
  }
}

// ------------------------- 3b) deterministic attention gather --------------
// Edge metadata (src node, norm) staged cooperatively in smem to remove the
// serial g_eid -> rowi -> g_norm pointer chase from the per-edge loop.
template <int NLEV>
__global__ __launch_bounds__(128) void attn_gather_kernel(
    const int* __restrict__ rowi, int l) {
  __shared__ int s_r[64];
  __shared__ float s_nrm[64];
  int c = blockIdx.x;
  int tid = threadIdx.x;
  const unsigned FULL = 0xffffffffu;
  float qv = g_q[c * Cc + tid];
  int s = g_off[c], e2 = g_off[c + 1];
  int len = e2 - s;
  int m = len < 64 ? len : 64;
  for (int i = tid; i < m; i += 128) {
    int e = g_eid[s + i];
    s_r[i] = (e < Ee) ? rowi[e] : (e - Ee);
    s_nrm[i] = g_norm[e];
  }
  __syncthreads();
  float acc = 0.f;
  for (int p = 0; p < len; p++) {
    int r;
    float nrm;
    if (p < 64) { r = s_r[p]; nrm = s_nrm[p]; }
    else {
      int e = g_eid[s + p];
      r = (e < Ee) ? rowi[e] : (e - Ee);
      nrm = g_norm[e];
    }
    float kk[NLEV], vv[NLEV];
#pragma unroll
    for (int lev = 0; lev < NLEV; lev++) {
      kk[lev] = g_k[(r * 4 + lev) * Cc + tid];
      vv[lev] = g_v[(r * 4 + lev) * Cc + tid];
    }
    float sc[NLEV];
    float mx = -1e30f;
#pragma unroll
    for (int lev = 0; lev < NLEV; lev++) {
      float t = qv * kk[lev];
      t += __shfl_xor_sync(FULL, t, 8);
      t += __shfl_xor_sync(FULL, t, 4);
      t += __shfl_xor_sync(FULL, t, 2);
      t += __shfl_xor_sync(FULL, t, 1);
      t *= 0.25f;   // 1/sqrt(DK)
      sc[lev] = t;
      mx = fmaxf(mx, t);
    }
    float den = 0.f;
#pragma unroll
    for (int lev = 0; lev < NLEV; lev++) {
      sc[lev] = expf(sc[lev] - mx);
      den += sc[lev];
    }
    float w = nrm / den;
#pragma unroll
    for (int lev = 0; lev < NLEV; lev++)
      acc = fmaf(sc[lev] * w, vv[lev], acc);
  }
  g_xall[(c * 5 + l + 1) * Cc + tid] = acc > 0.f ? acc : 0.f;
}

// ------------------------- 4) emb out + L2 normalize -----------------------
__global__ __launch_bounds__(128) void emb_norm_kernel(float* __restrict__ out_emb) {
  int n = blockIdx.x;
  int c = threadIdx.x;
  float v = g_xall[(n * 5 + 4) * Cc + c];
  out_emb[n * Cc + c] = v;
  float ss = v * v;
#pragma unroll
  for (int off = 16; off; off >>= 1) ss += __shfl_down_sync(0xffffffffu, ss, off);
  __shared__ float ws[4];
  if ((c & 31) == 0) ws[c >> 5] = ss;
  __syncthreads();
  float tot = ws[0] + ws[1] + ws[2] + ws[3];
  float nrm = fmaxf(sqrtf(tot), 1e-8f);
  g_en[n * Cc + c] = v / nrm;
}

// ------------------------- 5) p_lc = log_softmax(emb@W2+b2) ----------------
__global__ __launch_bounds__(128) void plc_kernel(const float* __restrict__ W2,
                                                  const float* __restrict__ b2) {
  int n = blockIdx.x;
  int t = threadIdx.x;
  __shared__ float xr[Cc];
  __shared__ float lg[NCc];
  __shared__ float red[2];
  xr[t] = g_xall[(n * 5 + 4) * Cc + t];
  __syncthreads();
  if (t < NCc) {
    float s = b2[t];
    for (int k = 0; k < Cc; k++) s = fmaf(xr[k], W2[k * NCc + t], s);
    lg[t] = s;
  }
  __syncthreads();
  if (t == 0) {
    float mx = lg[0];
    for (int i = 1; i < NCc; i++) mx = fmaxf(mx, lg[i]);
    float s = 0.f;
    for (int i = 0; i < NCc; i++) s += expf(lg[i] - mx);
    red[0] = mx;
    red[1] = logf(s);
  }
  __syncthreads();
  if (t < NCc) g_plc[n * NCc + t] = lg[t] - red[0] - red[1];
}

// ------------------------- 6) fused sim = en@en^T + top-16 -----------------
// f32x2 packed-FMA GEMM + threshold-buffer candidate top-k (exact, deterministic)
// v4: grid=296 balanced waves (2 x 148), SROWS=34, mixed per-warp rows
//     (warps 0-5 -> 4 rows, warps 6-7 -> 5 rows) via compile-time template.
#define SROWS 34
#define SGRID 296    // 296 * 34 = 10064 >= Nn, two full waves of 148
#define SCOLS 256
#define CPAD 258
#define CAP 192
#define SIM_SMEM ((128 * CPAD + SROWS * Cc + SROWS * CAP) * 4 + SROWS * CAP * 4 + SROWS * 8)

// exact tie-aware top-16 selection of buf[0..n) into buf[0..15]; updates thr/cnt
__device__ __noinline__ void refresh_row(float* __restrict__ v,
                                         int* __restrict__ ix,
                                         float* __restrict__ thr,
                                         int* __restrict__ cnt,
                                         int rl, int lane) {
  const unsigned FULL = 0xffffffffu;
  int n = cnt[rl];
#pragma unroll 1
  for (int pick = 0; pick < KT; pick++) {
    float mv = -3.4e38f; int mi = 0x7fffffff; int mp = pick;
    for (int s = pick + lane; s < n; s += 32) {
      float vv = v[s]; int ii = ix[s];
      if (vv > mv || (vv == mv && ii < mi)) { mv = vv; mi = ii; mp = s; }
    }
#pragma unroll
    for (int off = 16; off; off >>= 1) {
      float ov = __shfl_down_sync(FULL, mv, off);
      int oi = __shfl_down_sync(FULL, mi, off);
      int op = __shfl_down_sync(FULL, mp, off);
      if (ov > mv || (ov == mv && oi < mi)) { mv = ov; mi = oi; mp = op; }
    }
    mp = __shfl_sync(FULL, mp, 0);
    mv = __shfl_sync(FULL, mv, 0);
    mi = __shfl_sync(FULL, mi, 0);
    if (lane == 0 && mp != pick) {
      float tv = v[pick]; int ti = ix[pick];
      v[pick] = mv; ix[pick] = mi;
      v[mp] = tv; ix[mp] = ti;
    }
    __syncwarp();
  }
  if (lane == 0) { thr[rl] = v[KT - 1]; cnt[rl] = KT; }
  __syncwarp();
}

// one ballot-insert step for a single scalar candidate
#define COLLECT_ONE(val, colofs)                                          \
  do {                                                                    \
    float v_ = (val);                                                     \
    int colx_ = j0 + (colofs) + lane * 2;                                 \
    bool p_ = (colx_ < Nn) && (v_ >= thr_r);                              \
    unsigned mask_ = __ballot_sync(0xffffffffu, p_);                      \
    if (mask_) {                                                          \
      int base_ = cnt[rl];                                                \
      if (p_) {                                                           \
        int pos_ = base_ + __popc(mask_ & ((1u << lane) - 1u));           \
        bv[pos_] = v_;                                                    \
        bi[pos_] = colx_;                                                 \
      }                                                                   \
      int nb_ = base_ + __popc(mask_);                                    \
      if (lane == 0) cnt[rl] = nb_;                                       \
      __syncwarp();                                                       \
      if (nb_ >= CAP - 32) {                                              \
        refresh_row(bv, bi, thr, cnt, rl, lane);                          \
        thr_r = thr[rl];                                                  \
      }                                                                   \
    }                                                                     \
  } while (0)

// candidates for one row: 8 scalars = (c2,t) pairs, values passed by register
__device__ __noinline__ void collect_row(int rl, int j0, int lane,
                                         float4 va, float4 vb,
                                         float* __restrict__ bv,
                                         int* __restrict__ bi,
                                         float* __restrict__ thr,
                                         int* __restrict__ cnt) {
  float thr_r = thr[rl];
  COLLECT_ONE(va.x, 0);        // c2=0, t=0
  COLLECT_ONE(va.y, 1);        // c2=0, t=1
  COLLECT_ONE(va.z, 64);       // c2=1, t=0
  COLLECT_ONE(va.w, 65);       // c2=1, t=1
  COLLECT_ONE(vb.x, 128);      // c2=2, t=0
  COLLECT_ONE(vb.y, 129);      // c2=2, t=1
  COLLECT_ONE(vb.z, 192);      // c2=3, t=0
  COLLECT_ONE(vb.w, 193);      // c2=3, t=1
}

// GEMM + collect for R rows starting at rlbase (R is compile-time so the
// accumulators stay register-resident).
template <int R>
__device__ __forceinline__ void gemm_collect(
    const float* __restrict__ rows, const float* __restrict__ colsT,
    int rlbase, int j0, int lane,
    float* __restrict__ bufv, int* __restrict__ bufi,
    float* __restrict__ thr, int* __restrict__ cnt) {
  unsigned long long acc[R][4];
#pragma unroll
  for (int r = 0; r < R; r++)
#pragma unroll
    for (int c2 = 0; c2 < 4; c2++) acc[r][c2] = 0ULL;

  const float* rowp = rows + rlbase * Cc;
#pragma unroll 4
  for (int k = 0; k < Cc; k++) {
    unsigned long long cv[4];
    const float* cb = colsT + k * CPAD + lane * 2;
#pragma unroll
    for (int c2 = 0; c2 < 4; c2++)
      cv[c2] = *(const unsigned long long*)(cb + c2 * 64);
#pragma unroll
    for (int r = 0; r < R; r++) {
      float rv = rowp[r * Cc + k];
      unsigned long long rv2;
      asm("mov.b64 %0, {%1, %1};" : "=l"(rv2) : "f"(rv));
#pragma unroll
      for (int c2 = 0; c2 < 4; c2++)
        asm("fma.rn.f32x2 %0, %1, %2, %0;"
            : "+l"(acc[r][c2]) : "l"(rv2), "l"(cv[c2]));
    }
  }

#pragma unroll
  for (int r = 0; r < R; r++) {
    int rl = rlbase + r;
    float4 va, vb;
    asm("mov.b64 {%0, %1}, %2;" : "=f"(va.x), "=f"(va.y) : "l"(acc[r][0]));
    asm("mov.b64 {%0, %1}, %2;" : "=f"(va.z), "=f"(va.w) : "l"(acc[r][1]));
    asm("mov.b64 {%0, %1}, %2;" : "=f"(vb.x), "=f"(vb.y) : "l"(acc[r][2]));
    asm("mov.b64 {%0, %1}, %2;" : "=f"(vb.z), "=f"(vb.w) : "l"(acc[r][3]));
    collect_row(rl, j0, lane, va, vb,
                bufv + rl * CAP, bufi + rl * CAP, thr, cnt);
  }
}

__global__ __launch_bounds__(256) void sim_topk_kernel() {
  extern __shared__ float sm[];
  float* colsT = sm;                              // [128][CPAD]
  float* rows  = sm + 128 * CPAD;                 // [SROWS][128]
  float* bufv  = rows + SROWS * Cc;               // [SROWS][CAP]
  int*   bufi  = (int*)(bufv + SROWS * CAP);      // [SROWS][CAP]
  float* thr   = (float*)(bufi + SROWS * CAP);    // [SROWS]
  int*   cnt   = (int*)(thr + SROWS);             // [SROWS]

  int r0 = blockIdx.x * SROWS;
  int tid = threadIdx.x;
  int warp = tid >> 5, lane = tid & 31;
  // warps 0-5 own 4 rows each (0..23); warps 6,7 own 5 rows each (24..33)
  int rlbase = (warp < 6) ? warp * 4 : 24 + (warp - 6) * 5;
  int rpw = (warp < 6) ? 4 : 5;

  for (int i = tid; i < SROWS * Cc; i += 256) {
    int row = r0 + (i >> 7);
    rows[i] = (row < Nn) ? g_en[row * Cc + (i & 127)] : 0.f;
  }
  if (tid < SROWS) { thr[tid] = -3.3e38f; cnt[tid] = 0; }
  __syncthreads();

  int rlocal = lane >> 3;   // 0..3 (row within 4-row group of fill)
  int kc = lane & 7;        // 0..7 (16B k-chunk within quarter)

  for (int j0 = 0; j0 < Nn; j0 += SCOLS) {
    // ---- fill colsT[k][j] (transposed, coalesced float4 loads) ----
#pragma unroll 4
    for (int it = 0; it < 32; it++) {
      int u = it * 8 + warp;          // 256 warp-units
      int rowgrp = u >> 2, kq = u & 3;
      int j = rowgrp * 4 + rlocal;    // 0..255
      int k4 = kq * 8 + kc;           // 0..31
      int col = j0 + j;
      float4 val = make_float4(0.f, 0.f, 0.f, 0.f);
      if (col < Nn) val = ((const float4*)g_en)[col * (Cc / 4) + k4];
      colsT[(k4 * 4 + 0) * CPAD + j] = val.x;
      colsT[(k4 * 4 + 1) * CPAD + j] = val.y;
      colsT[(k4 * 4 + 2) * CPAD + j] = val.z;
      colsT[(k4 * 4 + 3) * CPAD + j] = val.w;
    }
    __syncthreads();

    if (warp < 6)
      gemm_collect<4>(rows, colsT, rlbase, j0, lane, bufv, bufi, thr, cnt);
    else
      gemm_collect<5>(rows, colsT, rlbase, j0, lane, bufv, bufi, thr, cnt);
    __syncthreads();
  }

  // ---- final exact selection + output ----
#pragma unroll 1
  for (int r = 0; r < 5; r++) {
    if (r >= rpw) break;
    int rl = rlbase + r;
    int grow = r0 + rl;
    if (grow >= Nn) continue;
    refresh_row(bufv + rl * CAP, bufi + rl * CAP, thr, cnt, rl, lane);
    if (lane < KT) {
      g_tval[grow * KT + lane] = bufv[rl * CAP + lane];
      g_tidx[grow * KT + lane] = bufi[rl * CAP + lane];
    }
  }
}

// ------------------------- 7) p_sim + final combine (deterministic) --------
__global__ __launch_bounds__(64) void psim_final_kernel(
    const int* __restrict__ y, float* __restrict__ out_final) {
  int n = blockIdx.x;
  int t = threadIdx.x;
  __shared__ float ex[KT];
  __shared__ int cls[KT];
  __shared__ float acc[NCc];
  __shared__ float red[2];
  if (t < KT) {
    ex[t] = expf(g_tval[n * KT + t]);
    cls[t] = y[g_tidx[n * KT + t]];
  }
  __syncthreads();
  if (t < NCc) {
    float s = 0.f;
    for (int j = 0; j < KT; j++)
      if (cls[j] == t) s += ex[j];
    acc[t] = s;
  }
  __syncthreads();
  if (t == 0) {
    float mx = acc[0];
    for (int i = 1; i < NCc; i++) mx = fmaxf(mx, acc[i]);
    float s = 0.f;
    for (int i = 0; i < NCc; i++) s += expf(acc[i] - mx);
    red[0] = mx;
    red[1] = logf(s);
  }
  __syncthreads();
  if (t < NCc)
    out_final[n * NCc + t] =
        0.5f * g_plc[n * NCc + t] + 0.5f * (acc[t] - red[0] - red[1]);
}

// ------------------------- host launch --------------------------------------
extern "C" void kernel_launch(void* const* d_in, const int* in_sizes, int n_in,
                              void* d_out, int out_size) {
  (void)in_sizes; (void)n_in; (void)out_size;
  const float* x  = (const float*)d_in[0];
  const float* W1 = (const float*)d_in[1];
  const float* b1 = (const float*)d_in[2];
  const float* Wq = (const float*)d_in[3];
  const float* bq = (const float*)d_in[4];
  const float* Wk = (const float*)d_in[5];
  const float* bk = (const float*)d_in[6];
  const float* Wv = (const float*)d_in[7];
  const float* bv = (const float*)d_in[8];
  const float* W2 = (const float*)d_in[9];
  const float* b2 = (const float*)d_in[10];
  const int* ei   = (const int*)d_in[11];
  const int* y    = (const int*)d_in[12];
  const int* rowi = ei;
  const int* coli = ei + Ee;
  float* out_final = (float*)d_out;
  float* out_emb   = (float*)d_out + (size_t)Nn * NCc;

  void* cntp = 0; cudaGetSymbolAddress(&cntp, g_cnt);
  void* curp = 0; cudaGetSymbolAddress(&curp, g_cur);
  cudaFuncSetAttribute(sim_topk_kernel,
                       cudaFuncAttributeMaxDynamicSharedMemorySize, SIM_SMEM);

  cudaMemsetAsync(cntp, 0, Nn * sizeof(int), 0);
  cudaMemsetAsync(curp, 0, Nn * sizeof(int), 0);
  gemm1_relu_kernel<<<(Nn + 63) / 64, 256>>>(x, W1, b1);
  count_kernel<<<(ETOT + 255) / 256, 256>>>(coli);
  dinv_kernel<<<(Nn + 255) / 256, 256>>>();
  norm_kernel<<<(ETOT + 255) / 256, 256>>>(rowi, coli);
  scan_kernel<<<1, 1024>>>();
  place_kernel<<<(ETOT + 255) / 256, 256>>>(coli);
  sort_bucket_kernel<<<(Nn + 127) / 128, 128>>>();

  for (int l = 0; l < NLAY; l++) {
    qkv_kernel<<<Nn, 128>>>(Wq, bq, Wk, bk, Wv, bv, l);
    switch (l) {
      case 0: attn_gather_kernel<1><<<Nn, 128>>>(rowi, l); break;
      case 1: attn_gather_kernel<2><<<Nn, 128>>>(rowi, l); break;
      case 2: attn_gather_kernel<3><<<Nn, 128>>>(rowi, l); break;
      default: attn_gather_kernel<4><<<Nn, 128>>>(rowi, l); break;
    }
  }

  emb_norm_kernel<<<Nn, 128>>>(out_emb);
  plc_kernel<<<Nn, 128>>>(W2, b2);
  sim_topk_kernel<<<SGRID, 256, SIM_SMEM>>>();
  psim_final_kernel<<<Nn, 64>>>(y, out_final);
}

// round 9
// speedup vs baseline: 1.9373x; 1.9373x over previous
#include <cuda_runtime.h>
#include <math.h>

#define Nn 10000
#define Ee 160000
#define ETOT (Ee + Nn)
#define IND 512
#define Cc 128
#define NCc 40
#define NLAY 4
#define HE 8
#define GR 16
#define KT 16
#define DKk 16

// ------------------------- scratch (device globals; no allocations) ---------
__device__ float g_xall[Nn * 5 * Cc];   // x_all levels 0..4
__device__ float g_q[Nn * Cc];
__device__ float g_k[Nn * 4 * Cc];      // levels 0..3
__device__ float g_v[Nn * 4 * Cc];
__device__ int   g_cnt[Nn];             // in-degree incl self loop
__device__ float g_dinv[Nn];
__device__ float g_norm[ETOT];
__device__ int   g_off[Nn + 1];
__device__ int   g_cur[Nn];
__device__ int   g_eid[ETOT];
__device__ float g_en[Nn * Cc];
__device__ float g_plc[Nn * NCc];
__device__ float g_tval[Nn * KT];
__device__ int   g_tidx[Nn * KT];

// ------------------------- 1) h0 = relu(x @ W1 + b1) ------------------------
__global__ __launch_bounds__(256) void gemm1_relu_kernel(
    const float* __restrict__ x, const float* __restrict__ W1,
    const float* __restrict__ b1) {
  __shared__ float xs[32][65];    // xs[k][m], 64 rows
  __shared__ float ws[32][128];
  int m0 = blockIdx.x * 64;
  int tid = threadIdx.x;
  int tc = tid & 15;   // 16 col-groups of 8
  int tr = tid >> 4;   // 16 row-groups of 4
  float acc[4][8];
#pragma unroll
  for (int r = 0; r < 4; r++)
#pragma unroll
    for (int c = 0; c < 8; c++) acc[r][c] = 0.f;

  for (int k0 = 0; k0 < IND; k0 += 32) {
    for (int i = tid; i < 64 * 32; i += 256) {
      int m = i >> 5, k = i & 31;
      int row = m0 + m;
      xs[k][m] = (row < Nn) ? x[row * IND + k0 + k] : 0.f;
    }
    for (int i = tid; i < 32 * 128; i += 256) {
      int k = i >> 7, c = i & 127;
      ws[k][c] = W1[(k0 + k) * Cc + c];
    }
    __syncthreads();
#pragma unroll
    for (int k = 0; k < 32; k++) {
      float xv[4], wv[8];
#pragma unroll
      for (int r = 0; r < 4; r++) xv[r] = xs[k][tr * 4 + r];
#pragma unroll
      for (int c = 0; c < 8; c++) wv[c] = ws[k][tc * 8 + c];
#pragma unroll
      for (int r = 0; r < 4; r++)
#pragma unroll
        for (int c = 0; c < 8; c++) acc[r][c] = fmaf(xv[r], wv[c], acc[r][c]);
    }
    __syncthreads();
  }
#pragma unroll
  for (int r = 0; r < 4; r++) {
    int row = m0 + tr * 4 + r;
    if (row < Nn) {
#pragma unroll
      for (int c = 0; c < 8; c++) {
        int col = tc * 8 + c;
        float v = acc[r][c] + b1[col];
        g_xall[row * 5 * Cc + col] = v > 0.f ? v : 0.f;   // level 0
      }
    }
  }
}

// ------------------------- 2) gcn_norm + CSR build (deterministic) ----------
__global__ void count_kernel(const int* __restrict__ coli) {
  int e = blockIdx.x * blockDim.x + threadIdx.x;
  if (e >= ETOT) return;
  int c = (e < Ee) ? coli[e] : (e - Ee);
  atomicAdd(&g_cnt[c], 1);
}

__global__ void dinv_kernel() {
  int n = blockIdx.x * blockDim.x + threadIdx.x;
  if (n < Nn) g_dinv[n] = 1.0f / sqrtf((float)g_cnt[n]);
}

__global__ void norm_kernel(const int* __restrict__ rowi,
                            const int* __restrict__ coli) {
  int e = blockIdx.x * blockDim.x + threadIdx.x;
  if (e >= ETOT) return;
  if (e < Ee) g_norm[e] = g_dinv[rowi[e]] * g_dinv[coli[e]];
  else { float d = g_dinv[e - Ee]; g_norm[e] = d * d; }
}

// deterministic pseudo-random fill of g_en (diagnostic only; overwritten by
// emb_norm before the real sim runs). Gives the profiled sim launch realistic
// data selectivity instead of all-zeros.
__global__ void init_en_kernel() {
  int i = blockIdx.x * blockDim.x + threadIdx.x;
  if (i < Nn * Cc) {
    unsigned h = (unsigned)i * 2654435761u;
    h ^= h >> 16; h *= 2246822519u; h ^= h >> 13;
    g_en[i] = (float)(h & 0xffff) * (1.0f / 65536.0f) - 0.5f;
  }
}

// single-block exclusive scan of g_cnt -> g_off (1024 threads, 10 elems each)
__global__ __launch_bounds__(1024) void scan_kernel() {
  __shared__ int ssum[1024];
  int t = threadIdx.x;
  int base = t * 10;
  int loc[10];
  int s = 0;
#pragma unroll
  for (int i = 0; i < 10; i++) {
    int idx = base + i;
    int v = (idx < Nn) ? g_cnt[idx] : 0;
    loc[i] = s;
    s += v;
  }
  ssum[t] = s;
  __syncthreads();
  for (int off = 1; off < 1024; off <<= 1) {
    int v = (t >= off) ? ssum[t - off] : 0;
    __syncthreads();
    ssum[t] += v;
    __syncthreads();
  }
  int pre = (t > 0) ? ssum[t - 1] : 0;
#pragma unroll
  for (int i = 0; i < 10; i++) {
    int idx = base + i;
    if (idx < Nn) g_off[idx] = pre + loc[i];
  }
  if (t == 1023) g_off[Nn] = ssum[1023];
}

__global__ void place_kernel(const int* __restrict__ coli) {
  int e = blockIdx.x * blockDim.x + threadIdx.x;
  if (e >= ETOT) return;
  int c = (e < Ee) ? coli[e] : (e - Ee);
  int pos = atomicAdd(&g_cur[c], 1);
  g_eid[g_off[c] + pos] = e;
}

// canonicalize bucket order: insertion-sort each bucket ascending by edge id
__global__ void sort_bucket_kernel() {
  int n = blockIdx.x * blockDim.x + threadIdx.x;
  if (n >= Nn) return;
  int s = g_off[n], e2 = g_off[n + 1];
  for (int i = s + 1; i < e2; i++) {
    int key = g_eid[i];
    int j = i - 1;
    while (j >= s && g_eid[j] > key) { g_eid[j + 1] = g_eid[j]; j--; }
    g_eid[j + 1] = key;
  }
}

// ------------------------- 3a) grouped q/k/v per layer ---------------------
__global__ __launch_bounds__(128) void qkv_kernel(
    const float* __restrict__ Wq, const float* __restrict__ bq,
    const float* __restrict__ Wk, const float* __restrict__ bk,
    const float* __restrict__ Wv, const float* __restrict__ bv, int l) {
  int n = blockIdx.x;
  int c = threadIdx.x;
  int g = c >> 3, o = c & 7;
  __shared__ float xs[Cc];
  float wq[8], wk[8], wv[8];
  int base = ((l * GR + g) * 8) * 8 + o;
#pragma unroll
  for (int i = 0; i < 8; i++) {
    wq[i] = Wq[base + i * 8];
    wk[i] = Wk[base + i * 8];
    wv[i] = Wv[base + i * 8];
  }
  float bqv = bq[l * Cc + c], bkv = bk[l * Cc + c], bvv = bv[l * Cc + c];
  for (int lev = 0; lev <= l; lev++) {
    __syncthreads();
    xs[c] = g_xall[(n * 5 + lev) * Cc + c];
    __syncthreads();
    float xg[8];
#pragma unroll
    for (int i = 0; i < 8; i++) xg[i] = xs[g * 8 + i];
    float sk = bkv, sv = bvv;
#pragma unroll
    for (int i = 0; i < 8; i++) {
      sk = fmaf(xg[i], wk[i], sk);
      sv = fmaf(xg[i], wv[i], sv);
    }
    g_k[(n * 4 + lev) * Cc + c] = sk;
    g_v[(n * 4 + lev) * Cc + c] = sv;
    if (lev == l) {
      float sq = bqv;
#pragma unroll
      for (int i = 0; i < 8; i++) sq = fmaf(xg[i], wq[i], sq);
      g_q[n * Cc + c] = sq;
    }
  }
}

// ------------------------- 3b) deterministic attention gather --------------
template <int NLEV>
__global__ __launch_bounds__(128) void attn_gather_kernel(
    const int* __restrict__ rowi, int l) {
  int c = blockIdx.x;
  int tid = threadIdx.x;
  const unsigned FULL = 0xffffffffu;
  float qv = g_q[c * Cc + tid];
  int s = g_off[c], e2 = g_off[c + 1];
  float acc = 0.f;
  for (int p = s; p < e2; p++) {
    int e = g_eid[p];
    int r = (e < Ee) ? rowi[e] : (e - Ee);
    float nrm = g_norm[e];
    float kk[NLEV], vv[NLEV];
#pragma unroll
    for (int lev = 0; lev < NLEV; lev++) {
      kk[lev] = g_k[(r * 4 + lev) * Cc + tid];
      vv[lev] = g_v[(r * 4 + lev) * Cc + tid];
    }
    float sc[NLEV];
    float mx = -1e30f;
#pragma unroll
    for (int lev = 0; lev < NLEV; lev++) {
      float t = qv * kk[lev];
      t += __shfl_xor_sync(FULL, t, 8);
      t += __shfl_xor_sync(FULL, t, 4);
      t += __shfl_xor_sync(FULL, t, 2);
      t += __shfl_xor_sync(FULL, t, 1);
      t *= 0.25f;   // 1/sqrt(DK)
      sc[lev] = t;
      mx = fmaxf(mx, t);
    }
    float den = 0.f;
#pragma unroll
    for (int lev = 0; lev < NLEV; lev++) {
      sc[lev] = expf(sc[lev] - mx);
      den += sc[lev];
    }
    float w = nrm / den;
#pragma unroll
    for (int lev = 0; lev < NLEV; lev++)
      acc = fmaf(sc[lev] * w, vv[lev], acc);
  }
  g_xall[(c * 5 + l + 1) * Cc + tid] = acc > 0.f ? acc : 0.f;
}

// ------------------------- 4) emb out + L2 normalize -----------------------
__global__ __launch_bounds__(128) void emb_norm_kernel(float* __restrict__ out_emb) {
  int n = blockIdx.x;
  int c = threadIdx.x;
  float v = g_xall[(n * 5 + 4) * Cc + c];
  out_emb[n * Cc + c] = v;
  float ss = v * v;
#pragma unroll
  for (int off = 16; off; off >>= 1) ss += __shfl_down_sync(0xffffffffu, ss, off);
  __shared__ float ws[4];
  if ((c & 31) == 0) ws[c >> 5] = ss;
  __syncthreads();
  float tot = ws[0] + ws[1] + ws[2] + ws[3];
  float nrm = fmaxf(sqrtf(tot), 1e-8f);
  g_en[n * Cc + c] = v / nrm;
}

// ------------------------- 5) p_lc = log_softmax(emb@W2+b2) ----------------
__global__ __launch_bounds__(128) void plc_kernel(const float* __restrict__ W2,
                                                  const float* __restrict__ b2) {
  int n = blockIdx.x;
  int t = threadIdx.x;
  __shared__ float xr[Cc];
  __shared__ float lg[NCc];
  __shared__ float red[2];
  xr[t] = g_xall[(n * 5 + 4) * Cc + t];
  __syncthreads();
  if (t < NCc) {
    float s = b2[t];
    for (int k = 0; k < Cc; k++) s = fmaf(xr[k], W2[k * NCc + t], s);
    lg[t] = s;
  }
  __syncthreads();
  if (t == 0) {
    float mx = lg[0];
    for (int i = 1; i < NCc; i++) mx = fmaxf(mx, lg[i]);
    float s = 0.f;
    for (int i = 0; i < NCc; i++) s += expf(lg[i] - mx);
    red[0] = mx;
    red[1] = logf(s);
  }
  __syncthreads();
  if (t < NCc) g_plc[n * NCc + t] = lg[t] - red[0] - red[1];
}

// ------------------------- 6) fused sim = en@en^T + top-16 -----------------
// f32x2 packed-FMA GEMM + threshold-buffer candidate top-k (exact, deterministic)
// R7 config (proven 1920us): RPW=5, SROWS=40, grid=250, register-resident acc.
// Templated on NCOL so a small diagnostic instance can be placed at ncu's
// capture slot (launch #6) — its output is overwritten by the real instance.
#define SROWS 40     // rows per block (8 warps x 5 rows)
#define RPW 5
#define SGRID 250
#define SCOLS 256
#define CPAD 258
#define CAP 192
#define SIM_SMEM ((128 * CPAD + SROWS * Cc + SROWS * CAP) * 4 + SROWS * CAP * 4 + SROWS * 8)

// exact tie-aware top-16 selection of buf[0..n) into buf[0..15]; updates thr/cnt
__device__ __noinline__ void refresh_row(float* __restrict__ v,
                                         int* __restrict__ ix,
                                         float* __restrict__ thr,
                                         int* __restrict__ cnt,
                                         int rl, int lane) {
  const unsigned FULL = 0xffffffffu;
  int n = cnt[rl];
#pragma unroll 1
  for (int pick = 0; pick < KT; pick++) {
    float mv = -3.4e38f; int mi = 0x7fffffff; int mp = pick;
    for (int s = pick + lane; s < n; s += 32) {
      float vv = v[s]; int ii = ix[s];
      if (vv > mv || (vv == mv && ii < mi)) { mv = vv; mi = ii; mp = s; }
    }
#pragma unroll
    for (int off = 16; off; off >>= 1) {
      float ov = __shfl_down_sync(FULL, mv, off);
      int oi = __shfl_down_sync(FULL, mi, off);
      int op = __shfl_down_sync(FULL, mp, off);
      if (ov > mv || (ov == mv && oi < mi)) { mv = ov; mi = oi; mp = op; }
    }
    mp = __shfl_sync(FULL, mp, 0);
    mv = __shfl_sync(FULL, mv, 0);
    mi = __shfl_sync(FULL, mi, 0);
    if (lane == 0 && mp != pick) {
      float tv = v[pick]; int ti = ix[pick];
      v[pick] = mv; ix[pick] = mi;
      v[mp] = tv; ix[mp] = ti;
    }
    __syncwarp();
  }
  if (lane == 0) { thr[rl] = v[KT - 1]; cnt[rl] = KT; }
  __syncwarp();
}

// one ballot-insert step for a single scalar candidate
#define COLLECT_ONE(val, colofs)                                          \
  do {                                                                    \
    float v_ = (val);                                                     \
    int colx_ = j0 + (colofs) + lane * 2;                                 \
    bool p_ = (colx_ < Nn) && (v_ >= thr_r);                              \
    unsigned mask_ = __ballot_sync(0xffffffffu, p_);                      \
    if (mask_) {                                                          \
      int base_ = cnt[rl];                                                \
      if (p_) {                                                           \
        int pos_ = base_ + __popc(mask_ & ((1u << lane) - 1u));           \
        bv[pos_] = v_;                                                    \
        bi[pos_] = colx_;                                                 \
      }                                                                   \
      int nb_ = base_ + __popc(mask_);                                    \
      if (lane == 0) cnt[rl] = nb_;                                       \
      __syncwarp();                                                       \
      if (nb_ >= CAP - 32) {                                              \
        refresh_row(bv, bi, thr, cnt, rl, lane);                          \
        thr_r = thr[rl];                                                  \
      }                                                                   \
    }                                                                     \
  } while (0)

// candidates for one row: 8 scalars = (c2,t) pairs, values passed by register
__device__ __noinline__ void collect_row(int rl, int j0, int lane,
                                         float4 va, float4 vb,
                                         float* __restrict__ bv,
                                         int* __restrict__ bi,
                                         float* __restrict__ thr,
                                         int* __restrict__ cnt) {
  float thr_r = thr[rl];
  COLLECT_ONE(va.x, 0);        // c2=0, t=0
  COLLECT_ONE(va.y, 1);        // c2=0, t=1
  COLLECT_ONE(va.z, 64);       // c2=1, t=0
  COLLECT_ONE(va.w, 65);       // c2=1, t=1
  COLLECT_ONE(vb.x, 128);      // c2=2, t=0
  COLLECT_ONE(vb.y, 129);      // c2=2, t=1
  COLLECT_ONE(vb.z, 192);      // c2=3, t=0
  COLLECT_ONE(vb.w, 193);      // c2=3, t=1
}

template <int NCOL>
__global__ __launch_bounds__(256) void sim_topk_impl() {
  extern __shared__ float sm[];
  float* colsT = sm;                              // [128][CPAD]
  float* rows  = sm + 128 * CPAD;                 // [SROWS][128]
  float* bufv  = rows + SROWS * Cc;               // [SROWS][CAP]
  int*   bufi  = (int*)(bufv + SROWS * CAP);      // [SROWS][CAP]
  float* thr   = (float*)(bufi + SROWS * CAP);    // [SROWS]
  int*   cnt   = (int*)(thr + SROWS);             // [SROWS]

  int r0 = blockIdx.x * SROWS;
  int tid = threadIdx.x;
  int warp = tid >> 5, lane = tid & 31;
  int rlbase = warp * RPW;

  for (int i = tid; i < SROWS * Cc; i += 256) {
    int row = r0 + (i >> 7);
    rows[i] = (row < Nn) ? g_en[row * Cc + (i & 127)] : 0.f;
  }
  if (tid < SROWS) { thr[tid] = -3.3e38f; cnt[tid] = 0; }
  __syncthreads();

  int rlocal = lane >> 3;   // 0..3 (row within 4-row group of fill)
  int kc = lane & 7;        // 0..7 (16B k-chunk within quarter)

  for (int j0 = 0; j0 < NCOL; j0 += SCOLS) {
    // ---- fill colsT[k][j] (transposed, coalesced float4 loads) ----
#pragma unroll 4
    for (int it = 0; it < 32; it++) {
      int u = it * 8 + warp;          // 256 warp-units
      int rowgrp = u >> 2, kq = u & 3;
      int j = rowgrp * 4 + rlocal;    // 0..255
      int k4 = kq * 8 + kc;           // 0..31
      int col = j0 + j;
      float4 val = make_float4(0.f, 0.f, 0.f, 0.f);
      if (col < Nn) val = ((const float4*)g_en)[col * (Cc / 4) + k4];
      colsT[(k4 * 4 + 0) * CPAD + j] = val.x;
      colsT[(k4 * 4 + 1) * CPAD + j] = val.y;
      colsT[(k4 * 4 + 2) * CPAD + j] = val.z;
      colsT[(k4 * 4 + 3) * CPAD + j] = val.w;
    }
    __syncthreads();

    // ---- packed f32x2 GEMM: RPW rows x 8 cols (4 pairs) per lane ----
    unsigned long long acc[RPW][4];
#pragma unroll
    for (int r = 0; r < RPW; r++)
#pragma unroll
      for (int c2 = 0; c2 < 4; c2++) acc[r][c2] = 0ULL;

    const float* rowp = rows + rlbase * Cc;
#pragma unroll 4
    for (int k = 0; k < Cc; k++) {
      unsigned long long cv[4];
      const float* cb = colsT + k * CPAD + lane * 2;
#pragma unroll
      for (int c2 = 0; c2 < 4; c2++)
        cv[c2] = *(const unsigned long long*)(cb + c2 * 64);
#pragma unroll
      for (int r = 0; r < RPW; r++) {
        float rv = rowp[r * Cc + k];
        unsigned long long rv2;
        asm("mov.b64 %0, {%1, %1};" : "=l"(rv2) : "f"(rv));
#pragma unroll
        for (int c2 = 0; c2 < 4; c2++)
          asm("fma.rn.f32x2 %0, %1, %2, %0;"
              : "+l"(acc[r][c2]) : "l"(rv2), "l"(cv[c2]));
      }
    }

    // ---- threshold-buffer candidate collection (acc constant-indexed) ----
#pragma unroll
    for (int r = 0; r < RPW; r++) {
      int rl = rlbase + r;
      float4 va, vb;
      asm("mov.b64 {%0, %1}, %2;" : "=f"(va.x), "=f"(va.y) : "l"(acc[r][0]));
      asm("mov.b64 {%0, %1}, %2;" : "=f"(va.z), "=f"(va.w) : "l"(acc[r][1]));
      asm("mov.b64 {%0, %1}, %2;" : "=f"(vb.x), "=f"(vb.y) : "l"(acc[r][2]));
      asm("mov.b64 {%0, %1}, %2;" : "=f"(vb.z), "=f"(vb.w) : "l"(acc[r][3]));
      collect_row(rl, j0, lane, va, vb,
                  bufv + rl * CAP, bufi + rl * CAP, thr, cnt);
    }
    __syncthreads();
  }

  // ---- final exact selection + output ----
#pragma unroll 1
  for (int r = 0; r < RPW; r++) {
    int rl = rlbase + r;
    int grow = r0 + rl;
    if (grow >= Nn) continue;
    refresh_row(bufv + rl * CAP, bufi + rl * CAP, thr, cnt, rl, lane);
    if (lane < KT) {
      g_tval[grow * KT + lane] = bufv[rl * CAP + lane];
      g_tidx[grow * KT + lane] = bufi[rl * CAP + lane];
    }
  }
}

// ------------------------- 7) p_sim + final combine (deterministic) --------
__global__ __launch_bounds__(64) void psim_final_kernel(
    const int* __restrict__ y, float* __restrict__ out_final) {
  int n = blockIdx.x;
  int t = threadIdx.x;
  __shared__ float ex[KT];
  __shared__ int cls[KT];
  __shared__ float acc[NCc];
  __shared__ float red[2];
  if (t < KT) {
    ex[t] = expf(g_tval[n * KT + t]);
    cls[t] = y[g_tidx[n * KT + t]];
  }
  __syncthreads();
  if (t < NCc) {
    float s = 0.f;
    for (int j = 0; j < KT; j++)
      if (cls[j] == t) s += ex[j];
    acc[t] = s;
  }
  __syncthreads();
  if (t == 0) {
    float mx = acc[0];
    for (int i = 1; i < NCc; i++) mx = fmaxf(mx, acc[i]);
    float s = 0.f;
    for (int i = 0; i < NCc; i++) s += expf(acc[i] - mx);
    red[0] = mx;
    red[1] = logf(s);
  }
  __syncthreads();
  if (t < NCc)
    out_final[n * NCc + t] =
        0.5f * g_plc[n * NCc + t] + 0.5f * (acc[t] - red[0] - red[1]);
}

// ------------------------- host launch --------------------------------------
extern "C" void kernel_launch(void* const* d_in, const int* in_sizes, int n_in,
                              void* d_out, int out_size) {
  (void)in_sizes; (void)n_in; (void)out_size;
  const float* x  = (const float*)d_in[0];
  const float* W1 = (const float*)d_in[1];
  const float* b1 = (const float*)d_in[2];
  const float* Wq = (const float*)d_in[3];
  const float* bq = (const float*)d_in[4];
  const float* Wk = (const float*)d_in[5];
  const float* bk = (const float*)d_in[6];
  const float* Wv = (const float*)d_in[7];
  const float* bv = (const float*)d_in[8];
  const float* W2 = (const float*)d_in[9];
  const float* b2 = (const float*)d_in[10];
  const int* ei   = (const int*)d_in[11];
  const int* y    = (const int*)d_in[12];
  const int* rowi = ei;
  const int* coli = ei + Ee;
  float* out_final = (float*)d_out;
  float* out_emb   = (float*)d_out + (size_t)Nn * NCc;

  void* cntp = 0; cudaGetSymbolAddress(&cntp, g_cnt);
  void* curp = 0; cudaGetSymbolAddress(&curp, g_cur);
  cudaFuncSetAttribute(sim_topk_impl<Nn>,
                       cudaFuncAttributeMaxDynamicSharedMemorySize, SIM_SMEM);
  cudaFuncSetAttribute(sim_topk_impl<1280>,
                       cudaFuncAttributeMaxDynamicSharedMemorySize, SIM_SMEM);

  // Launch slots (ncu captures slot 6 via -s 5 -c 1, memsets included):
  cudaMemsetAsync(cntp, 0, Nn * sizeof(int), 0);                 // 1
  cudaMemsetAsync(curp, 0, Nn * sizeof(int), 0);                 // 2
  gemm1_relu_kernel<<<(Nn + 63) / 64, 256>>>(x, W1, b1);         // 3
  count_kernel<<<(ETOT + 255) / 256, 256>>>(coli);               // 4
  init_en_kernel<<<(Nn * Cc + 255) / 256, 256>>>();              // 5 (diag data)
  sim_topk_impl<1280><<<148, 256, SIM_SMEM>>>();                 // 6 <- ncu target
  dinv_kernel<<<(Nn + 255) / 256, 256>>>();
  norm_kernel<<<(ETOT + 255) / 256, 256>>>(rowi, coli);
  scan_kernel<<<1, 1024>>>();
  place_kernel<<<(ETOT + 255) / 256, 256>>>(coli);
  sort_bucket_kernel<<<(Nn + 127) / 128, 128>>>();

  for (int l = 0; l < NLAY; l++) {
    qkv_kernel<<<Nn, 128>>>(Wq, bq, Wk, bk, Wv, bv, l);
    switch (l) {
      case 0: attn_gather_kernel<1><<<Nn, 128>>>(rowi, l); break;
      case 1: attn_gather_kernel<2><<<Nn, 128>>>(rowi, l); break;
      case 2: attn_gather_kernel<3><<<Nn, 128>>>(rowi, l); break;
      default: attn_gather_kernel<4><<<Nn, 128>>>(rowi, l); break;
    }
  }

  emb_norm_kernel<<<Nn, 128>>>(out_emb);
  plc_kernel<<<Nn, 128>>>(W2, b2);
  sim_topk_impl<Nn><<<SGRID, 256, SIM_SMEM>>>();
  psim_final_kernel<<<Nn, 64>>>(y, out_final);
}

// round 10
// speedup vs baseline: 1.9980x; 1.0313x over previous
#include <cuda_runtime.h>
#include <math.h>

#define Nn 10000
#define Ee 160000
#define ETOT (Ee + Nn)
#define IND 512
#define Cc 128
#define NCc 40
#define NLAY 4
#define HE 8
#define GR 16
#define KT 16
#define DKk 16

// ------------------------- scratch (device globals; no allocations) ---------
__device__ float g_xall[Nn * 5 * Cc];   // x_all levels 0..4
__device__ float g_q[Nn * Cc];
__device__ float g_k[Nn * 4 * Cc];      // levels 0..3
__device__ float g_v[Nn * 4 * Cc];
__device__ int   g_cnt[Nn];             // in-degree incl self loop
__device__ float g_dinv[Nn];
__device__ float g_norm[ETOT];
__device__ int   g_off[Nn + 1];
__device__ int   g_cur[Nn];
__device__ int   g_eid[ETOT];
__device__ float g_en[Nn * Cc];
__device__ float g_plc[Nn * NCc];
__device__ float g_tval[Nn * KT];
__device__ int   g_tidx[Nn * KT];

// ------------------------- 1) h0 = relu(x @ W1 + b1) ------------------------
__global__ __launch_bounds__(256) void gemm1_relu_kernel(
    const float* __restrict__ x, const float* __restrict__ W1,
    const float* __restrict__ b1) {
  __shared__ float xs[32][65];    // xs[k][m], 64 rows
  __shared__ float ws[32][128];
  int m0 = blockIdx.x * 64;
  int tid = threadIdx.x;
  int tc = tid & 15;   // 16 col-groups of 8
  int tr = tid >> 4;   // 16 row-groups of 4
  float acc[4][8];
#pragma unroll
  for (int r = 0; r < 4; r++)
#pragma unroll
    for (int c = 0; c < 8; c++) acc[r][c] = 0.f;

  for (int k0 = 0; k0 < IND; k0 += 32) {
    for (int i = tid; i < 64 * 32; i += 256) {
      int m = i >> 5, k = i & 31;
      int row = m0 + m;
      xs[k][m] = (row < Nn) ? x[row * IND + k0 + k] : 0.f;
    }
    for (int i = tid; i < 32 * 128; i += 256) {
      int k = i >> 7, c = i & 127;
      ws[k][c] = W1[(k0 + k) * Cc + c];
    }
    __syncthreads();
#pragma unroll
    for (int k = 0; k < 32; k++) {
      float xv[4], wv[8];
#pragma unroll
      for (int r = 0; r < 4; r++) xv[r] = xs[k][tr * 4 + r];
#pragma unroll
      for (int c = 0; c < 8; c++) wv[c] = ws[k][tc * 8 + c];
#pragma unroll
      for (int r = 0; r < 4; r++)
#pragma unroll
        for (int c = 0; c < 8; c++) acc[r][c] = fmaf(xv[r], wv[c], acc[r][c]);
    }
    __syncthreads();
  }
#pragma unroll
  for (int r = 0; r < 4; r++) {
    int row = m0 + tr * 4 + r;
    if (row < Nn) {
#pragma unroll
      for (int c = 0; c < 8; c++) {
        int col = tc * 8 + c;
        float v = acc[r][c] + b1[col];
        g_xall[row * 5 * Cc + col] = v > 0.f ? v : 0.f;   // level 0
      }
    }
  }
}

// ------------------------- 2) gcn_norm + CSR build (deterministic) ----------
__global__ void count_kernel(const int* __restrict__ coli) {
  int e = blockIdx.x * blockDim.x + threadIdx.x;
  if (e >= ETOT) return;
  int c = (e < Ee) ? coli[e] : (e - Ee);
  atomicAdd(&g_cnt[c], 1);
}

__global__ void dinv_kernel() {
  int n = blockIdx.x * blockDim.x + threadIdx.x;
  if (n < Nn) g_dinv[n] = 1.0f / sqrtf((float)g_cnt[n]);
}

__global__ void norm_kernel(const int* __restrict__ rowi,
                            const int* __restrict__ coli) {
  int e = blockIdx.x * blockDim.x + threadIdx.x;
  if (e >= ETOT) return;
  if (e < Ee) g_norm[e] = g_dinv[rowi[e]] * g_dinv[coli[e]];
  else { float d = g_dinv[e - Ee]; g_norm[e] = d * d; }
}

// deterministic pseudo-random fill of g_en (diagnostic only; overwritten by
// emb_norm before the real sim runs).
__global__ void init_en_kernel() {
  int i = blockIdx.x * blockDim.x + threadIdx.x;
  if (i < Nn * Cc) {
    unsigned h = (unsigned)i * 2654435761u;
    h ^= h >> 16; h *= 2246822519u; h ^= h >> 13;
    g_en[i] = (float)(h & 0xffff) * (1.0f / 65536.0f) - 0.5f;
  }
}

// single-block exclusive scan of g_cnt -> g_off (1024 threads, 10 elems each)
__global__ __launch_bounds__(1024) void scan_kernel() {
  __shared__ int ssum[1024];
  int t = threadIdx.x;
  int base = t * 10;
  int loc[10];
  int s = 0;
#pragma unroll
  for (int i = 0; i < 10; i++) {
    int idx = base + i;
    int v = (idx < Nn) ? g_cnt[idx] : 0;
    loc[i] = s;
    s += v;
  }
  ssum[t] = s;
  __syncthreads();
  for (int off = 1; off < 1024; off <<= 1) {
    int v = (t >= off) ? ssum[t - off] : 0;
    __syncthreads();
    ssum[t] += v;
    __syncthreads();
  }
  int pre = (t > 0) ? ssum[t - 1] : 0;
#pragma unroll
  for (int i = 0; i < 10; i++) {
    int idx = base + i;
    if (idx < Nn) g_off[idx] = pre + loc[i];
  }
  if (t == 1023) g_off[Nn] = ssum[1023];
}

__global__ void place_kernel(const int* __restrict__ coli) {
  int e = blockIdx.x * blockDim.x + threadIdx.x;
  if (e >= ETOT) return;
  int c = (e < Ee) ? coli[e] : (e - Ee);
  int pos = atomicAdd(&g_cur[c], 1);
  g_eid[g_off[c] + pos] = e;
}

// canonicalize bucket order: insertion-sort each bucket ascending by edge id
__global__ void sort_bucket_kernel() {
  int n = blockIdx.x * blockDim.x + threadIdx.x;
  if (n >= Nn) return;
  int s = g_off[n], e2 = g_off[n + 1];
  for (int i = s + 1; i < e2; i++) {
    int key = g_eid[i];
    int j = i - 1;
    while (j >= s && g_eid[j] > key) { g_eid[j + 1] = g_eid[j]; j--; }
    g_eid[j + 1] = key;
  }
}

// ------------------------- 3a) grouped q/k/v per layer ---------------------
__global__ __launch_bounds__(128) void qkv_kernel(
    const float* __restrict__ Wq, const float* __restrict__ bq,
    const float* __restrict__ Wk, const float* __restrict__ bk,
    const float* __restrict__ Wv, const float* __restrict__ bv, int l) {
  int n = blockIdx.x;
  int c = threadIdx.x;
  int g = c >> 3, o = c & 7;
  __shared__ float xs[Cc];
  float wq[8], wk[8], wv[8];
  int base = ((l * GR + g) * 8) * 8 + o;
#pragma unroll
  for (int i = 0; i < 8; i++) {
    wq[i] = Wq[base + i * 8];
    wk[i] = Wk[base + i * 8];
    wv[i] = Wv[base + i * 8];
  }
  float bqv = bq[l * Cc + c], bkv = bk[l * Cc + c], bvv = bv[l * Cc + c];
  for (int lev = 0; lev <= l; lev++) {
    __syncthreads();
    xs[c] = g_xall[(n * 5 + lev) * Cc + c];
    __syncthreads();
    float xg[8];
#pragma unroll
    for (int i = 0; i < 8; i++) xg[i] = xs[g * 8 + i];
    float sk = bkv, sv = bvv;
#pragma unroll
    for (int i = 0; i < 8; i++) {
      sk = fmaf(xg[i], wk[i], sk);
      sv = fmaf(xg[i], wv[i], sv);
    }
    g_k[(n * 4 + lev) * Cc + c] = sk;
    g_v[(n * 4 + lev) * Cc + c] = sv;
    if (lev == l) {
      float sq = bqv;
#pragma unroll
      for (int i = 0; i < 8; i++) sq = fmaf(xg[i], wq[i], sq);
      g_q[n * Cc + c] = sq;
    }
  }
}

// ------------------------- 3b) deterministic attention gather --------------
template <int NLEV>
__global__ __launch_bounds__(128) void attn_gather_kernel(
    const int* __restrict__ rowi, int l) {
  int c = blockIdx.x;
  int tid = threadIdx.x;
  const unsigned FULL = 0xffffffffu;
  float qv = g_q[c * Cc + tid];
  int s = g_off[c], e2 = g_off[c + 1];
  float acc = 0.f;
  for (int p = s; p < e2; p++) {
    int e = g_eid[p];
    int r = (e < Ee) ? rowi[e] : (e - Ee);
    float nrm = g_norm[e];
    float kk[NLEV], vv[NLEV];
#pragma unroll
    for (int lev = 0; lev < NLEV; lev++) {
      kk[lev] = g_k[(r * 4 + lev) * Cc + tid];
      vv[lev] = g_v[(r * 4 + lev) * Cc + tid];
    }
    float sc[NLEV];
    float mx = -1e30f;
#pragma unroll
    for (int lev = 0; lev < NLEV; lev++) {
      float t = qv * kk[lev];
      t += __shfl_xor_sync(FULL, t, 8);
      t += __shfl_xor_sync(FULL, t, 4);
      t += __shfl_xor_sync(FULL, t, 2);
      t += __shfl_xor_sync(FULL, t, 1);
      t *= 0.25f;   // 1/sqrt(DK)
      sc[lev] = t;
      mx = fmaxf(mx, t);
    }
    float den = 0.f;
#pragma unroll
    for (int lev = 0; lev < NLEV; lev++) {
      sc[lev] = expf(sc[lev] - mx);
      den += sc[lev];
    }
    float w = nrm / den;
#pragma unroll
    for (int lev = 0; lev < NLEV; lev++)
      acc = fmaf(sc[lev] * w, vv[lev], acc);
  }
  g_xall[(c * 5 + l + 1) * Cc + tid] = acc > 0.f ? acc : 0.f;
}

// ------------------------- 4) emb out + L2 normalize -----------------------
__global__ __launch_bounds__(128) void emb_norm_kernel(float* __restrict__ out_emb) {
  int n = blockIdx.x;
  int c = threadIdx.x;
  float v = g_xall[(n * 5 + 4) * Cc + c];
  out_emb[n * Cc + c] = v;
  float ss = v * v;
#pragma unroll
  for (int off = 16; off; off >>= 1) ss += __shfl_down_sync(0xffffffffu, ss, off);
  __shared__ float ws[4];
  if ((c & 31) == 0) ws[c >> 5] = ss;
  __syncthreads();
  float tot = ws[0] + ws[1] + ws[2] + ws[3];
  float nrm = fmaxf(sqrtf(tot), 1e-8f);
  g_en[n * Cc + c] = v / nrm;
}

// ------------------------- 5) p_lc = log_softmax(emb@W2+b2) ----------------
__global__ __launch_bounds__(128) void plc_kernel(const float* __restrict__ W2,
                                                  const float* __restrict__ b2) {
  int n = blockIdx.x;
  int t = threadIdx.x;
  __shared__ float xr[Cc];
  __shared__ float lg[NCc];
  __shared__ float red[2];
  xr[t] = g_xall[(n * 5 + 4) * Cc + t];
  __syncthreads();
  if (t < NCc) {
    float s = b2[t];
    for (int k = 0; k < Cc; k++) s = fmaf(xr[k], W2[k * NCc + t], s);
    lg[t] = s;
  }
  __syncthreads();
  if (t == 0) {
    float mx = lg[0];
    for (int i = 1; i < NCc; i++) mx = fmaxf(mx, lg[i]);
    float s = 0.f;
    for (int i = 0; i < NCc; i++) s += expf(lg[i] - mx);
    red[0] = mx;
    red[1] = logf(s);
  }
  __syncthreads();
  if (t < NCc) g_plc[n * NCc + t] = lg[t] - red[0] - red[1];
}

// ------------------------- 6) fused sim = en@en^T + top-16 -----------------
// f32x2 packed-FMA GEMM + threshold-buffer candidate top-k (exact, deterministic)
// v5 (profile-driven): 512 threads = 16 warps (4/SMSP, was 2 -> issue-bound),
// SROWS=80, RPW=5 uniform, grid=125 (exactly Nn, single wave), CAP=80 to fit
// smem (224.9 KB). GEMM/collect inner code identical to R7 -> bit-identical out.
#define SROWS 80     // rows per block (16 warps x 5 rows)
#define RPW 5
#define SGRID 125    // 125 * 80 = 10000 exactly; single wave on 148 SMs
#define STHREADS 512
#define SCOLS 256
#define CPAD 258
#define CAP 80
#define SIM_SMEM ((128 * CPAD + SROWS * Cc + SROWS * CAP) * 4 + SROWS * CAP * 4 + SROWS * 8)

// exact tie-aware top-16 selection of buf[0..n) into buf[0..15]; updates thr/cnt
__device__ __noinline__ void refresh_row(float* __restrict__ v,
                                         int* __restrict__ ix,
                                         float* __restrict__ thr,
                                         int* __restrict__ cnt,
                                         int rl, int lane) {
  const unsigned FULL = 0xffffffffu;
  int n = cnt[rl];
#pragma unroll 1
  for (int pick = 0; pick < KT; pick++) {
    float mv = -3.4e38f; int mi = 0x7fffffff; int mp = pick;
    for (int s = pick + lane; s < n; s += 32) {
      float vv = v[s]; int ii = ix[s];
      if (vv > mv || (vv == mv && ii < mi)) { mv = vv; mi = ii; mp = s; }
    }
#pragma unroll
    for (int off = 16; off; off >>= 1) {
      float ov = __shfl_down_sync(FULL, mv, off);
      int oi = __shfl_down_sync(FULL, mi, off);
      int op = __shfl_down_sync(FULL, mp, off);
      if (ov > mv || (ov == mv && oi < mi)) { mv = ov; mi = oi; mp = op; }
    }
    mp = __shfl_sync(FULL, mp, 0);
    mv = __shfl_sync(FULL, mv, 0);
    mi = __shfl_sync(FULL, mi, 0);
    if (lane == 0 && mp != pick) {
      float tv = v[pick]; int ti = ix[pick];
      v[pick] = mv; ix[pick] = mi;
      v[mp] = tv; ix[mp] = ti;
    }
    __syncwarp();
  }
  if (lane == 0) { thr[rl] = v[KT - 1]; cnt[rl] = KT; }
  __syncwarp();
}

// one ballot-insert step for a single scalar candidate
#define COLLECT_ONE(val, colofs)                                          \
  do {                                                                    \
    float v_ = (val);                                                     \
    int colx_ = j0 + (colofs) + lane * 2;                                 \
    bool p_ = (colx_ < Nn) && (v_ >= thr_r);                              \
    unsigned mask_ = __ballot_sync(0xffffffffu, p_);                      \
    if (mask_) {                                                          \
      int base_ = cnt[rl];                                                \
      if (p_) {                                                           \
        int pos_ = base_ + __popc(mask_ & ((1u << lane) - 1u));           \
        bv[pos_] = v_;                                                    \
        bi[pos_] = colx_;                                                 \
      }                                                                   \
      int nb_ = base_ + __popc(mask_);                                    \
      if (lane == 0) cnt[rl] = nb_;                                       \
      __syncwarp();                                                       \
      if (nb_ >= CAP - 32) {                                              \
        refresh_row(bv, bi, thr, cnt, rl, lane);                          \
        thr_r = thr[rl];                                                  \
      }                                                                   \
    }                                                                     \
  } while (0)

// candidates for one row: 8 scalars = (c2,t) pairs, values passed by register
__device__ __noinline__ void collect_row(int rl, int j0, int lane,
                                         float4 va, float4 vb,
                                         float* __restrict__ bv,
                                         int* __restrict__ bi,
                                         float* __restrict__ thr,
                                         int* __restrict__ cnt) {
  float thr_r = thr[rl];
  COLLECT_ONE(va.x, 0);        // c2=0, t=0
  COLLECT_ONE(va.y, 1);        // c2=0, t=1
  COLLECT_ONE(va.z, 64);       // c2=1, t=0
  COLLECT_ONE(va.w, 65);       // c2=1, t=1
  COLLECT_ONE(vb.x, 128);      // c2=2, t=0
  COLLECT_ONE(vb.y, 129);      // c2=2, t=1
  COLLECT_ONE(vb.z, 192);      // c2=3, t=0
  COLLECT_ONE(vb.w, 193);      // c2=3, t=1
}

template <int NCOL>
__global__ __launch_bounds__(STHREADS) void sim_topk_impl() {
  extern __shared__ float sm[];
  float* colsT = sm;                              // [128][CPAD]
  float* rows  = sm + 128 * CPAD;                 // [SROWS][128]
  float* bufv  = rows + SROWS * Cc;               // [SROWS][CAP]
  int*   bufi  = (int*)(bufv + SROWS * CAP);      // [SROWS][CAP]
  float* thr   = (float*)(bufi + SROWS * CAP);    // [SROWS]
  int*   cnt   = (int*)(thr + SROWS);             // [SROWS]

  int r0 = blockIdx.x * SROWS;
  int tid = threadIdx.x;
  int warp = tid >> 5, lane = tid & 31;
  int rlbase = warp * RPW;

  for (int i = tid; i < SROWS * Cc; i += STHREADS) {
    int row = r0 + (i >> 7);
    rows[i] = (row < Nn) ? g_en[row * Cc + (i & 127)] : 0.f;
  }
  if (tid < SROWS) { thr[tid] = -3.3e38f; cnt[tid] = 0; }
  __syncthreads();

  int rlocal = lane >> 3;   // 0..3 (row within 4-row group of fill)
  int kc = lane & 7;        // 0..7 (16B k-chunk within quarter)

  for (int j0 = 0; j0 < NCOL; j0 += SCOLS) {
    // ---- fill colsT[k][j] (transposed, coalesced float4 loads) ----
    // 256 warp-units split across 16 warps
#pragma unroll 4
    for (int it = 0; it < 16; it++) {
      int u = it * 16 + warp;
      int rowgrp = u >> 2, kq = u & 3;
      int j = rowgrp * 4 + rlocal;    // 0..255
      int k4 = kq * 8 + kc;           // 0..31
      int col = j0 + j;
      float4 val = make_float4(0.f, 0.f, 0.f, 0.f);
      if (col < Nn) val = ((const float4*)g_en)[col * (Cc / 4) + k4];
      colsT[(k4 * 4 + 0) * CPAD + j] = val.x;
      colsT[(k4 * 4 + 1) * CPAD + j] = val.y;
      colsT[(k4 * 4 + 2) * CPAD + j] = val.z;
      colsT[(k4 * 4 + 3) * CPAD + j] = val.w;
    }
    __syncthreads();

    // ---- packed f32x2 GEMM: RPW rows x 8 cols (4 pairs) per lane ----
    unsigned long long acc[RPW][4];
#pragma unroll
    for (int r = 0; r < RPW; r++)
#pragma unroll
      for (int c2 = 0; c2 < 4; c2++) acc[r][c2] = 0ULL;

    const float* rowp = rows + rlbase * Cc;
#pragma unroll 4
    for (int k = 0; k < Cc; k++) {
      unsigned long long cv[4];
      const float* cb = colsT + k * CPAD + lane * 2;
#pragma unroll
      for (int c2 = 0; c2 < 4; c2++)
        cv[c2] = *(const unsigned long long*)(cb + c2 * 64);
#pragma unroll
      for (int r = 0; r < RPW; r++) {
        float rv = rowp[r * Cc + k];
        unsigned long long rv2;
        asm("mov.b64 %0, {%1, %1};" : "=l"(rv2) : "f"(rv));
#pragma unroll
        for (int c2 = 0; c2 < 4; c2++)
          asm("fma.rn.f32x2 %0, %1, %2, %0;"
              : "+l"(acc[r][c2]) : "l"(rv2), "l"(cv[c2]));
      }
    }

    // ---- threshold-buffer candidate collection (acc constant-indexed) ----
#pragma unroll
    for (int r = 0; r < RPW; r++) {
      int rl = rlbase + r;
      float4 va, vb;
      asm("mov.b64 {%0, %1}, %2;" : "=f"(va.x), "=f"(va.y) : "l"(acc[r][0]));
      asm("mov.b64 {%0, %1}, %2;" : "=f"(va.z), "=f"(va.w) : "l"(acc[r][1]));
      asm("mov.b64 {%0, %1}, %2;" : "=f"(vb.x), "=f"(vb.y) : "l"(acc[r][2]));
      asm("mov.b64 {%0, %1}, %2;" : "=f"(vb.z), "=f"(vb.w) : "l"(acc[r][3]));
      collect_row(rl, j0, lane, va, vb,
                  bufv + rl * CAP, bufi + rl * CAP, thr, cnt);
    }
    __syncthreads();
  }

  // ---- final exact selection + output ----
#pragma unroll 1
  for (int r = 0; r < RPW; r++) {
    int rl = rlbase + r;
    int grow = r0 + rl;
    if (grow >= Nn) continue;
    refresh_row(bufv + rl * CAP, bufi + rl * CAP, thr, cnt, rl, lane);
    if (lane < KT) {
      g_tval[grow * KT + lane] = bufv[rl * CAP + lane];
      g_tidx[grow * KT + lane] = bufi[rl * CAP + lane];
    }
  }
}

// ------------------------- 7) p_sim + final combine (deterministic) --------
__global__ __launch_bounds__(64) void psim_final_kernel(
    const int* __restrict__ y, float* __restrict__ out_final) {
  int n = blockIdx.x;
  int t = threadIdx.x;
  __shared__ float ex[KT];
  __shared__ int cls[KT];
  __shared__ float acc[NCc];
  __shared__ float red[2];
  if (t < KT) {
    ex[t] = expf(g_tval[n * KT + t]);
    cls[t] = y[g_tidx[n * KT + t]];
  }
  __syncthreads();
  if (t < NCc) {
    float s = 0.f;
    for (int j = 0; j < KT; j++)
      if (cls[j] == t) s += ex[j];
    acc[t] = s;
  }
  __syncthreads();
  if (t == 0) {
    float mx = acc[0];
    for (int i = 1; i < NCc; i++) mx = fmaxf(mx, acc[i]);
    float s = 0.f;
    for (int i = 0; i < NCc; i++) s += expf(acc[i] - mx);
    red[0] = mx;
    red[1] = logf(s);
  }
  __syncthreads();
  if (t < NCc)
    out_final[n * NCc + t] =
        0.5f * g_plc[n * NCc + t] + 0.5f * (acc[t] - red[0] - red[1]);
}

// ------------------------- host launch --------------------------------------
extern "C" void kernel_launch(void* const* d_in, const int* in_sizes, int n_in,
                              void* d_out, int out_size) {
  (void)in_sizes; (void)n_in; (void)out_size;
  const float* x  = (const float*)d_in[0];
  const float* W1 = (const float*)d_in[1];
  const float* b1 = (const float*)d_in[2];
  const float* Wq = (const float*)d_in[3];
  const float* bq = (const float*)d_in[4];
  const float* Wk = (const float*)d_in[5];
  const float* bk = (const float*)d_in[6];
  const float* Wv = (const float*)d_in[7];
  const float* bv = (const float*)d_in[8];
  const float* W2 = (const float*)d_in[9];
  const float* b2 = (const float*)d_in[10];
  const int* ei   = (const int*)d_in[11];
  const int* y    = (const int*)d_in[12];
  const int* rowi = ei;
  const int* coli = ei + Ee;
  float* out_final = (float*)d_out;
  float* out_emb   = (float*)d_out + (size_t)Nn * NCc;

  void* cntp = 0; cudaGetSymbolAddress(&cntp, g_cnt);
  void* curp = 0; cudaGetSymbolAddress(&curp, g_cur);
  cudaFuncSetAttribute(sim_topk_impl<Nn>,
                       cudaFuncAttributeMaxDynamicSharedMemorySize, SIM_SMEM);
  cudaFuncSetAttribute(sim_topk_impl<512>,
                       cudaFuncAttributeMaxDynamicSharedMemorySize, SIM_SMEM);

  // Launch slots (ncu captures slot 6 via -s 5 -c 1, memsets included):
  cudaMemsetAsync(cntp, 0, Nn * sizeof(int), 0);                 // 1
  cudaMemsetAsync(curp, 0, Nn * sizeof(int), 0);                 // 2
  gemm1_relu_kernel<<<(Nn + 63) / 64, 256>>>(x, W1, b1);         // 3
  count_kernel<<<(ETOT + 255) / 256, 256>>>(coli);               // 4
  init_en_kernel<<<(Nn * Cc + 255) / 256, 256>>>();              // 5 (diag data)
  sim_topk_impl<512><<<SGRID, STHREADS, SIM_SMEM>>>();           // 6 <- ncu target
  dinv_kernel<<<(Nn + 255) / 256, 256>>>();
  norm_kernel<<<(ETOT + 255) / 256, 256>>>(rowi, coli);
  scan_kernel<<<1, 1024>>>();
  place_kernel<<<(ETOT + 255) / 256, 256>>>(coli);
  sort_bucket_kernel<<<(Nn + 127) / 128, 128>>>();

  for (int l = 0; l < NLAY; l++) {
    qkv_kernel<<<Nn, 128>>>(Wq, bq, Wk, bk, Wv, bv, l);
    switch (l) {
      case 0: attn_gather_kernel<1><<<Nn, 128>>>(rowi, l); break;
      case 1: attn_gather_kernel<2><<<Nn, 128>>>(rowi, l); break;
      case 2: attn_gather_kernel<3><<<Nn, 128>>>(rowi, l); break;
      default: attn_gather_kernel<4><<<Nn, 128>>>(rowi, l); break;
    }
  }

  emb_norm_kernel<<<Nn, 128>>>(out_emb);
  plc_kernel<<<Nn, 128>>>(W2, b2);
  sim_topk_impl<Nn><<<SGRID, STHREADS, SIM_SMEM>>>();
  psim_final_kernel<<<Nn, 64>>>(y, out_final);
}

// round 11
// speedup vs baseline: 2.0635x; 1.0328x over previous
#include <cuda_runtime.h>
#include <math.h>

#define Nn 10000
#define Ee 160000
#define ETOT (Ee + Nn)
#define IND 512
#define Cc 128
#define NCc 40
#define NLAY 4
#define HE 8
#define GR 16
#define KT 16
#define DKk 16

// ------------------------- scratch (device globals; no allocations) ---------
__device__ float g_xall[Nn * 5 * Cc];   // x_all levels 0..4
__device__ float g_q[Nn * Cc];
__device__ float g_k[Nn * 4 * Cc];      // levels 0..3
__device__ float g_v[Nn * 4 * Cc];
__device__ int   g_cnt[Nn];             // in-degree incl self loop
__device__ float g_dinv[Nn];
__device__ float g_norm[ETOT];
__device__ int   g_off[Nn + 1];
__device__ int   g_cur[Nn];
__device__ int   g_eid[ETOT];
__device__ float g_en[Nn * Cc];
__device__ float g_plc[Nn * NCc];
__device__ float g_tval[Nn * KT];
__device__ int   g_tidx[Nn * KT];

// ------------------------- 1) h0 = relu(x @ W1 + b1) ------------------------
__global__ __launch_bounds__(256) void gemm1_relu_kernel(
    const float* __restrict__ x, const float* __restrict__ W1,
    const float* __restrict__ b1) {
  __shared__ float xs[32][65];    // xs[k][m], 64 rows
  __shared__ float ws[32][128];
  int m0 = blockIdx.x * 64;
  int tid = threadIdx.x;
  int tc = tid & 15;   // 16 col-groups of 8
  int tr = tid >> 4;   // 16 row-groups of 4
  float acc[4][8];
#pragma unroll
  for (int r = 0; r < 4; r++)
#pragma unroll
    for (int c = 0; c < 8; c++) acc[r][c] = 0.f;

  for (int k0 = 0; k0 < IND; k0 += 32) {
    for (int i = tid; i < 64 * 32; i += 256) {
      int m = i >> 5, k = i & 31;
      int row = m0 + m;
      xs[k][m] = (row < Nn) ? x[row * IND + k0 + k] : 0.f;
    }
    for (int i = tid; i < 32 * 128; i += 256) {
      int k = i >> 7, c = i & 127;
      ws[k][c] = W1[(k0 + k) * Cc + c];
    }
    __syncthreads();
#pragma unroll
    for (int k = 0; k < 32; k++) {
      float xv[4], wv[8];
#pragma unroll
      for (int r = 0; r < 4; r++) xv[r] = xs[k][tr * 4 + r];
#pragma unroll
      for (int c = 0; c < 8; c++) wv[c] = ws[k][tc * 8 + c];
#pragma unroll
      for (int r = 0; r < 4; r++)
#pragma unroll
        for (int c = 0; c < 8; c++) acc[r][c] = fmaf(xv[r], wv[c], acc[r][c]);
    }
    __syncthreads();
  }
#pragma unroll
  for (int r = 0; r < 4; r++) {
    int row = m0 + tr * 4 + r;
    if (row < Nn) {
#pragma unroll
      for (int c = 0; c < 8; c++) {
        int col = tc * 8 + c;
        float v = acc[r][c] + b1[col];
        g_xall[row * 5 * Cc + col] = v > 0.f ? v : 0.f;   // level 0
      }
    }
  }
}

// ------------------------- 2) gcn_norm + CSR build (deterministic) ----------
__global__ void count_kernel(const int* __restrict__ coli) {
  int e = blockIdx.x * blockDim.x + threadIdx.x;
  if (e >= ETOT) return;
  int c = (e < Ee) ? coli[e] : (e - Ee);
  atomicAdd(&g_cnt[c], 1);
}

__global__ void dinv_kernel() {
  int n = blockIdx.x * blockDim.x + threadIdx.x;
  if (n < Nn) g_dinv[n] = 1.0f / sqrtf((float)g_cnt[n]);
}

__global__ void norm_kernel(const int* __restrict__ rowi,
                            const int* __restrict__ coli) {
  int e = blockIdx.x * blockDim.x + threadIdx.x;
  if (e >= ETOT) return;
  if (e < Ee) g_norm[e] = g_dinv[rowi[e]] * g_dinv[coli[e]];
  else { float d = g_dinv[e - Ee]; g_norm[e] = d * d; }
}

// single-block exclusive scan of g_cnt -> g_off (1024 threads, 10 elems each)
__global__ __launch_bounds__(1024) void scan_kernel() {
  __shared__ int ssum[1024];
  int t = threadIdx.x;
  int base = t * 10;
  int loc[10];
  int s = 0;
#pragma unroll
  for (int i = 0; i < 10; i++) {
    int idx = base + i;
    int v = (idx < Nn) ? g_cnt[idx] : 0;
    loc[i] = s;
    s += v;
  }
  ssum[t] = s;
  __syncthreads();
  for (int off = 1; off < 1024; off <<= 1) {
    int v = (t >= off) ? ssum[t - off] : 0;
    __syncthreads();
    ssum[t] += v;
    __syncthreads();
  }
  int pre = (t > 0) ? ssum[t - 1] : 0;
#pragma unroll
  for (int i = 0; i < 10; i++) {
    int idx = base + i;
    if (idx < Nn) g_off[idx] = pre + loc[i];
  }
  if (t == 1023) g_off[Nn] = ssum[1023];
}

__global__ void place_kernel(const int* __restrict__ coli) {
  int e = blockIdx.x * blockDim.x + threadIdx.x;
  if (e >= ETOT) return;
  int c = (e < Ee) ? coli[e] : (e - Ee);
  int pos = atomicAdd(&g_cur[c], 1);
  g_eid[g_off[c] + pos] = e;
}

// canonicalize bucket order: insertion-sort each bucket ascending by edge id
__global__ void sort_bucket_kernel() {
  int n = blockIdx.x * blockDim.x + threadIdx.x;
  if (n >= Nn) return;
  int s = g_off[n], e2 = g_off[n + 1];
  for (int i = s + 1; i < e2; i++) {
    int key = g_eid[i];
    int j = i - 1;
    while (j >= s && g_eid[j] > key) { g_eid[j + 1] = g_eid[j]; j--; }
    g_eid[j + 1] = key;
  }
}

// ------------------------- 3a) grouped q/k/v per layer ---------------------
__global__ __launch_bounds__(128) void qkv_kernel(
    const float* __restrict__ Wq, const float* __restrict__ bq,
    const float* __restrict__ Wk, const float* __restrict__ bk,
    const float* __restrict__ Wv, const float* __restrict__ bv, int l) {
  int n = blockIdx.x;
  int c = threadIdx.x;
  int g = c >> 3, o = c & 7;
  __shared__ float xs[Cc];
  float wq[8], wk[8], wv[8];
  int base = ((l * GR + g) * 8) * 8 + o;
#pragma unroll
  for (int i = 0; i < 8; i++) {
    wq[i] = Wq[base + i * 8];
    wk[i] = Wk[base + i * 8];
    wv[i] = Wv[base + i * 8];
  }
  float bqv = bq[l * Cc + c], bkv = bk[l * Cc + c], bvv = bv[l * Cc + c];
  for (int lev = 0; lev <= l; lev++) {
    __syncthreads();
    xs[c] = g_xall[(n * 5 + lev) * Cc + c];
    __syncthreads();
    float xg[8];
#pragma unroll
    for (int i = 0; i < 8; i++) xg[i] = xs[g * 8 + i];
    float sk = bkv, sv = bvv;
#pragma unroll
    for (int i = 0; i < 8; i++) {
      sk = fmaf(xg[i], wk[i], sk);
      sv = fmaf(xg[i], wv[i], sv);
    }
    g_k[(n * 4 + lev) * Cc + c] = sk;
    g_v[(n * 4 + lev) * Cc + c] = sv;
    if (lev == l) {
      float sq = bqv;
#pragma unroll
      for (int i = 0; i < 8; i++) sq = fmaf(xg[i], wq[i], sq);
      g_q[n * Cc + c] = sq;
    }
  }
}

// ------------------------- 3b) deterministic attention gather --------------
template <int NLEV>
__global__ __launch_bounds__(128) void attn_gather_kernel(
    const int* __restrict__ rowi, int l) {
  int c = blockIdx.x;
  int tid = threadIdx.x;
  const unsigned FULL = 0xffffffffu;
  float qv = g_q[c * Cc + tid];
  int s = g_off[c], e2 = g_off[c + 1];
  float acc = 0.f;
  for (int p = s; p < e2; p++) {
    int e = g_eid[p];
    int r = (e < Ee) ? rowi[e] : (e - Ee);
    float nrm = g_norm[e];
    float kk[NLEV], vv[NLEV];
#pragma unroll
    for (int lev = 0; lev < NLEV; lev++) {
      kk[lev] = g_k[(r * 4 + lev) * Cc + tid];
      vv[lev] = g_v[(r * 4 + lev) * Cc + tid];
    }
    float sc[NLEV];
    float mx = -1e30f;
#pragma unroll
    for (int lev = 0; lev < NLEV; lev++) {
      float t = qv * kk[lev];
      t += __shfl_xor_sync(FULL, t, 8);
      t += __shfl_xor_sync(FULL, t, 4);
      t += __shfl_xor_sync(FULL, t, 2);
      t += __shfl_xor_sync(FULL, t, 1);
      t *= 0.25f;   // 1/sqrt(DK)
      sc[lev] = t;
      mx = fmaxf(mx, t);
    }
    float den = 0.f;
#pragma unroll
    for (int lev = 0; lev < NLEV; lev++) {
      sc[lev] = expf(sc[lev] - mx);
      den += sc[lev];
    }
    float w = nrm / den;
#pragma unroll
    for (int lev = 0; lev < NLEV; lev++)
      acc = fmaf(sc[lev] * w, vv[lev], acc);
  }
  g_xall[(c * 5 + l + 1) * Cc + tid] = acc > 0.f ? acc : 0.f;
}

// ------------------------- 4) emb out + L2 normalize -----------------------
__global__ __launch_bounds__(128) void emb_norm_kernel(float* __restrict__ out_emb) {
  int n = blockIdx.x;
  int c = threadIdx.x;
  float v = g_xall[(n * 5 + 4) * Cc + c];
  out_emb[n * Cc + c] = v;
  float ss = v * v;
#pragma unroll
  for (int off = 16; off; off >>= 1) ss += __shfl_down_sync(0xffffffffu, ss, off);
  __shared__ float ws[4];
  if ((c & 31) == 0) ws[c >> 5] = ss;
  __syncthreads();
  float tot = ws[0] + ws[1] + ws[2] + ws[3];
  float nrm = fmaxf(sqrtf(tot), 1e-8f);
  g_en[n * Cc + c] = v / nrm;
}

// ------------------------- 5) p_lc = log_softmax(emb@W2+b2) ----------------
__global__ __launch_bounds__(128) void plc_kernel(const float* __restrict__ W2,
                                                  const float* __restrict__ b2) {
  int n = blockIdx.x;
  int t = threadIdx.x;
  __shared__ float xr[Cc];
  __shared__ float lg[NCc];
  __shared__ float red[2];
  xr[t] = g_xall[(n * 5 + 4) * Cc + t];
  __syncthreads();
  if (t < NCc) {
    float s = b2[t];
    for (int k = 0; k < Cc; k++) s = fmaf(xr[k], W2[k * NCc + t], s);
    lg[t] = s;
  }
  __syncthreads();
  if (t == 0) {
    float mx = lg[0];
    for (int i = 1; i < NCc; i++) mx = fmaxf(mx, lg[i]);
    float s = 0.f;
    for (int i = 0; i < NCc; i++) s += expf(lg[i] - mx);
    red[0] = mx;
    red[1] = logf(s);
  }
  __syncthreads();
  if (t < NCc) g_plc[n * NCc + t] = lg[t] - red[0] - red[1];
}

// ------------------------- 6) fused sim = en@en^T + top-16 -----------------
// f32x2 packed-FMA GEMM + threshold-buffer candidate top-k (exact, deterministic)
// v6 (profile-driven): v5 shape (512 thr, SROWS=80, grid=125, single wave) +
// DIAGONAL-FIRST tile order: each block processes the tile(s) containing its
// own rows' columns first, so self-sim (=1.0, the row max) tightens the
// threshold immediately and later tiles take the empty-ballot fast path.
// Tile order does not change the result: the buffer provably contains the
// exact top-16 superset at all times; final refresh is exact + tie-aware.
#define SROWS 80     // rows per block (16 warps x 5 rows)
#define RPW 5
#define SGRID 125    // 125 * 80 = 10000 exactly; single wave on 148 SMs
#define STHREADS 512
#define SCOLS 256
#define NTILES 40    // ceil(10000/256)
#define CPAD 258
#define CAP 80
#define SIM_SMEM ((128 * CPAD + SROWS * Cc + SROWS * CAP) * 4 + SROWS * CAP * 4 + SROWS * 8)

// exact tie-aware top-16 selection of buf[0..n) into buf[0..15]; updates thr/cnt
__device__ __noinline__ void refresh_row(float* __restrict__ v,
                                         int* __restrict__ ix,
                                         float* __restrict__ thr,
                                         int* __restrict__ cnt,
                                         int rl, int lane) {
  const unsigned FULL = 0xffffffffu;
  int n = cnt[rl];
#pragma unroll 1
  for (int pick = 0; pick < KT; pick++) {
    float mv = -3.4e38f; int mi = 0x7fffffff; int mp = pick;
    for (int s = pick + lane; s < n; s += 32) {
      float vv = v[s]; int ii = ix[s];
      if (vv > mv || (vv == mv && ii < mi)) { mv = vv; mi = ii; mp = s; }
    }
#pragma unroll
    for (int off = 16; off; off >>= 1) {
      float ov = __shfl_down_sync(FULL, mv, off);
      int oi = __shfl_down_sync(FULL, mi, off);
      int op = __shfl_down_sync(FULL, mp, off);
      if (ov > mv || (ov == mv && oi < mi)) { mv = ov; mi = oi; mp = op; }
    }
    mp = __shfl_sync(FULL, mp, 0);
    mv = __shfl_sync(FULL, mv, 0);
    mi = __shfl_sync(FULL, mi, 0);
    if (lane == 0 && mp != pick) {
      float tv = v[pick]; int ti = ix[pick];
      v[pick] = mv; ix[pick] = mi;
      v[mp] = tv; ix[mp] = ti;
    }
    __syncwarp();
  }
  if (lane == 0) { thr[rl] = v[KT - 1]; cnt[rl] = KT; }
  __syncwarp();
}

// one ballot-insert step for a single scalar candidate
#define COLLECT_ONE(val, colofs)                                          \
  do {                                                                    \
    float v_ = (val);                                                     \
    int colx_ = j0 + (colofs) + lane * 2;                                 \
    bool p_ = (colx_ < Nn) && (v_ >= thr_r);                              \
    unsigned mask_ = __ballot_sync(0xffffffffu, p_);                      \
    if (mask_) {                                                          \
      int base_ = cnt[rl];                                                \
      if (p_) {                                                           \
        int pos_ = base_ + __popc(mask_ & ((1u << lane) - 1u));           \
        bv[pos_] = v_;                                                    \
        bi[pos_] = colx_;                                                 \
      }                                                                   \
      int nb_ = base_ + __popc(mask_);                                    \
      if (lane == 0) cnt[rl] = nb_;                                       \
      __syncwarp();                                                       \
      if (nb_ >= CAP - 32) {                                              \
        refresh_row(bv, bi, thr, cnt, rl, lane);                          \
        thr_r = thr[rl];                                                  \
      }                                                                   \
    }                                                                     \
  } while (0)

// candidates for one row: 8 scalars = (c2,t) pairs, values passed by register
__device__ __noinline__ void collect_row(int rl, int j0, int lane,
                                         float4 va, float4 vb,
                                         float* __restrict__ bv,
                                         int* __restrict__ bi,
                                         float* __restrict__ thr,
                                         int* __restrict__ cnt) {
  float thr_r = thr[rl];
  COLLECT_ONE(va.x, 0);        // c2=0, t=0
  COLLECT_ONE(va.y, 1);        // c2=0, t=1
  COLLECT_ONE(va.z, 64);       // c2=1, t=0
  COLLECT_ONE(va.w, 65);       // c2=1, t=1
  COLLECT_ONE(vb.x, 128);      // c2=2, t=0
  COLLECT_ONE(vb.y, 129);      // c2=2, t=1
  COLLECT_ONE(vb.z, 192);      // c2=3, t=0
  COLLECT_ONE(vb.w, 193);      // c2=3, t=1
}

__global__ __launch_bounds__(STHREADS) void sim_topk_kernel() {
  extern __shared__ float sm[];
  float* colsT = sm;                              // [128][CPAD]
  float* rows  = sm + 128 * CPAD;                 // [SROWS][128]
  float* bufv  = rows + SROWS * Cc;               // [SROWS][CAP]
  int*   bufi  = (int*)(bufv + SROWS * CAP);      // [SROWS][CAP]
  float* thr   = (float*)(bufi + SROWS * CAP);    // [SROWS]
  int*   cnt   = (int*)(thr + SROWS);             // [SROWS]

  int r0 = blockIdx.x * SROWS;
  int tid = threadIdx.x;
  int warp = tid >> 5, lane = tid & 31;
  int rlbase = warp * RPW;

  for (int i = tid; i < SROWS * Cc; i += STHREADS) {
    int row = r0 + (i >> 7);
    rows[i] = (row < Nn) ? g_en[row * Cc + (i & 127)] : 0.f;
  }
  if (tid < SROWS) { thr[tid] = -3.3e38f; cnt[tid] = 0; }
  __syncthreads();

  int rlocal = lane >> 3;   // 0..3 (row within 4-row group of fill)
  int kc = lane & 7;        // 0..7 (16B k-chunk within quarter)

  // diagonal-first tile permutation
  int t0 = r0 / SCOLS;
  int t1 = (r0 + SROWS - 1) / SCOLS;
  int nlead = (t1 != t0) ? 2 : 1;
  int tlo = t0 < t1 ? t0 : t1, thi = t0 < t1 ? t1 : t0;

  for (int tt = 0; tt < NTILES; tt++) {
    int ti;
    if (tt == 0) ti = t0;
    else if (tt == 1 && nlead == 2) ti = t1;
    else {
      int idx = tt - nlead;
      ti = idx + (idx >= tlo ? 1 : 0);
      if (nlead == 2 && ti >= thi) ti++;
    }
    int j0 = ti * SCOLS;

    // ---- fill colsT[k][j] (transposed, coalesced float4 loads) ----
#pragma unroll 4
    for (int it = 0; it < 16; it++) {
      int u = it * 16 + warp;
      int rowgrp = u >> 2, kq = u & 3;
      int j = rowgrp * 4 + rlocal;    // 0..255
      int k4 = kq * 8 + kc;           // 0..31
      int col = j0 + j;
      float4 val = make_float4(0.f, 0.f, 0.f, 0.f);
      if (col < Nn) val = ((const float4*)g_en)[col * (Cc / 4) + k4];
      colsT[(k4 * 4 + 0) * CPAD + j] = val.x;
      colsT[(k4 * 4 + 1) * CPAD + j] = val.y;
      colsT[(k4 * 4 + 2) * CPAD + j] = val.z;
      colsT[(k4 * 4 + 3) * CPAD + j] = val.w;
    }
    __syncthreads();

    // ---- packed f32x2 GEMM: RPW rows x 8 cols (4 pairs) per lane ----
    unsigned long long acc[RPW][4];
#pragma unroll
    for (int r = 0; r < RPW; r++)
#pragma unroll
      for (int c2 = 0; c2 < 4; c2++) acc[r][c2] = 0ULL;

    const float* rowp = rows + rlbase * Cc;
#pragma unroll 4
    for (int k = 0; k < Cc; k++) {
      unsigned long long cv[4];
      const float* cb = colsT + k * CPAD + lane * 2;
#pragma unroll
      for (int c2 = 0; c2 < 4; c2++)
        cv[c2] = *(const unsigned long long*)(cb + c2 * 64);
#pragma unroll
      for (int r = 0; r < RPW; r++) {
        float rv = rowp[r * Cc + k];
        unsigned long long rv2;
        asm("mov.b64 %0, {%1, %1};" : "=l"(rv2) : "f"(rv));
#pragma unroll
        for (int c2 = 0; c2 < 4; c2++)
          asm("fma.rn.f32x2 %0, %1, %2, %0;"
              : "+l"(acc[r][c2]) : "l"(rv2), "l"(cv[c2]));
      }
    }

    // ---- threshold-buffer candidate collection (acc constant-indexed) ----
#pragma unroll
    for (int r = 0; r < RPW; r++) {
      int rl = rlbase + r;
      float4 va, vb;
      asm("mov.b64 {%0, %1}, %2;" : "=f"(va.x), "=f"(va.y) : "l"(acc[r][0]));
      asm("mov.b64 {%0, %1}, %2;" : "=f"(va.z), "=f"(va.w) : "l"(acc[r][1]));
      asm("mov.b64 {%0, %1}, %2;" : "=f"(vb.x), "=f"(vb.y) : "l"(acc[r][2]));
      asm("mov.b64 {%0, %1}, %2;" : "=f"(vb.z), "=f"(vb.w) : "l"(acc[r][3]));
      collect_row(rl, j0, lane, va, vb,
                  bufv + rl * CAP, bufi + rl * CAP, thr, cnt);
    }
    __syncthreads();
  }

  // ---- final exact selection + output ----
#pragma unroll 1
  for (int r = 0; r < RPW; r++) {
    int rl = rlbase + r;
    int grow = r0 + rl;
    if (grow >= Nn) continue;
    refresh_row(bufv + rl * CAP, bufi + rl * CAP, thr, cnt, rl, lane);
    if (lane < KT) {
      g_tval[grow * KT + lane] = bufv[rl * CAP + lane];
      g_tidx[grow * KT + lane] = bufi[rl * CAP + lane];
    }
  }
}

// ------------------------- 7) p_sim + final combine (deterministic) --------
__global__ __launch_bounds__(64) void psim_final_kernel(
    const int* __restrict__ y, float* __restrict__ out_final) {
  int n = blockIdx.x;
  int t = threadIdx.x;
  __shared__ float ex[KT];
  __shared__ int cls[KT];
  __shared__ float acc[NCc];
  __shared__ float red[2];
  if (t < KT) {
    ex[t] = expf(g_tval[n * KT + t]);
    cls[t] = y[g_tidx[n * KT + t]];
  }
  __syncthreads();
  if (t < NCc) {
    float s = 0.f;
    for (int j = 0; j < KT; j++)
      if (cls[j] == t) s += ex[j];
    acc[t] = s;
  }
  __syncthreads();
  if (t == 0) {
    float mx = acc[0];
    for (int i = 1; i < NCc; i++) mx = fmaxf(mx, acc[i]);
    float s = 0.f;
    for (int i = 0; i < NCc; i++) s += expf(acc[i] - mx);
    red[0] = mx;
    red[1] = logf(s);
  }
  __syncthreads();
  if (t < NCc)
    out_final[n * NCc + t] =
        0.5f * g_plc[n * NCc + t] + 0.5f * (acc[t] - red[0] - red[1]);
}

// ------------------------- host launch --------------------------------------
extern "C" void kernel_launch(void* const* d_in, const int* in_sizes, int n_in,
                              void* d_out, int out_size) {
  (void)in_sizes; (void)n_in; (void)out_size;
  const float* x  = (const float*)d_in[0];
  const float* W1 = (const float*)d_in[1];
  const float* b1 = (const float*)d_in[2];
  const float* Wq = (const float*)d_in[3];
  const float* bq = (const float*)d_in[4];
  const float* Wk = (const float*)d_in[5];
  const float* bk = (const float*)d_in[6];
  const float* Wv = (const float*)d_in[7];
  const float* bv = (const float*)d_in[8];
  const float* W2 = (const float*)d_in[9];
  const float* b2 = (const float*)d_in[10];
  const int* ei   = (const int*)d_in[11];
  const int* y    = (const int*)d_in[12];
  const int* rowi = ei;
  const int* coli = ei + Ee;
  float* out_final = (float*)d_out;
  float* out_emb   = (float*)d_out + (size_t)Nn * NCc;

  void* cntp = 0; cudaGetSymbolAddress(&cntp, g_cnt);
  void* curp = 0; cudaGetSymbolAddress(&curp, g_cur);
  cudaFuncSetAttribute(sim_topk_kernel,
                       cudaFuncAttributeMaxDynamicSharedMemorySize, SIM_SMEM);

  cudaMemsetAsync(cntp, 0, Nn * sizeof(int), 0);
  cudaMemsetAsync(curp, 0, Nn * sizeof(int), 0);
  gemm1_relu_kernel<<<(Nn + 63) / 64, 256>>>(x, W1, b1);
  count_kernel<<<(ETOT + 255) / 256, 256>>>(coli);
  dinv_kernel<<<(Nn + 255) / 256, 256>>>();
  norm_kernel<<<(ETOT + 255) / 256, 256>>>(rowi, coli);
  scan_kernel<<<1, 1024>>>();
  place_kernel<<<(ETOT + 255) / 256, 256>>>(coli);
  sort_bucket_kernel<<<(Nn + 127) / 128, 128>>>();

  for (int l = 0; l < NLAY; l++) {
    qkv_kernel<<<Nn, 128>>>(Wq, bq, Wk, bk, Wv, bv, l);
    switch (l) {
      case 0: attn_gather_kernel<1><<<Nn, 128>>>(rowi, l); break;
      case 1: attn_gather_kernel<2><<<Nn, 128>>>(rowi, l); break;
      case 2: attn_gather_kernel<3><<<Nn, 128>>>(rowi, l); break;
      default: attn_gather_kernel<4><<<Nn, 128>>>(rowi, l); break;
    }
  }

  emb_norm_kernel<<<Nn, 128>>>(out_emb);
  plc_kernel<<<Nn, 128>>>(W2, b2);
  sim_topk_kernel<<<SGRID, STHREADS, SIM_SMEM>>>();
  psim_final_kernel<<<Nn, 64>>>(y, out_final);
}

// round 12
// speedup vs baseline: 2.1770x; 1.0550x over previous
#include <cuda_runtime.h>
#include <math.h>

#define Nn 10000
#define Ee 160000
#define ETOT (Ee + Nn)
#define IND 512
#define Cc 128
#define NCc 40
#define NLAY 4
#define HE 8
#define GR 16
#define KT 16
#define DKk 16

// ------------------------- scratch (device globals; no allocations) ---------
__device__ float g_xall[Nn * 5 * Cc];   // x_all levels 0..4
__device__ float g_q[Nn * Cc];
__device__ float g_k[Nn * 4 * Cc];      // levels 0..3
__device__ float g_v[Nn * 4 * Cc];
__device__ int   g_cnt[Nn];             // in-degree incl self loop
__device__ float g_dinv[Nn];
__device__ float g_norm[ETOT];
__device__ int   g_off[Nn + 1];
__device__ int   g_cur[Nn];
__device__ int   g_eid[ETOT];
__device__ float g_en[Nn * Cc];
__device__ float g_plc[Nn * NCc];
__device__ float g_tval[Nn * KT];
__device__ int   g_tidx[Nn * KT];

// ------------------------- 1) h0 = relu(x @ W1 + b1) ------------------------
__global__ __launch_bounds__(256) void gemm1_relu_kernel(
    const float* __restrict__ x, const float* __restrict__ W1,
    const float* __restrict__ b1) {
  __shared__ float xs[32][65];    // xs[k][m], 64 rows
  __shared__ float ws[32][128];
  int m0 = blockIdx.x * 64;
  int tid = threadIdx.x;
  int tc = tid & 15;   // 16 col-groups of 8
  int tr = tid >> 4;   // 16 row-groups of 4
  float acc[4][8];
#pragma unroll
  for (int r = 0; r < 4; r++)
#pragma unroll
    for (int c = 0; c < 8; c++) acc[r][c] = 0.f;

  for (int k0 = 0; k0 < IND; k0 += 32) {
    for (int i = tid; i < 64 * 32; i += 256) {
      int m = i >> 5, k = i & 31;
      int row = m0 + m;
      xs[k][m] = (row < Nn) ? x[row * IND + k0 + k] : 0.f;
    }
    for (int i = tid; i < 32 * 128; i += 256) {
      int k = i >> 7, c = i & 127;
      ws[k][c] = W1[(k0 + k) * Cc + c];
    }
    __syncthreads();
#pragma unroll
    for (int k = 0; k < 32; k++) {
      float xv[4], wv[8];
#pragma unroll
      for (int r = 0; r < 4; r++) xv[r] = xs[k][tr * 4 + r];
#pragma unroll
      for (int c = 0; c < 8; c++) wv[c] = ws[k][tc * 8 + c];
#pragma unroll
      for (int r = 0; r < 4; r++)
#pragma unroll
        for (int c = 0; c < 8; c++) acc[r][c] = fmaf(xv[r], wv[c], acc[r][c]);
    }
    __syncthreads();
  }
#pragma unroll
  for (int r = 0; r < 4; r++) {
    int row = m0 + tr * 4 + r;
    if (row < Nn) {
#pragma unroll
      for (int c = 0; c < 8; c++) {
        int col = tc * 8 + c;
        float v = acc[r][c] + b1[col];
        g_xall[row * 5 * Cc + col] = v > 0.f ? v : 0.f;   // level 0
      }
    }
  }
}

// ------------------------- 2) gcn_norm + CSR build (deterministic) ----------
__global__ void count_kernel(const int* __restrict__ coli) {
  int e = blockIdx.x * blockDim.x + threadIdx.x;
  if (e >= ETOT) return;
  int c = (e < Ee) ? coli[e] : (e - Ee);
  atomicAdd(&g_cnt[c], 1);
}

__global__ void dinv_kernel() {
  int n = blockIdx.x * blockDim.x + threadIdx.x;
  if (n < Nn) g_dinv[n] = 1.0f / sqrtf((float)g_cnt[n]);
}

__global__ void norm_kernel(const int* __restrict__ rowi,
                            const int* __restrict__ coli) {
  int e = blockIdx.x * blockDim.x + threadIdx.x;
  if (e >= ETOT) return;
  if (e < Ee) g_norm[e] = g_dinv[rowi[e]] * g_dinv[coli[e]];
  else { float d = g_dinv[e - Ee]; g_norm[e] = d * d; }
}

// single-block exclusive scan of g_cnt -> g_off (1024 threads, 10 elems each)
__global__ __launch_bounds__(1024) void scan_kernel() {
  __shared__ int ssum[1024];
  int t = threadIdx.x;
  int base = t * 10;
  int loc[10];
  int s = 0;
#pragma unroll
  for (int i = 0; i < 10; i++) {
    int idx = base + i;
    int v = (idx < Nn) ? g_cnt[idx] : 0;
    loc[i] = s;
    s += v;
  }
  ssum[t] = s;
  __syncthreads();
  for (int off = 1; off < 1024; off <<= 1) {
    int v = (t >= off) ? ssum[t - off] : 0;
    __syncthreads();
    ssum[t] += v;
    __syncthreads();
  }
  int pre = (t > 0) ? ssum[t - 1] : 0;
#pragma unroll
  for (int i = 0; i < 10; i++) {
    int idx = base + i;
    if (idx < Nn) g_off[idx] = pre + loc[i];
  }
  if (t == 1023) g_off[Nn] = ssum[1023];
}

__global__ void place_kernel(const int* __restrict__ coli) {
  int e = blockIdx.x * blockDim.x + threadIdx.x;
  if (e >= ETOT) return;
  int c = (e < Ee) ? coli[e] : (e - Ee);
  int pos = atomicAdd(&g_cur[c], 1);
  g_eid[g_off[c] + pos] = e;
}

// canonicalize bucket order: insertion-sort each bucket ascending by edge id
__global__ void sort_bucket_kernel() {
  int n = blockIdx.x * blockDim.x + threadIdx.x;
  if (n >= Nn) return;
  int s = g_off[n], e2 = g_off[n + 1];
  for (int i = s + 1; i < e2; i++) {
    int key = g_eid[i];
    int j = i - 1;
    while (j >= s && g_eid[j] > key) { g_eid[j + 1] = g_eid[j]; j--; }
    g_eid[j + 1] = key;
  }
}

// ------------------------- 3a) grouped q/k/v per layer ---------------------
__global__ __launch_bounds__(128) void qkv_kernel(
    const float* __restrict__ Wq, const float* __restrict__ bq,
    const float* __restrict__ Wk, const float* __restrict__ bk,
    const float* __restrict__ Wv, const float* __restrict__ bv, int l) {
  int n = blockIdx.x;
  int c = threadIdx.x;
  int g = c >> 3, o = c & 7;
  __shared__ float xs[Cc];
  float wq[8], wk[8], wv[8];
  int base = ((l * GR + g) * 8) * 8 + o;
#pragma unroll
  for (int i = 0; i < 8; i++) {
    wq[i] = Wq[base + i * 8];
    wk[i] = Wk[base + i * 8];
    wv[i] = Wv[base + i * 8];
  }
  float bqv = bq[l * Cc + c], bkv = bk[l * Cc + c], bvv = bv[l * Cc + c];
  for (int lev = 0; lev <= l; lev++) {
    __syncthreads();
    xs[c] = g_xall[(n * 5 + lev) * Cc + c];
    __syncthreads();
    float xg[8];
#pragma unroll
    for (int i = 0; i < 8; i++) xg[i] = xs[g * 8 + i];
    float sk = bkv, sv = bvv;
#pragma unroll
    for (int i = 0; i < 8; i++) {
      sk = fmaf(xg[i], wk[i], sk);
      sv = fmaf(xg[i], wv[i], sv);
    }
    g_k[(n * 4 + lev) * Cc + c] = sk;
    g_v[(n * 4 + lev) * Cc + c] = sv;
    if (lev == l) {
      float sq = bqv;
#pragma unroll
      for (int i = 0; i < 8; i++) sq = fmaf(xg[i], wq[i], sq);
      g_q[n * Cc + c] = sq;
    }
  }
}

// ------------------------- 3b) deterministic attention gather --------------
template <int NLEV>
__global__ __launch_bounds__(128) void attn_gather_kernel(
    const int* __restrict__ rowi, int l) {
  int c = blockIdx.x;
  int tid = threadIdx.x;
  const unsigned FULL = 0xffffffffu;
  float qv = g_q[c * Cc + tid];
  int s = g_off[c], e2 = g_off[c + 1];
  float acc = 0.f;
  for (int p = s; p < e2; p++) {
    int e = g_eid[p];
    int r = (e < Ee) ? rowi[e] : (e - Ee);
    float nrm = g_norm[e];
    float kk[NLEV], vv[NLEV];
#pragma unroll
    for (int lev = 0; lev < NLEV; lev++) {
      kk[lev] = g_k[(r * 4 + lev) * Cc + tid];
      vv[lev] = g_v[(r * 4 + lev) * Cc + tid];
    }
    float sc[NLEV];
    float mx = -1e30f;
#pragma unroll
    for (int lev = 0; lev < NLEV; lev++) {
      float t = qv * kk[lev];
      t += __shfl_xor_sync(FULL, t, 8);
      t += __shfl_xor_sync(FULL, t, 4);
      t += __shfl_xor_sync(FULL, t, 2);
      t += __shfl_xor_sync(FULL, t, 1);
      t *= 0.25f;   // 1/sqrt(DK)
      sc[lev] = t;
      mx = fmaxf(mx, t);
    }
    float den = 0.f;
#pragma unroll
    for (int lev = 0; lev < NLEV; lev++) {
      sc[lev] = expf(sc[lev] - mx);
      den += sc[lev];
    }
    float w = nrm / den;
#pragma unroll
    for (int lev = 0; lev < NLEV; lev++)
      acc = fmaf(sc[lev] * w, vv[lev], acc);
  }
  g_xall[(c * 5 + l + 1) * Cc + tid] = acc > 0.f ? acc : 0.f;
}

// ------------------------- 4) emb out + L2 normalize -----------------------
__global__ __launch_bounds__(128) void emb_norm_kernel(float* __restrict__ out_emb) {
  int n = blockIdx.x;
  int c = threadIdx.x;
  float v = g_xall[(n * 5 + 4) * Cc + c];
  out_emb[n * Cc + c] = v;
  float ss = v * v;
#pragma unroll
  for (int off = 16; off; off >>= 1) ss += __shfl_down_sync(0xffffffffu, ss, off);
  __shared__ float ws[4];
  if ((c & 31) == 0) ws[c >> 5] = ss;
  __syncthreads();
  float tot = ws[0] + ws[1] + ws[2] + ws[3];
  float nrm = fmaxf(sqrtf(tot), 1e-8f);
  g_en[n * Cc + c] = v / nrm;
}

// ------------------------- 5) p_lc = log_softmax(emb@W2+b2) ----------------
__global__ __launch_bounds__(128) void plc_kernel(const float* __restrict__ W2,
                                                  const float* __restrict__ b2) {
  int n = blockIdx.x;
  int t = threadIdx.x;
  __shared__ float xr[Cc];
  __shared__ float lg[NCc];
  __shared__ float red[2];
  xr[t] = g_xall[(n * 5 + 4) * Cc + t];
  __syncthreads();
  if (t < NCc) {
    float s = b2[t];
    for (int k = 0; k < Cc; k++) s = fmaf(xr[k], W2[k * NCc + t], s);
    lg[t] = s;
  }
  __syncthreads();
  if (t == 0) {
    float mx = lg[0];
    for (int i = 1; i < NCc; i++) mx = fmaxf(mx, lg[i]);
    float s = 0.f;
    for (int i = 0; i < NCc; i++) s += expf(lg[i] - mx);
    red[0] = mx;
    red[1] = logf(s);
  }
  __syncthreads();
  if (t < NCc) g_plc[n * NCc + t] = lg[t] - red[0] - red[1];
}

// ------------------------- 6) fused sim = en@en^T + top-16 -----------------
// f32x2 packed-FMA GEMM + threshold-buffer candidate top-k (exact, deterministic)
// v7: v5 shape (512 thr, SROWS=80, grid=125, single wave), ascending tiles
// (diag-first reverted: measured +130us), + rowmax-guard fast path in collect
// (bit-identical: skips only all-below-threshold cases == 8 empty ballots).
#define SROWS 80     // rows per block (16 warps x 5 rows)
#define RPW 5
#define SGRID 125    // 125 * 80 = 10000 exactly; single wave on 148 SMs
#define STHREADS 512
#define SCOLS 256
#define CPAD 258
#define CAP 80
#define SIM_SMEM ((128 * CPAD + SROWS * Cc + SROWS * CAP) * 4 + SROWS * CAP * 4 + SROWS * 8)

// exact tie-aware top-16 selection of buf[0..n) into buf[0..15]; updates thr/cnt
__device__ __noinline__ void refresh_row(float* __restrict__ v,
                                         int* __restrict__ ix,
                                         float* __restrict__ thr,
                                         int* __restrict__ cnt,
                                         int rl, int lane) {
  const unsigned FULL = 0xffffffffu;
  int n = cnt[rl];
#pragma unroll 1
  for (int pick = 0; pick < KT; pick++) {
    float mv = -3.4e38f; int mi = 0x7fffffff; int mp = pick;
    for (int s = pick + lane; s < n; s += 32) {
      float vv = v[s]; int ii = ix[s];
      if (vv > mv || (vv == mv && ii < mi)) { mv = vv; mi = ii; mp = s; }
    }
#pragma unroll
    for (int off = 16; off; off >>= 1) {
      float ov = __shfl_down_sync(FULL, mv, off);
      int oi = __shfl_down_sync(FULL, mi, off);
      int op = __shfl_down_sync(FULL, mp, off);
      if (ov > mv || (ov == mv && oi < mi)) { mv = ov; mi = oi; mp = op; }
    }
    mp = __shfl_sync(FULL, mp, 0);
    mv = __shfl_sync(FULL, mv, 0);
    mi = __shfl_sync(FULL, mi, 0);
    if (lane == 0 && mp != pick) {
      float tv = v[pick]; int ti = ix[pick];
      v[pick] = mv; ix[pick] = mi;
      v[mp] = tv; ix[mp] = ti;
    }
    __syncwarp();
  }
  if (lane == 0) { thr[rl] = v[KT - 1]; cnt[rl] = KT; }
  __syncwarp();
}

// one ballot-insert step for a single scalar candidate
#define COLLECT_ONE(val, colofs)                                          \
  do {                                                                    \
    float v_ = (val);                                                     \
    int colx_ = j0 + (colofs) + lane * 2;                                 \
    bool p_ = (colx_ < Nn) && (v_ >= thr_r);                              \
    unsigned mask_ = __ballot_sync(0xffffffffu, p_);                      \
    if (mask_) {                                                          \
      int base_ = cnt[rl];                                                \
      if (p_) {                                                           \
        int pos_ = base_ + __popc(mask_ & ((1u << lane) - 1u));           \
        bv[pos_] = v_;                                                    \
        bi[pos_] = colx_;                                                 \
      }                                                                   \
      int nb_ = base_ + __popc(mask_);                                    \
      if (lane == 0) cnt[rl] = nb_;                                       \
      __syncwarp();                                                       \
      if (nb_ >= CAP - 32) {                                              \
        refresh_row(bv, bi, thr, cnt, rl, lane);                          \
        thr_r = thr[rl];                                                  \
      }                                                                   \
    }                                                                     \
  } while (0)

// candidates for one row: 8 scalars = (c2,t) pairs, values passed by register.
// rowmax guard: if every candidate in the warp is below threshold, skip all 8
// ballots (exactly equivalent to 8 empty-mask COLLECT_ONEs).
__device__ __noinline__ void collect_row(int rl, int j0, int lane,
                                         float4 va, float4 vb,
                                         float* __restrict__ bv,
                                         int* __restrict__ bi,
                                         float* __restrict__ thr,
                                         int* __restrict__ cnt) {
  float thr_r = thr[rl];
  float m0 = fmaxf(fmaxf(va.x, va.y), fmaxf(va.z, va.w));
  float m1 = fmaxf(fmaxf(vb.x, vb.y), fmaxf(vb.z, vb.w));
  float rmax = fmaxf(m0, m1);
  unsigned any = __ballot_sync(0xffffffffu, rmax >= thr_r);
  if (!any) return;
  COLLECT_ONE(va.x, 0);        // c2=0, t=0
  COLLECT_ONE(va.y, 1);        // c2=0, t=1
  COLLECT_ONE(va.z, 64);       // c2=1, t=0
  COLLECT_ONE(va.w, 65);       // c2=1, t=1
  COLLECT_ONE(vb.x, 128);      // c2=2, t=0
  COLLECT_ONE(vb.y, 129);      // c2=2, t=1
  COLLECT_ONE(vb.z, 192);      // c2=3, t=0
  COLLECT_ONE(vb.w, 193);      // c2=3, t=1
}

__global__ __launch_bounds__(STHREADS) void sim_topk_kernel() {
  extern __shared__ float sm[];
  float* colsT = sm;                              // [128][CPAD]
  float* rows  = sm + 128 * CPAD;                 // [SROWS][128]
  float* bufv  = rows + SROWS * Cc;               // [SROWS][CAP]
  int*   bufi  = (int*)(bufv + SROWS * CAP);      // [SROWS][CAP]
  float* thr   = (float*)(bufi + SROWS * CAP);    // [SROWS]
  int*   cnt   = (int*)(thr + SROWS);             // [SROWS]

  int r0 = blockIdx.x * SROWS;
  int tid = threadIdx.x;
  int warp = tid >> 5, lane = tid & 31;
  int rlbase = warp * RPW;

  for (int i = tid; i < SROWS * Cc; i += STHREADS) {
    int row = r0 + (i >> 7);
    rows[i] = (row < Nn) ? g_en[row * Cc + (i & 127)] : 0.f;
  }
  if (tid < SROWS) { thr[tid] = -3.3e38f; cnt[tid] = 0; }
  __syncthreads();

  int rlocal = lane >> 3;   // 0..3 (row within 4-row group of fill)
  int kc = lane & 7;        // 0..7 (16B k-chunk within quarter)

  for (int j0 = 0; j0 < Nn; j0 += SCOLS) {
    // ---- fill colsT[k][j] (transposed, coalesced float4 loads) ----
#pragma unroll 4
    for (int it = 0; it < 16; it++) {
      int u = it * 16 + warp;
      int rowgrp = u >> 2, kq = u & 3;
      int j = rowgrp * 4 + rlocal;    // 0..255
      int k4 = kq * 8 + kc;           // 0..31
      int col = j0 + j;
      float4 val = make_float4(0.f, 0.f, 0.f, 0.f);
      if (col < Nn) val = ((const float4*)g_en)[col * (Cc / 4) + k4];
      colsT[(k4 * 4 + 0) * CPAD + j] = val.x;
      colsT[(k4 * 4 + 1) * CPAD + j] = val.y;
      colsT[(k4 * 4 + 2) * CPAD + j] = val.z;
      colsT[(k4 * 4 + 3) * CPAD + j] = val.w;
    }
    __syncthreads();

    // ---- packed f32x2 GEMM: RPW rows x 8 cols (4 pairs) per lane ----
    unsigned long long acc[RPW][4];
#pragma unroll
    for (int r = 0; r < RPW; r++)
#pragma unroll
      for (int c2 = 0; c2 < 4; c2++) acc[r][c2] = 0ULL;

    const float* rowp = rows + rlbase * Cc;
#pragma unroll 4
    for (int k = 0; k < Cc; k++) {
      unsigned long long cv[4];
      const float* cb = colsT + k * CPAD + lane * 2;
#pragma unroll
      for (int c2 = 0; c2 < 4; c2++)
        cv[c2] = *(const unsigned long long*)(cb + c2 * 64);
#pragma unroll
      for (int r = 0; r < RPW; r++) {
        float rv = rowp[r * Cc + k];
        unsigned long long rv2;
        asm("mov.b64 %0, {%1, %1};" : "=l"(rv2) : "f"(rv));
#pragma unroll
        for (int c2 = 0; c2 < 4; c2++)
          asm("fma.rn.f32x2 %0, %1, %2, %0;"
              : "+l"(acc[r][c2]) : "l"(rv2), "l"(cv[c2]));
      }
    }

    // ---- threshold-buffer candidate collection (acc constant-indexed) ----
#pragma unroll
    for (int r = 0; r < RPW; r++) {
      int rl = rlbase + r;
      float4 va, vb;
      asm("mov.b64 {%0, %1}, %2;" : "=f"(va.x), "=f"(va.y) : "l"(acc[r][0]));
      asm("mov.b64 {%0, %1}, %2;" : "=f"(va.z), "=f"(va.w) : "l"(acc[r][1]));
      asm("mov.b64 {%0, %1}, %2;" : "=f"(vb.x), "=f"(vb.y) : "l"(acc[r][2]));
      asm("mov.b64 {%0, %1}, %2;" : "=f"(vb.z), "=f"(vb.w) : "l"(acc[r][3]));
      collect_row(rl, j0, lane, va, vb,
                  bufv + rl * CAP, bufi + rl * CAP, thr, cnt);
    }
    __syncthreads();
  }

  // ---- final exact selection + output ----
#pragma unroll 1
  for (int r = 0; r < RPW; r++) {
    int rl = rlbase + r;
    int grow = r0 + rl;
    if (grow >= Nn) continue;
    refresh_row(bufv + rl * CAP, bufi + rl * CAP, thr, cnt, rl, lane);
    if (lane < KT) {
      g_tval[grow * KT + lane] = bufv[rl * CAP + lane];
      g_tidx[grow * KT + lane] = bufi[rl * CAP + lane];
    }
  }
}

// ------------------------- 7) p_sim + final combine (deterministic) --------
__global__ __launch_bounds__(64) void psim_final_kernel(
    const int* __restrict__ y, float* __restrict__ out_final) {
  int n = blockIdx.x;
  int t = threadIdx.x;
  __shared__ float ex[KT];
  __shared__ int cls[KT];
  __shared__ float acc[NCc];
  __shared__ float red[2];
  if (t < KT) {
    ex[t] = expf(g_tval[n * KT + t]);
    cls[t] = y[g_tidx[n * KT + t]];
  }
  __syncthreads();
  if (t < NCc) {
    float s = 0.f;
    for (int j = 0; j < KT; j++)
      if (cls[j] == t) s += ex[j];
    acc[t] = s;
  }
  __syncthreads();
  if (t == 0) {
    float mx = acc[0];
    for (int i = 1; i < NCc; i++) mx = fmaxf(mx, acc[i]);
    float s = 0.f;
    for (int i = 0; i < NCc; i++) s += expf(acc[i] - mx);
    red[0] = mx;
    red[1] = logf(s);
  }
  __syncthreads();
  if (t < NCc)
    out_final[n * NCc + t] =
        0.5f * g_plc[n * NCc + t] + 0.5f * (acc[t] - red[0] - red[1]);
}

// ------------------------- host launch --------------------------------------
extern "C" void kernel_launch(void* const* d_in, const int* in_sizes, int n_in,
                              void* d_out, int out_size) {
  (void)in_sizes; (void)n_in; (void)out_size;
  const float* x  = (const float*)d_in[0];
  const float* W1 = (const float*)d_in[1];
  const float* b1 = (const float*)d_in[2];
  const float* Wq = (const float*)d_in[3];
  const float* bq = (const float*)d_in[4];
  const float* Wk = (const float*)d_in[5];
  const float* bk = (const float*)d_in[6];
  const float* Wv = (const float*)d_in[7];
  const float* bv = (const float*)d_in[8];
  const float* W2 = (const float*)d_in[9];
  const float* b2 = (const float*)d_in[10];
  const int* ei   = (const int*)d_in[11];
  const int* y    = (const int*)d_in[12];
  const int* rowi = ei;
  const int* coli = ei + Ee;
  float* out_final = (float*)d_out;
  float* out_emb   = (float*)d_out + (size_t)Nn * NCc;

  void* cntp = 0; cudaGetSymbolAddress(&cntp, g_cnt);
  void* curp = 0; cudaGetSymbolAddress(&curp, g_cur);
  cudaFuncSetAttribute(sim_topk_kernel,
                       cudaFuncAttributeMaxDynamicSharedMemorySize, SIM_SMEM);

  // Launch slots (ncu captures slot 6 via -s 5 -c 1, memsets included).
  // Slot 6 = attn_gather<4> diagnostic on nodes [0,2000): reads CSR (built) +
  // q/k/v/norm junk (prev replay / zeros on first call); writes only g_xall
  // level-4 rows 0..1999, which the real layer-4 attention overwrites before
  // any consumer reads level 4. Output provably unchanged.
  cudaMemsetAsync(cntp, 0, Nn * sizeof(int), 0);                 // 1
  cudaMemsetAsync(curp, 0, Nn * sizeof(int), 0);                 // 2
  count_kernel<<<(ETOT + 255) / 256, 256>>>(coli);               // 3
  scan_kernel<<<1, 1024>>>();                                    // 4
  place_kernel<<<(ETOT + 255) / 256, 256>>>(coli);               // 5
  attn_gather_kernel<4><<<2000, 128>>>(rowi, 3);                 // 6 <- ncu
  gemm1_relu_kernel<<<(Nn + 63) / 64, 256>>>(x, W1, b1);
  dinv_kernel<<<(Nn + 255) / 256, 256>>>();
  norm_kernel<<<(ETOT + 255) / 256, 256>>>(rowi, coli);
  sort_bucket_kernel<<<(Nn + 127) / 128, 128>>>();

  for (int l = 0; l < NLAY; l++) {
    qkv_kernel<<<Nn, 128>>>(Wq, bq, Wk, bk, Wv, bv, l);
    switch (l) {
      case 0: attn_gather_kernel<1><<<Nn, 128>>>(rowi, l); break;
      case 1: attn_gather_kernel<2><<<Nn, 128>>>(rowi, l); break;
      case 2: attn_gather_kernel<3><<<Nn, 128>>>(rowi, l); break;
      default: attn_gather_kernel<4><<<Nn, 128>>>(rowi, l); break;
    }
  }

  emb_norm_kernel<<<Nn, 128>>>(out_emb);
  plc_kernel<<<Nn, 128>>>(W2, b2);
  sim_topk_kernel<<<SGRID, STHREADS, SIM_SMEM>>>();
  psim_final_kernel<<<Nn, 64>>>(y, out_final);
}

// round 13
// speedup vs baseline: 2.1932x; 1.0074x over previous
#include <cuda_runtime.h>
#include <math.h>

#define Nn 10000
#define Ee 160000
#define ETOT (Ee + Nn)
#define IND 512
#define Cc 128
#define NCc 40
#define NLAY 4
#define HE 8
#define GR 16
#define KT 16
#define DKk 16

// ------------------------- scratch (device globals; no allocations) ---------
__device__ float g_xall[Nn * 5 * Cc];   // x_all levels 0..4
__device__ float g_q[Nn * Cc];
__device__ float g_k[Nn * 4 * Cc];      // levels 0..3
__device__ float g_v[Nn * 4 * Cc];
__device__ int   g_cnt[Nn];             // in-degree incl self loop
__device__ float g_dinv[Nn];
__device__ float g_norm[ETOT];
__device__ int   g_off[Nn + 1];
__device__ int   g_cur[Nn];
__device__ int   g_eid[ETOT];
__device__ float g_en[Nn * Cc];
__device__ float g_plc[Nn * NCc];
__device__ float g_tval[Nn * KT];
__device__ int   g_tidx[Nn * KT];

// ------------------------- 1) h0 = relu(x @ W1 + b1) ------------------------
__global__ __launch_bounds__(256) void gemm1_relu_kernel(
    const float* __restrict__ x, const float* __restrict__ W1,
    const float* __restrict__ b1) {
  __shared__ float xs[32][65];    // xs[k][m], 64 rows
  __shared__ float ws[32][128];
  int m0 = blockIdx.x * 64;
  int tid = threadIdx.x;
  int tc = tid & 15;   // 16 col-groups of 8
  int tr = tid >> 4;   // 16 row-groups of 4
  float acc[4][8];
#pragma unroll
  for (int r = 0; r < 4; r++)
#pragma unroll
    for (int c = 0; c < 8; c++) acc[r][c] = 0.f;

  for (int k0 = 0; k0 < IND; k0 += 32) {
    for (int i = tid; i < 64 * 32; i += 256) {
      int m = i >> 5, k = i & 31;
      int row = m0 + m;
      xs[k][m] = (row < Nn) ? x[row * IND + k0 + k] : 0.f;
    }
    for (int i = tid; i < 32 * 128; i += 256) {
      int k = i >> 7, c = i & 127;
      ws[k][c] = W1[(k0 + k) * Cc + c];
    }
    __syncthreads();
#pragma unroll
    for (int k = 0; k < 32; k++) {
      float xv[4], wv[8];
#pragma unroll
      for (int r = 0; r < 4; r++) xv[r] = xs[k][tr * 4 + r];
#pragma unroll
      for (int c = 0; c < 8; c++) wv[c] = ws[k][tc * 8 + c];
#pragma unroll
      for (int r = 0; r < 4; r++)
#pragma unroll
        for (int c = 0; c < 8; c++) acc[r][c] = fmaf(xv[r], wv[c], acc[r][c]);
    }
    __syncthreads();
  }
#pragma unroll
  for (int r = 0; r < 4; r++) {
    int row = m0 + tr * 4 + r;
    if (row < Nn) {
#pragma unroll
      for (int c = 0; c < 8; c++) {
        int col = tc * 8 + c;
        float v = acc[r][c] + b1[col];
        g_xall[row * 5 * Cc + col] = v > 0.f ? v : 0.f;   // level 0
      }
    }
  }
}

// ------------------------- 2) gcn_norm + CSR build (deterministic) ----------
__global__ void count_kernel(const int* __restrict__ coli) {
  int e = blockIdx.x * blockDim.x + threadIdx.x;
  if (e >= ETOT) return;
  int c = (e < Ee) ? coli[e] : (e - Ee);
  atomicAdd(&g_cnt[c], 1);
}

__global__ void dinv_kernel() {
  int n = blockIdx.x * blockDim.x + threadIdx.x;
  if (n < Nn) g_dinv[n] = 1.0f / sqrtf((float)g_cnt[n]);
}

__global__ void norm_kernel(const int* __restrict__ rowi,
                            const int* __restrict__ coli) {
  int e = blockIdx.x * blockDim.x + threadIdx.x;
  if (e >= ETOT) return;
  if (e < Ee) g_norm[e] = g_dinv[rowi[e]] * g_dinv[coli[e]];
  else { float d = g_dinv[e - Ee]; g_norm[e] = d * d; }
}

// single-block exclusive scan of g_cnt -> g_off (1024 threads, 10 elems each)
__global__ __launch_bounds__(1024) void scan_kernel() {
  __shared__ int ssum[1024];
  int t = threadIdx.x;
  int base = t * 10;
  int loc[10];
  int s = 0;
#pragma unroll
  for (int i = 0; i < 10; i++) {
    int idx = base + i;
    int v = (idx < Nn) ? g_cnt[idx] : 0;
    loc[i] = s;
    s += v;
  }
  ssum[t] = s;
  __syncthreads();
  for (int off = 1; off < 1024; off <<= 1) {
    int v = (t >= off) ? ssum[t - off] : 0;
    __syncthreads();
    ssum[t] += v;
    __syncthreads();
  }
  int pre = (t > 0) ? ssum[t - 1] : 0;
#pragma unroll
  for (int i = 0; i < 10; i++) {
    int idx = base + i;
    if (idx < Nn) g_off[idx] = pre + loc[i];
  }
  if (t == 1023) g_off[Nn] = ssum[1023];
}

__global__ void place_kernel(const int* __restrict__ coli) {
  int e = blockIdx.x * blockDim.x + threadIdx.x;
  if (e >= ETOT) return;
  int c = (e < Ee) ? coli[e] : (e - Ee);
  int pos = atomicAdd(&g_cur[c], 1);
  g_eid[g_off[c] + pos] = e;
}

// canonicalize bucket order: insertion-sort each bucket ascending by edge id
__global__ void sort_bucket_kernel() {
  int n = blockIdx.x * blockDim.x + threadIdx.x;
  if (n >= Nn) return;
  int s = g_off[n], e2 = g_off[n + 1];
  for (int i = s + 1; i < e2; i++) {
    int key = g_eid[i];
    int j = i - 1;
    while (j >= s && g_eid[j] > key) { g_eid[j + 1] = g_eid[j]; j--; }
    g_eid[j + 1] = key;
  }
}

// ------------------------- 3a) grouped q/k/v per layer ---------------------
__global__ __launch_bounds__(128) void qkv_kernel(
    const float* __restrict__ Wq, const float* __restrict__ bq,
    const float* __restrict__ Wk, const float* __restrict__ bk,
    const float* __restrict__ Wv, const float* __restrict__ bv, int l) {
  int n = blockIdx.x;
  int c = threadIdx.x;
  int g = c >> 3, o = c & 7;
  __shared__ float xs[Cc];
  float wq[8], wk[8], wv[8];
  int base = ((l * GR + g) * 8) * 8 + o;
#pragma unroll
  for (int i = 0; i < 8; i++) {
    wq[i] = Wq[base + i * 8];
    wk[i] = Wk[base + i * 8];
    wv[i] = Wv[base + i * 8];
  }
  float bqv = bq[l * Cc + c], bkv = bk[l * Cc + c], bvv = bv[l * Cc + c];
  for (int lev = 0; lev <= l; lev++) {
    __syncthreads();
    xs[c] = g_xall[(n * 5 + lev) * Cc + c];
    __syncthreads();
    float xg[8];
#pragma unroll
    for (int i = 0; i < 8; i++) xg[i] = xs[g * 8 + i];
    float sk = bkv, sv = bvv;
#pragma unroll
    for (int i = 0; i < 8; i++) {
      sk = fmaf(xg[i], wk[i], sk);
      sv = fmaf(xg[i], wv[i], sv);
    }
    g_k[(n * 4 + lev) * Cc + c] = sk;
    g_v[(n * 4 + lev) * Cc + c] = sv;
    if (lev == l) {
      float sq = bqv;
#pragma unroll
      for (int i = 0; i < 8; i++) sq = fmaf(xg[i], wq[i], sq);
      g_q[n * Cc + c] = sq;
    }
  }
}

// ------------------------- 3b) deterministic attention gather --------------
// ILP-2 edge unroll: two edges' loads + softmax chains in flight per
// iteration; accumulation applied in strict edge order (bit-identical).
template <int NLEV>
__device__ __forceinline__ float edge_weight(int r, int e, float qv, int tid,
                                             float* __restrict__ sc) {
  const unsigned FULL = 0xffffffffu;
  float nrm = g_norm[e];
  float mx = -1e30f;
#pragma unroll
  for (int lev = 0; lev < NLEV; lev++) {
    float t = qv * g_k[(r * 4 + lev) * Cc + tid];
    t += __shfl_xor_sync(FULL, t, 8);
    t += __shfl_xor_sync(FULL, t, 4);
    t += __shfl_xor_sync(FULL, t, 2);
    t += __shfl_xor_sync(FULL, t, 1);
    t *= 0.25f;   // 1/sqrt(DK)
    sc[lev] = t;
    mx = fmaxf(mx, t);
  }
  float den = 0.f;
#pragma unroll
  for (int lev = 0; lev < NLEV; lev++) {
    sc[lev] = expf(sc[lev] - mx);
    den += sc[lev];
  }
  return nrm / den;
}

template <int NLEV>
__global__ __launch_bounds__(128) void attn_gather_kernel(
    const int* __restrict__ rowi, int l) {
  int c = blockIdx.x;
  int tid = threadIdx.x;
  float qv = g_q[c * Cc + tid];
  int s = g_off[c], e2 = g_off[c + 1];
  float acc = 0.f;
  int p = s;
  for (; p + 1 < e2; p += 2) {
    int ea = g_eid[p];
    int eb = g_eid[p + 1];
    int ra = (ea < Ee) ? rowi[ea] : (ea - Ee);
    int rb = (eb < Ee) ? rowi[eb] : (eb - Ee);
    // both edges' v loads issued up front (independent of weight chains)
    float va[NLEV], vb[NLEV];
#pragma unroll
    for (int lev = 0; lev < NLEV; lev++) {
      va[lev] = g_v[(ra * 4 + lev) * Cc + tid];
      vb[lev] = g_v[(rb * 4 + lev) * Cc + tid];
    }
    float sca[NLEV], scb[NLEV];
    float wa = edge_weight<NLEV>(ra, ea, qv, tid, sca);
    float wb = edge_weight<NLEV>(rb, eb, qv, tid, scb);
    // accumulate in strict edge order (bit-identical to one-edge loop)
#pragma unroll
    for (int lev = 0; lev < NLEV; lev++)
      acc = fmaf(sca[lev] * wa, va[lev], acc);
#pragma unroll
    for (int lev = 0; lev < NLEV; lev++)
      acc = fmaf(scb[lev] * wb, vb[lev], acc);
  }
  if (p < e2) {
    int e = g_eid[p];
    int r = (e < Ee) ? rowi[e] : (e - Ee);
    float vv[NLEV];
#pragma unroll
    for (int lev = 0; lev < NLEV; lev++)
      vv[lev] = g_v[(r * 4 + lev) * Cc + tid];
    float sc[NLEV];
    float w = edge_weight<NLEV>(r, e, qv, tid, sc);
#pragma unroll
    for (int lev = 0; lev < NLEV; lev++)
      acc = fmaf(sc[lev] * w, vv[lev], acc);
  }
  g_xall[(c * 5 + l + 1) * Cc + tid] = acc > 0.f ? acc : 0.f;
}

// ------------------------- 4) emb out + L2 normalize -----------------------
__global__ __launch_bounds__(128) void emb_norm_kernel(float* __restrict__ out_emb) {
  int n = blockIdx.x;
  int c = threadIdx.x;
  float v = g_xall[(n * 5 + 4) * Cc + c];
  out_emb[n * Cc + c] = v;
  float ss = v * v;
#pragma unroll
  for (int off = 16; off; off >>= 1) ss += __shfl_down_sync(0xffffffffu, ss, off);
  __shared__ float ws[4];
  if ((c & 31) == 0) ws[c >> 5] = ss;
  __syncthreads();
  float tot = ws[0] + ws[1] + ws[2] + ws[3];
  float nrm = fmaxf(sqrtf(tot), 1e-8f);
  g_en[n * Cc + c] = v / nrm;
}

// ------------------------- 5) p_lc = log_softmax(emb@W2+b2) ----------------
__global__ __launch_bounds__(128) void plc_kernel(const float* __restrict__ W2,
                                                  const float* __restrict__ b2) {
  int n = blockIdx.x;
  int t = threadIdx.x;
  __shared__ float xr[Cc];
  __shared__ float lg[NCc];
  __shared__ float red[2];
  xr[t] = g_xall[(n * 5 + 4) * Cc + t];
  __syncthreads();
  if (t < NCc) {
    float s = b2[t];
    for (int k = 0; k < Cc; k++) s = fmaf(xr[k], W2[k * NCc + t], s);
    lg[t] = s;
  }
  __syncthreads();
  if (t == 0) {
    float mx = lg[0];
    for (int i = 1; i < NCc; i++) mx = fmaxf(mx, lg[i]);
    float s = 0.f;
    for (int i = 0; i < NCc; i++) s += expf(lg[i] - mx);
    red[0] = mx;
    red[1] = logf(s);
  }
  __syncthreads();
  if (t < NCc) g_plc[n * NCc + t] = lg[t] - red[0] - red[1];
}

// ------------------------- 6) fused sim = en@en^T + top-16 -----------------
// f32x2 packed-FMA GEMM + threshold-buffer candidate top-k (exact, deterministic)
// v7 (current best): 512 thr, SROWS=80, grid=125 single wave, ascending tiles,
// rowmax-guard collect.
#define SROWS 80     // rows per block (16 warps x 5 rows)
#define RPW 5
#define SGRID 125    // 125 * 80 = 10000 exactly; single wave on 148 SMs
#define STHREADS 512
#define SCOLS 256
#define CPAD 258
#define CAP 80
#define SIM_SMEM ((128 * CPAD + SROWS * Cc + SROWS * CAP) * 4 + SROWS * CAP * 4 + SROWS * 8)

// exact tie-aware top-16 selection of buf[0..n) into buf[0..15]; updates thr/cnt
__device__ __noinline__ void refresh_row(float* __restrict__ v,
                                         int* __restrict__ ix,
                                         float* __restrict__ thr,
                                         int* __restrict__ cnt,
                                         int rl, int lane) {
  const unsigned FULL = 0xffffffffu;
  int n = cnt[rl];
#pragma unroll 1
  for (int pick = 0; pick < KT; pick++) {
    float mv = -3.4e38f; int mi = 0x7fffffff; int mp = pick;
    for (int s = pick + lane; s < n; s += 32) {
      float vv = v[s]; int ii = ix[s];
      if (vv > mv || (vv == mv && ii < mi)) { mv = vv; mi = ii; mp = s; }
    }
#pragma unroll
    for (int off = 16; off; off >>= 1) {
      float ov = __shfl_down_sync(FULL, mv, off);
      int oi = __shfl_down_sync(FULL, mi, off);
      int op = __shfl_down_sync(FULL, mp, off);
      if (ov > mv || (ov == mv && oi < mi)) { mv = ov; mi = oi; mp = op; }
    }
    mp = __shfl_sync(FULL, mp, 0);
    mv = __shfl_sync(FULL, mv, 0);
    mi = __shfl_sync(FULL, mi, 0);
    if (lane == 0 && mp != pick) {
      float tv = v[pick]; int ti = ix[pick];
      v[pick] = mv; ix[pick] = mi;
      v[mp] = tv; ix[mp] = ti;
    }
    __syncwarp();
  }
  if (lane == 0) { thr[rl] = v[KT - 1]; cnt[rl] = KT; }
  __syncwarp();
}

// one ballot-insert step for a single scalar candidate
#define COLLECT_ONE(val, colofs)                                          \
  do {                                                                    \
    float v_ = (val);                                                     \
    int colx_ = j0 + (colofs) + lane * 2;                                 \
    bool p_ = (colx_ < Nn) && (v_ >= thr_r);                              \
    unsigned mask_ = __ballot_sync(0xffffffffu, p_);                      \
    if (mask_) {                                                          \
      int base_ = cnt[rl];                                                \
      if (p_) {                                                           \
        int pos_ = base_ + __popc(mask_ & ((1u << lane) - 1u));           \
        bv[pos_] = v_;                                                    \
        bi[pos_] = colx_;                                                 \
      }                                                                   \
      int nb_ = base_ + __popc(mask_);                                    \
      if (lane == 0) cnt[rl] = nb_;                                       \
      __syncwarp();                                                       \
      if (nb_ >= CAP - 32) {                                              \
        refresh_row(bv, bi, thr, cnt, rl, lane);                          \
        thr_r = thr[rl];                                                  \
      }                                                                   \
    }                                                                     \
  } while (0)

// candidates for one row: 8 scalars = (c2,t) pairs, values passed by register.
// rowmax guard: if every candidate in the warp is below threshold, skip all 8
// ballots (exactly equivalent to 8 empty-mask COLLECT_ONEs).
__device__ __noinline__ void collect_row(int rl, int j0, int lane,
                                         float4 va, float4 vb,
                                         float* __restrict__ bv,
                                         int* __restrict__ bi,
                                         float* __restrict__ thr,
                                         int* __restrict__ cnt) {
  float thr_r = thr[rl];
  float m0 = fmaxf(fmaxf(va.x, va.y), fmaxf(va.z, va.w));
  float m1 = fmaxf(fmaxf(vb.x, vb.y), fmaxf(vb.z, vb.w));
  float rmax = fmaxf(m0, m1);
  unsigned any = __ballot_sync(0xffffffffu, rmax >= thr_r);
  if (!any) return;
  COLLECT_ONE(va.x, 0);        // c2=0, t=0
  COLLECT_ONE(va.y, 1);        // c2=0, t=1
  COLLECT_ONE(va.z, 64);       // c2=1, t=0
  COLLECT_ONE(va.w, 65);       // c2=1, t=1
  COLLECT_ONE(vb.x, 128);      // c2=2, t=0
  COLLECT_ONE(vb.y, 129);      // c2=2, t=1
  COLLECT_ONE(vb.z, 192);      // c2=3, t=0
  COLLECT_ONE(vb.w, 193);      // c2=3, t=1
}

__global__ __launch_bounds__(STHREADS) void sim_topk_kernel() {
  extern __shared__ float sm[];
  float* colsT = sm;                              // [128][CPAD]
  float* rows  = sm + 128 * CPAD;                 // [SROWS][128]
  float* bufv  = rows + SROWS * Cc;               // [SROWS][CAP]
  int*   bufi  = (int*)(bufv + SROWS * CAP);      // [SROWS][CAP]
  float* thr   = (float*)(bufi + SROWS * CAP);    // [SROWS]
  int*   cnt   = (int*)(thr + SROWS);             // [SROWS]

  int r0 = blockIdx.x * SROWS;
  int tid = threadIdx.x;
  int warp = tid >> 5, lane = tid & 31;
  int rlbase = warp * RPW;

  for (int i = tid; i < SROWS * Cc; i += STHREADS) {
    int row = r0 + (i >> 7);
    rows[i] = (row < Nn) ? g_en[row * Cc + (i & 127)] : 0.f;
  }
  if (tid < SROWS) { thr[tid] = -3.3e38f; cnt[tid] = 0; }
  __syncthreads();

  int rlocal = lane >> 3;   // 0..3 (row within 4-row group of fill)
  int kc = lane & 7;        // 0..7 (16B k-chunk within quarter)

  for (int j0 = 0; j0 < Nn; j0 += SCOLS) {
    // ---- fill colsT[k][j] (transposed, coalesced float4 loads) ----
#pragma unroll 4
    for (int it = 0; it < 16; it++) {
      int u = it * 16 + warp;
      int rowgrp = u >> 2, kq = u & 3;
      int j = rowgrp * 4 + rlocal;    // 0..255
      int k4 = kq * 8 + kc;           // 0..31
      int col = j0 + j;
      float4 val = make_float4(0.f, 0.f, 0.f, 0.f);
      if (col < Nn) val = ((const float4*)g_en)[col * (Cc / 4) + k4];
      colsT[(k4 * 4 + 0) * CPAD + j] = val.x;
      colsT[(k4 * 4 + 1) * CPAD + j] = val.y;
      colsT[(k4 * 4 + 2) * CPAD + j] = val.z;
      colsT[(k4 * 4 + 3) * CPAD + j] = val.w;
    }
    __syncthreads();

    // ---- packed f32x2 GEMM: RPW rows x 8 cols (4 pairs) per lane ----
    unsigned long long acc[RPW][4];
#pragma unroll
    for (int r = 0; r < RPW; r++)
#pragma unroll
      for (int c2 = 0; c2 < 4; c2++) acc[r][c2] = 0ULL;

    const float* rowp = rows + rlbase * Cc;
#pragma unroll 4
    for (int k = 0; k < Cc; k++) {
      unsigned long long cv[4];
      const float* cb = colsT + k * CPAD + lane * 2;
#pragma unroll
      for (int c2 = 0; c2 < 4; c2++)
        cv[c2] = *(const unsigned long long*)(cb + c2 * 64);
#pragma unroll
      for (int r = 0; r < RPW; r++) {
        float rv = rowp[r * Cc + k];
        unsigned long long rv2;
        asm("mov.b64 %0, {%1, %1};" : "=l"(rv2) : "f"(rv));
#pragma unroll
        for (int c2 = 0; c2 < 4; c2++)
          asm("fma.rn.f32x2 %0, %1, %2, %0;"
              : "+l"(acc[r][c2]) : "l"(rv2), "l"(cv[c2]));
      }
    }

    // ---- threshold-buffer candidate collection (acc constant-indexed) ----
#pragma unroll
    for (int r = 0; r < RPW; r++) {
      int rl = rlbase + r;
      float4 va, vb;
      asm("mov.b64 {%0, %1}, %2;" : "=f"(va.x), "=f"(va.y) : "l"(acc[r][0]));
      asm("mov.b64 {%0, %1}, %2;" : "=f"(va.z), "=f"(va.w) : "l"(acc[r][1]));
      asm("mov.b64 {%0, %1}, %2;" : "=f"(vb.x), "=f"(vb.y) : "l"(acc[r][2]));
      asm("mov.b64 {%0, %1}, %2;" : "=f"(vb.z), "=f"(vb.w) : "l"(acc[r][3]));
      collect_row(rl, j0, lane, va, vb,
                  bufv + rl * CAP, bufi + rl * CAP, thr, cnt);
    }
    __syncthreads();
  }

  // ---- final exact selection + output ----
#pragma unroll 1
  for (int r = 0; r < RPW; r++) {
    int rl = rlbase + r;
    int grow = r0 + rl;
    if (grow >= Nn) continue;
    refresh_row(bufv + rl * CAP, bufi + rl * CAP, thr, cnt, rl, lane);
    if (lane < KT) {
      g_tval[grow * KT + lane] = bufv[rl * CAP + lane];
      g_tidx[grow * KT + lane] = bufi[rl * CAP + lane];
    }
  }
}

// ------------------------- 7) p_sim + final combine (deterministic) --------
__global__ __launch_bounds__(64) void psim_final_kernel(
    const int* __restrict__ y, float* __restrict__ out_final) {
  int n = blockIdx.x;
  int t = threadIdx.x;
  __shared__ float ex[KT];
  __shared__ int cls[KT];
  __shared__ float acc[NCc];
  __shared__ float red[2];
  if (t < KT) {
    ex[t] = expf(g_tval[n * KT + t]);
    cls[t] = y[g_tidx[n * KT + t]];
  }
  __syncthreads();
  if (t < NCc) {
    float s = 0.f;
    for (int j = 0; j < KT; j++)
      if (cls[j] == t) s += ex[j];
    acc[t] = s;
  }
  __syncthreads();
  if (t == 0) {
    float mx = acc[0];
    for (int i = 1; i < NCc; i++) mx = fmaxf(mx, acc[i]);
    float s = 0.f;
    for (int i = 0; i < NCc; i++) s += expf(acc[i] - mx);
    red[0] = mx;
    red[1] = logf(s);
  }
  __syncthreads();
  if (t < NCc)
    out_final[n * NCc + t] =
        0.5f * g_plc[n * NCc + t] + 0.5f * (acc[t] - red[0] - red[1]);
}

// ------------------------- host launch --------------------------------------
extern "C" void kernel_launch(void* const* d_in, const int* in_sizes, int n_in,
                              void* d_out, int out_size) {
  (void)in_sizes; (void)n_in; (void)out_size;
  const float* x  = (const float*)d_in[0];
  const float* W1 = (const float*)d_in[1];
  const float* b1 = (const float*)d_in[2];
  const float* Wq = (const float*)d_in[3];
  const float* bq = (const float*)d_in[4];
  const float* Wk = (const float*)d_in[5];
  const float* bk = (const float*)d_in[6];
  const float* Wv = (const float*)d_in[7];
  const float* bv = (const float*)d_in[8];
  const float* W2 = (const float*)d_in[9];
  const float* b2 = (const float*)d_in[10];
  const int* ei   = (const int*)d_in[11];
  const int* y    = (const int*)d_in[12];
  const int* rowi = ei;
  const int* coli = ei + Ee;
  float* out_final = (float*)d_out;
  float* out_emb   = (float*)d_out + (size_t)Nn * NCc;

  void* cntp = 0; cudaGetSymbolAddress(&cntp, g_cnt);
  void* curp = 0; cudaGetSymbolAddress(&curp, g_cur);
  cudaFuncSetAttribute(sim_topk_kernel,
                       cudaFuncAttributeMaxDynamicSharedMemorySize, SIM_SMEM);

  // Launch slots (ncu captures slot 6 via -s 5 -c 1, memsets included).
  // Slot 6 = attn_gather<4> diagnostic on nodes [0,2000): reads CSR (built) +
  // q/k/v/norm junk; writes only g_xall level-4 rows 0..1999, overwritten by
  // the real layer-4 attention before any consumer reads level 4.
  cudaMemsetAsync(cntp, 0, Nn * sizeof(int), 0);                 // 1
  cudaMemsetAsync(curp, 0, Nn * sizeof(int), 0);                 // 2
  count_kernel<<<(ETOT + 255) / 256, 256>>>(coli);               // 3
  scan_kernel<<<1, 1024>>>();                                    // 4
  place_kernel<<<(ETOT + 255) / 256, 256>>>(coli);               // 5
  attn_gather_kernel<4><<<2000, 128>>>(rowi, 3);                 // 6 <- ncu
  gemm1_relu_kernel<<<(Nn + 63) / 64, 256>>>(x, W1, b1);
  dinv_kernel<<<(Nn + 255) / 256, 256>>>();
  norm_kernel<<<(ETOT + 255) / 256, 256>>>(rowi, coli);
  sort_bucket_kernel<<<(Nn + 127) / 128, 128>>>();

  for (int l = 0; l < NLAY; l++) {
    qkv_kernel<<<Nn, 128>>>(Wq, bq, Wk, bk, Wv, bv, l);
    switch (l) {
      case 0: attn_gather_kernel<1><<<Nn, 128>>>(rowi, l); break;
      case 1: attn_gather_kernel<2><<<Nn, 128>>>(rowi, l); break;
      case 2: attn_gather_kernel<3><<<Nn, 128>>>(rowi, l); break;
      default: attn_gather_kernel<4><<<Nn, 128>>>(rowi, l); break;
    }
  }

  emb_norm_kernel<<<Nn, 128>>>(out_emb);
  plc_kernel<<<Nn, 128>>>(W2, b2);
  sim_topk_kernel<<<SGRID, STHREADS, SIM_SMEM>>>();
  psim_final_kernel<<<Nn, 64>>>(y, out_final);
}

// round 14
// speedup vs baseline: 2.2380x; 1.0205x over previous
#include <cuda_runtime.h>
#include <math.h>

#define Nn 10000
#define Ee 160000
#define ETOT (Ee + Nn)
#define IND 512
#define Cc 128
#define NCc 40
#define NLAY 4
#define HE 8
#define GR 16
#define KT 16
#define DKk 16

// ------------------------- scratch (device globals; no allocations) ---------
__device__ float g_xall[Nn * 5 * Cc];   // x_all levels 0..4
__device__ float g_q[Nn * Cc];
__device__ float g_k[Nn * 4 * Cc];      // levels 0..3
__device__ float g_v[Nn * 4 * Cc];
__device__ int   g_cnt[Nn];             // in-degree incl self loop
__device__ float g_dinv[Nn];
__device__ float g_norm[ETOT];
__device__ int   g_off[Nn + 1];
__device__ int   g_cur[Nn];
__device__ int   g_eid[ETOT];
__device__ float g_en[Nn * Cc];
__device__ float g_plc[Nn * NCc];
__device__ float g_tval[Nn * KT];
__device__ int   g_tidx[Nn * KT];

// ------------------------- 1) h0 = relu(x @ W1 + b1) ------------------------
__global__ __launch_bounds__(256) void gemm1_relu_kernel(
    const float* __restrict__ x, const float* __restrict__ W1,
    const float* __restrict__ b1) {
  __shared__ float xs[32][65];    // xs[k][m], 64 rows
  __shared__ float ws[32][128];
  int m0 = blockIdx.x * 64;
  int tid = threadIdx.x;
  int tc = tid & 15;   // 16 col-groups of 8
  int tr = tid >> 4;   // 16 row-groups of 4
  float acc[4][8];
#pragma unroll
  for (int r = 0; r < 4; r++)
#pragma unroll
    for (int c = 0; c < 8; c++) acc[r][c] = 0.f;

  for (int k0 = 0; k0 < IND; k0 += 32) {
    for (int i = tid; i < 64 * 32; i += 256) {
      int m = i >> 5, k = i & 31;
      int row = m0 + m;
      xs[k][m] = (row < Nn) ? x[row * IND + k0 + k] : 0.f;
    }
    for (int i = tid; i < 32 * 128; i += 256) {
      int k = i >> 7, c = i & 127;
      ws[k][c] = W1[(k0 + k) * Cc + c];
    }
    __syncthreads();
#pragma unroll
    for (int k = 0; k < 32; k++) {
      float xv[4], wv[8];
#pragma unroll
      for (int r = 0; r < 4; r++) xv[r] = xs[k][tr * 4 + r];
#pragma unroll
      for (int c = 0; c < 8; c++) wv[c] = ws[k][tc * 8 + c];
#pragma unroll
      for (int r = 0; r < 4; r++)
#pragma unroll
        for (int c = 0; c < 8; c++) acc[r][c] = fmaf(xv[r], wv[c], acc[r][c]);
    }
    __syncthreads();
  }
#pragma unroll
  for (int r = 0; r < 4; r++) {
    int row = m0 + tr * 4 + r;
    if (row < Nn) {
#pragma unroll
      for (int c = 0; c < 8; c++) {
        int col = tc * 8 + c;
        float v = acc[r][c] + b1[col];
        g_xall[row * 5 * Cc + col] = v > 0.f ? v : 0.f;   // level 0
      }
    }
  }
}

// ------------------------- 2) gcn_norm + CSR build (deterministic) ----------
__global__ void count_kernel(const int* __restrict__ coli) {
  int e = blockIdx.x * blockDim.x + threadIdx.x;
  if (e >= ETOT) return;
  int c = (e < Ee) ? coli[e] : (e - Ee);
  atomicAdd(&g_cnt[c], 1);
}

__global__ void dinv_kernel() {
  int n = blockIdx.x * blockDim.x + threadIdx.x;
  if (n < Nn) g_dinv[n] = 1.0f / sqrtf((float)g_cnt[n]);
}

__global__ void norm_kernel(const int* __restrict__ rowi,
                            const int* __restrict__ coli) {
  int e = blockIdx.x * blockDim.x + threadIdx.x;
  if (e >= ETOT) return;
  if (e < Ee) g_norm[e] = g_dinv[rowi[e]] * g_dinv[coli[e]];
  else { float d = g_dinv[e - Ee]; g_norm[e] = d * d; }
}

// single-block exclusive scan of g_cnt -> g_off (1024 threads, 10 elems each)
__global__ __launch_bounds__(1024) void scan_kernel() {
  __shared__ int ssum[1024];
  int t = threadIdx.x;
  int base = t * 10;
  int loc[10];
  int s = 0;
#pragma unroll
  for (int i = 0; i < 10; i++) {
    int idx = base + i;
    int v = (idx < Nn) ? g_cnt[idx] : 0;
    loc[i] = s;
    s += v;
  }
  ssum[t] = s;
  __syncthreads();
  for (int off = 1; off < 1024; off <<= 1) {
    int v = (t >= off) ? ssum[t - off] : 0;
    __syncthreads();
    ssum[t] += v;
    __syncthreads();
  }
  int pre = (t > 0) ? ssum[t - 1] : 0;
#pragma unroll
  for (int i = 0; i < 10; i++) {
    int idx = base + i;
    if (idx < Nn) g_off[idx] = pre + loc[i];
  }
  if (t == 1023) g_off[Nn] = ssum[1023];
}

__global__ void place_kernel(const int* __restrict__ coli) {
  int e = blockIdx.x * blockDim.x + threadIdx.x;
  if (e >= ETOT) return;
  int c = (e < Ee) ? coli[e] : (e - Ee);
  int pos = atomicAdd(&g_cur[c], 1);
  g_eid[g_off[c] + pos] = e;
}

// canonicalize bucket order: insertion-sort each bucket ascending by edge id.
// Buckets <= 64 staged in shared memory (column-major: conflict-free, ~35 cyc
// per op vs ~234 in L2); rare larger buckets fall back to the global path.
// Output identical to the global-memory sort (same sorted order).
#define SB(i) sbuf[(i) * 128 + tid]
__global__ __launch_bounds__(128) void sort_bucket_kernel() {
  __shared__ int sbuf[64 * 128];
  int tid = threadIdx.x;
  int n = blockIdx.x * 128 + tid;
  if (n >= Nn) return;
  int s = g_off[n], e2 = g_off[n + 1];
  int len = e2 - s;
  if (len <= 64) {
    for (int i = 0; i < len; i++) SB(i) = g_eid[s + i];
    for (int i = 1; i < len; i++) {
      int key = SB(i);
      int j = i - 1;
      while (j >= 0) {
        int v = SB(j);
        if (v <= key) break;
        SB(j + 1) = v;
        j--;
      }
      SB(j + 1) = key;
    }
    for (int i = 0; i < len; i++) g_eid[s + i] = SB(i);
  } else {
    for (int i = s + 1; i < e2; i++) {
      int key = g_eid[i];
      int j = i - 1;
      while (j >= s && g_eid[j] > key) { g_eid[j + 1] = g_eid[j]; j--; }
      g_eid[j + 1] = key;
    }
  }
}

// ------------------------- 3a) grouped q/k/v per layer ---------------------
__global__ __launch_bounds__(128) void qkv_kernel(
    const float* __restrict__ Wq, const float* __restrict__ bq,
    const float* __restrict__ Wk, const float* __restrict__ bk,
    const float* __restrict__ Wv, const float* __restrict__ bv, int l) {
  int n = blockIdx.x;
  int c = threadIdx.x;
  int g = c >> 3, o = c & 7;
  __shared__ float xs[Cc];
  float wq[8], wk[8], wv[8];
  int base = ((l * GR + g) * 8) * 8 + o;
#pragma unroll
  for (int i = 0; i < 8; i++) {
    wq[i] = Wq[base + i * 8];
    wk[i] = Wk[base + i * 8];
    wv[i] = Wv[base + i * 8];
  }
  float bqv = bq[l * Cc + c], bkv = bk[l * Cc + c], bvv = bv[l * Cc + c];
  for (int lev = 0; lev <= l; lev++) {
    __syncthreads();
    xs[c] = g_xall[(n * 5 + lev) * Cc + c];
    __syncthreads();
    float xg[8];
#pragma unroll
    for (int i = 0; i < 8; i++) xg[i] = xs[g * 8 + i];
    float sk = bkv, sv = bvv;
#pragma unroll
    for (int i = 0; i < 8; i++) {
      sk = fmaf(xg[i], wk[i], sk);
      sv = fmaf(xg[i], wv[i], sv);
    }
    g_k[(n * 4 + lev) * Cc + c] = sk;
    g_v[(n * 4 + lev) * Cc + c] = sv;
    if (lev == l) {
      float sq = bqv;
#pragma unroll
      for (int i = 0; i < 8; i++) sq = fmaf(xg[i], wq[i], sq);
      g_q[n * Cc + c] = sq;
    }
  }
}

// ------------------------- 3b) deterministic attention gather --------------
// ILP-2 edge unroll; accumulation in strict edge order (bit-identical).
template <int NLEV>
__device__ __forceinline__ float edge_weight(int r, int e, float qv, int tid,
                                             float* __restrict__ sc) {
  const unsigned FULL = 0xffffffffu;
  float nrm = g_norm[e];
  float mx = -1e30f;
#pragma unroll
  for (int lev = 0; lev < NLEV; lev++) {
    float t = qv * g_k[(r * 4 + lev) * Cc + tid];
    t += __shfl_xor_sync(FULL, t, 8);
    t += __shfl_xor_sync(FULL, t, 4);
    t += __shfl_xor_sync(FULL, t, 2);
    t += __shfl_xor_sync(FULL, t, 1);
    t *= 0.25f;   // 1/sqrt(DK)
    sc[lev] = t;
    mx = fmaxf(mx, t);
  }
  float den = 0.f;
#pragma unroll
  for (int lev = 0; lev < NLEV; lev++) {
    sc[lev] = expf(sc[lev] - mx);
    den += sc[lev];
  }
  return nrm / den;
}

template <int NLEV>
__global__ __launch_bounds__(128) void attn_gather_kernel(
    const int* __restrict__ rowi, int l) {
  int c = blockIdx.x;
  int tid = threadIdx.x;
  float qv = g_q[c * Cc + tid];
  int s = g_off[c], e2 = g_off[c + 1];
  float acc = 0.f;
  int p = s;
  for (; p + 1 < e2; p += 2) {
    int ea = g_eid[p];
    int eb = g_eid[p + 1];
    int ra = (ea < Ee) ? rowi[ea] : (ea - Ee);
    int rb = (eb < Ee) ? rowi[eb] : (eb - Ee);
    float va[NLEV], vb[NLEV];
#pragma unroll
    for (int lev = 0; lev < NLEV; lev++) {
      va[lev] = g_v[(ra * 4 + lev) * Cc + tid];
      vb[lev] = g_v[(rb * 4 + lev) * Cc + tid];
    }
    float sca[NLEV], scb[NLEV];
    float wa = edge_weight<NLEV>(ra, ea, qv, tid, sca);
    float wb = edge_weight<NLEV>(rb, eb, qv, tid, scb);
#pragma unroll
    for (int lev = 0; lev < NLEV; lev++)
      acc = fmaf(sca[lev] * wa, va[lev], acc);
#pragma unroll
    for (int lev = 0; lev < NLEV; lev++)
      acc = fmaf(scb[lev] * wb, vb[lev], acc);
  }
  if (p < e2) {
    int e = g_eid[p];
    int r = (e < Ee) ? rowi[e] : (e - Ee);
    float vv[NLEV];
#pragma unroll
    for (int lev = 0; lev < NLEV; lev++)
      vv[lev] = g_v[(r * 4 + lev) * Cc + tid];
    float sc[NLEV];
    float w = edge_weight<NLEV>(r, e, qv, tid, sc);
#pragma unroll
    for (int lev = 0; lev < NLEV; lev++)
      acc = fmaf(sc[lev] * w, vv[lev], acc);
  }
  g_xall[(c * 5 + l + 1) * Cc + tid] = acc > 0.f ? acc : 0.f;
}

// ------------------------- 4) emb out + L2 normalize -----------------------
__global__ __launch_bounds__(128) void emb_norm_kernel(float* __restrict__ out_emb) {
  int n = blockIdx.x;
  int c = threadIdx.x;
  float v = g_xall[(n * 5 + 4) * Cc + c];
  out_emb[n * Cc + c] = v;
  float ss = v * v;
#pragma unroll
  for (int off = 16; off; off >>= 1) ss += __shfl_down_sync(0xffffffffu, ss, off);
  __shared__ float ws[4];
  if ((c & 31) == 0) ws[c >> 5] = ss;
  __syncthreads();
  float tot = ws[0] + ws[1] + ws[2] + ws[3];
  float nrm = fmaxf(sqrtf(tot), 1e-8f);
  g_en[n * Cc + c] = v / nrm;
}

// ------------------------- 5) p_lc = log_softmax(emb@W2+b2) ----------------
__global__ __launch_bounds__(128) void plc_kernel(const float* __restrict__ W2,
                                                  const float* __restrict__ b2) {
  int n = blockIdx.x;
  int t = threadIdx.x;
  __shared__ float xr[Cc];
  __shared__ float lg[NCc];
  __shared__ float red[2];
  xr[t] = g_xall[(n * 5 + 4) * Cc + t];
  __syncthreads();
  if (t < NCc) {
    float s = b2[t];
    for (int k = 0; k < Cc; k++) s = fmaf(xr[k], W2[k * NCc + t], s);
    lg[t] = s;
  }
  __syncthreads();
  if (t == 0) {
    float mx = lg[0];
    for (int i = 1; i < NCc; i++) mx = fmaxf(mx, lg[i]);
    float s = 0.f;
    for (int i = 0; i < NCc; i++) s += expf(lg[i] - mx);
    red[0] = mx;
    red[1] = logf(s);
  }
  __syncthreads();
  if (t < NCc) g_plc[n * NCc + t] = lg[t] - red[0] - red[1];
}

// ------------------------- 6) fused sim = en@en^T + top-16 -----------------
// v7 (current best): 512 thr, SROWS=80, grid=125 single wave, ascending tiles,
// rowmax-guard collect. Exact + deterministic.
#define SROWS 80     // rows per block (16 warps x 5 rows)
#define RPW 5
#define SGRID 125    // 125 * 80 = 10000 exactly; single wave on 148 SMs
#define STHREADS 512
#define SCOLS 256
#define CPAD 258
#define CAP 80
#define SIM_SMEM ((128 * CPAD + SROWS * Cc + SROWS * CAP) * 4 + SROWS * CAP * 4 + SROWS * 8)

// exact tie-aware top-16 selection of buf[0..n) into buf[0..15]; updates thr/cnt
__device__ __noinline__ void refresh_row(float* __restrict__ v,
                                         int* __restrict__ ix,
                                         float* __restrict__ thr,
                                         int* __restrict__ cnt,
                                         int rl, int lane) {
  const unsigned FULL = 0xffffffffu;
  int n = cnt[rl];
#pragma unroll 1
  for (int pick = 0; pick < KT; pick++) {
    float mv = -3.4e38f; int mi = 0x7fffffff; int mp = pick;
    for (int s = pick + lane; s < n; s += 32) {
      float vv = v[s]; int ii = ix[s];
      if (vv > mv || (vv == mv && ii < mi)) { mv = vv; mi = ii; mp = s; }
    }
#pragma unroll
    for (int off = 16; off; off >>= 1) {
      float ov = __shfl_down_sync(FULL, mv, off);
      int oi = __shfl_down_sync(FULL, mi, off);
      int op = __shfl_down_sync(FULL, mp, off);
      if (ov > mv || (ov == mv && oi < mi)) { mv = ov; mi = oi; mp = op; }
    }
    mp = __shfl_sync(FULL, mp, 0);
    mv = __shfl_sync(FULL, mv, 0);
    mi = __shfl_sync(FULL, mi, 0);
    if (lane == 0 && mp != pick) {
      float tv = v[pick]; int ti = ix[pick];
      v[pick] = mv; ix[pick] = mi;
      v[mp] = tv; ix[mp] = ti;
    }
    __syncwarp();
  }
  if (lane == 0) { thr[rl] = v[KT - 1]; cnt[rl] = KT; }
  __syncwarp();
}

// one ballot-insert step for a single scalar candidate
#define COLLECT_ONE(val, colofs)                                          \
  do {                                                                    \
    float v_ = (val);                                                     \
    int colx_ = j0 + (colofs) + lane * 2;                                 \
    bool p_ = (colx_ < Nn) && (v_ >= thr_r);                              \
    unsigned mask_ = __ballot_sync(0xffffffffu, p_);                      \
    if (mask_) {                                                          \
      int base_ = cnt[rl];                                                \
      if (p_) {                                                           \
        int pos_ = base_ + __popc(mask_ & ((1u << lane) - 1u));           \
        bv[pos_] = v_;                                                    \
        bi[pos_] = colx_;                                                 \
      }                                                                   \
      int nb_ = base_ + __popc(mask_);                                    \
      if (lane == 0) cnt[rl] = nb_;                                       \
      __syncwarp();                                                       \
      if (nb_ >= CAP - 32) {                                              \
        refresh_row(bv, bi, thr, cnt, rl, lane);                          \
        thr_r = thr[rl];                                                  \
      }                                                                   \
    }                                                                     \
  } while (0)

// candidates for one row: 8 scalars = (c2,t) pairs, values passed by register.
// rowmax guard: skip all 8 ballots when every candidate is below threshold
// (exactly equivalent to 8 empty-mask COLLECT_ONEs).
__device__ __noinline__ void collect_row(int rl, int j0, int lane,
                                         float4 va, float4 vb,
                                         float* __restrict__ bv,
                                         int* __restrict__ bi,
                                         float* __restrict__ thr,
                                         int* __restrict__ cnt) {
  float thr_r = thr[rl];
  float m0 = fmaxf(fmaxf(va.x, va.y), fmaxf(va.z, va.w));
  float m1 = fmaxf(fmaxf(vb.x, vb.y), fmaxf(vb.z, vb.w));
  float rmax = fmaxf(m0, m1);
  unsigned any = __ballot_sync(0xffffffffu, rmax >= thr_r);
  if (!any) return;
  COLLECT_ONE(va.x, 0);        // c2=0, t=0
  COLLECT_ONE(va.y, 1);        // c2=0, t=1
  COLLECT_ONE(va.z, 64);       // c2=1, t=0
  COLLECT_ONE(va.w, 65);       // c2=1, t=1
  COLLECT_ONE(vb.x, 128);      // c2=2, t=0
  COLLECT_ONE(vb.y, 129);      // c2=2, t=1
  COLLECT_ONE(vb.z, 192);      // c2=3, t=0
  COLLECT_ONE(vb.w, 193);      // c2=3, t=1
}

__global__ __launch_bounds__(STHREADS) void sim_topk_kernel() {
  extern __shared__ float sm[];
  float* colsT = sm;                              // [128][CPAD]
  float* rows  = sm + 128 * CPAD;                 // [SROWS][128]
  float* bufv  = rows + SROWS * Cc;               // [SROWS][CAP]
  int*   bufi  = (int*)(bufv + SROWS * CAP);      // [SROWS][CAP]
  float* thr   = (float*)(bufi + SROWS * CAP);    // [SROWS]
  int*   cnt   = (int*)(thr + SROWS);             // [SROWS]

  int r0 = blockIdx.x * SROWS;
  int tid = threadIdx.x;
  int warp = tid >> 5, lane = tid & 31;
  int rlbase = warp * RPW;

  for (int i = tid; i < SROWS * Cc; i += STHREADS) {
    int row = r0 + (i >> 7);
    rows[i] = (row < Nn) ? g_en[row * Cc + (i & 127)] : 0.f;
  }
  if (tid < SROWS) { thr[tid] = -3.3e38f; cnt[tid] = 0; }
  __syncthreads();

  int rlocal = lane >> 3;   // 0..3 (row within 4-row group of fill)
  int kc = lane & 7;        // 0..7 (16B k-chunk within quarter)

  for (int j0 = 0; j0 < Nn; j0 += SCOLS) {
    // ---- fill colsT[k][j] (transposed, coalesced float4 loads) ----
#pragma unroll 4
    for (int it = 0; it < 16; it++) {
      int u = it * 16 + warp;
      int rowgrp = u >> 2, kq = u & 3;
      int j = rowgrp * 4 + rlocal;    // 0..255
      int k4 = kq * 8 + kc;           // 0..31
      int col = j0 + j;
      float4 val = make_float4(0.f, 0.f, 0.f, 0.f);
      if (col < Nn) val = ((const float4*)g_en)[col * (Cc / 4) + k4];
      colsT[(k4 * 4 + 0) * CPAD + j] = val.x;
      colsT[(k4 * 4 + 1) * CPAD + j] = val.y;
      colsT[(k4 * 4 + 2) * CPAD + j] = val.z;
      colsT[(k4 * 4 + 3) * CPAD + j] = val.w;
    }
    __syncthreads();

    // ---- packed f32x2 GEMM: RPW rows x 8 cols (4 pairs) per lane ----
    unsigned long long acc[RPW][4];
#pragma unroll
    for (int r = 0; r < RPW; r++)
#pragma unroll
      for (int c2 = 0; c2 < 4; c2++) acc[r][c2] = 0ULL;

    const float* rowp = rows + rlbase * Cc;
#pragma unroll 4
    for (int k = 0; k < Cc; k++) {
      unsigned long long cv[4];
      const float* cb = colsT + k * CPAD + lane * 2;
#pragma unroll
      for (int c2 = 0; c2 < 4; c2++)
        cv[c2] = *(const unsigned long long*)(cb + c2 * 64);
#pragma unroll
      for (int r = 0; r < RPW; r++) {
        float rv = rowp[r * Cc + k];
        unsigned long long rv2;
        asm("mov.b64 %0, {%1, %1};" : "=l"(rv2) : "f"(rv));
#pragma unroll
        for (int c2 = 0; c2 < 4; c2++)
          asm("fma.rn.f32x2 %0, %1, %2, %0;"
              : "+l"(acc[r][c2]) : "l"(rv2), "l"(cv[c2]));
      }
    }

    // ---- threshold-buffer candidate collection (acc constant-indexed) ----
#pragma unroll
    for (int r = 0; r < RPW; r++) {
      int rl = rlbase + r;
      float4 va, vb;
      asm("mov.b64 {%0, %1}, %2;" : "=f"(va.x), "=f"(va.y) : "l"(acc[r][0]));
      asm("mov.b64 {%0, %1}, %2;" : "=f"(va.z), "=f"(va.w) : "l"(acc[r][1]));
      asm("mov.b64 {%0, %1}, %2;" : "=f"(vb.x), "=f"(vb.y) : "l"(acc[r][2]));
      asm("mov.b64 {%0, %1}, %2;" : "=f"(vb.z), "=f"(vb.w) : "l"(acc[r][3]));
      collect_row(rl, j0, lane, va, vb,
                  bufv + rl * CAP, bufi + rl * CAP, thr, cnt);
    }
    __syncthreads();
  }

  // ---- final exact selection + output ----
#pragma unroll 1
  for (int r = 0; r < RPW; r++) {
    int rl = rlbase + r;
    int grow = r0 + rl;
    if (grow >= Nn) continue;
    refresh_row(bufv + rl * CAP, bufi + rl * CAP, thr, cnt, rl, lane);
    if (lane < KT) {
      g_tval[grow * KT + lane] = bufv[rl * CAP + lane];
      g_tidx[grow * KT + lane] = bufi[rl * CAP + lane];
    }
  }
}

// ------------------------- 7) p_sim + final combine (deterministic) --------
__global__ __launch_bounds__(64) void psim_final_kernel(
    const int* __restrict__ y, float* __restrict__ out_final) {
  int n = blockIdx.x;
  int t = threadIdx.x;
  __shared__ float ex[KT];
  __shared__ int cls[KT];
  __shared__ float acc[NCc];
  __shared__ float red[2];
  if (t < KT) {
    ex[t] = expf(g_tval[n * KT + t]);
    cls[t] = y[g_tidx[n * KT + t]];
  }
  __syncthreads();
  if (t < NCc) {
    float s = 0.f;
    for (int j = 0; j < KT; j++)
      if (cls[j] == t) s += ex[j];
    acc[t] = s;
  }
  __syncthreads();
  if (t == 0) {
    float mx = acc[0];
    for (int i = 1; i < NCc; i++) mx = fmaxf(mx, acc[i]);
    float s = 0.f;
    for (int i = 0; i < NCc; i++) s += expf(acc[i] - mx);
    red[0] = mx;
    red[1] = logf(s);
  }
  __syncthreads();
  if (t < NCc)
    out_final[n * NCc + t] =
        0.5f * g_plc[n * NCc + t] + 0.5f * (acc[t] - red[0] - red[1]);
}

// ------------------------- host launch --------------------------------------
extern "C" void kernel_launch(void* const* d_in, const int* in_sizes, int n_in,
                              void* d_out, int out_size) {
  (void)in_sizes; (void)n_in; (void)out_size;
  const float* x  = (const float*)d_in[0];
  const float* W1 = (const float*)d_in[1];
  const float* b1 = (const float*)d_in[2];
  const float* Wq = (const float*)d_in[3];
  const float* bq = (const float*)d_in[4];
  const float* Wk = (const float*)d_in[5];
  const float* bk = (const float*)d_in[6];
  const float* Wv = (const float*)d_in[7];
  const float* bv = (const float*)d_in[8];
  const float* W2 = (const float*)d_in[9];
  const float* b2 = (const float*)d_in[10];
  const int* ei   = (const int*)d_in[11];
  const int* y    = (const int*)d_in[12];
  const int* rowi = ei;
  const int* coli = ei + Ee;
  float* out_final = (float*)d_out;
  float* out_emb   = (float*)d_out + (size_t)Nn * NCc;

  void* cntp = 0; cudaGetSymbolAddress(&cntp, g_cnt);
  void* curp = 0; cudaGetSymbolAddress(&curp, g_cur);
  cudaFuncSetAttribute(sim_topk_kernel,
                       cudaFuncAttributeMaxDynamicSharedMemorySize, SIM_SMEM);

  cudaMemsetAsync(cntp, 0, Nn * sizeof(int), 0);
  cudaMemsetAsync(curp, 0, Nn * sizeof(int), 0);
  gemm1_relu_kernel<<<(Nn + 63) / 64, 256>>>(x, W1, b1);
  count_kernel<<<(ETOT + 255) / 256, 256>>>(coli);
  dinv_kernel<<<(Nn + 255) / 256, 256>>>();
  norm_kernel<<<(ETOT + 255) / 256, 256>>>(rowi, coli);
  scan_kernel<<<1, 1024>>>();
  place_kernel<<<(ETOT + 255) / 256, 256>>>(coli);
  sort_bucket_kernel<<<(Nn + 127) / 128, 128>>>();

  for (int l = 0; l < NLAY; l++) {
    qkv_kernel<<<Nn, 128>>>(Wq, bq, Wk, bk, Wv, bv, l);
    switch (l) {
      case 0: attn_gather_kernel<1><<<Nn, 128>>>(rowi, l); break;
      case 1: attn_gather_kernel<2><<<Nn, 128>>>(rowi, l); break;
      case 2: attn_gather_kernel<3><<<Nn, 128>>>(rowi, l); break;
      default: attn_gather_kernel<4><<<Nn, 128>>>(rowi, l); break;
    }
  }

  emb_norm_kernel<<<Nn, 128>>>(out_emb);
  plc_kernel<<<Nn, 128>>>(W2, b2);
  sim_topk_kernel<<<SGRID, STHREADS, SIM_SMEM>>>();
  psim_final_kernel<<<Nn, 64>>>(y, out_final);
}

// round 15
// speedup vs baseline: 2.4219x; 1.0822x over previous
#include <cuda_runtime.h>
#include <math.h>

#define Nn 10000
#define Ee 160000
#define ETOT (Ee + Nn)
#define IND 512
#define Cc 128
#define NCc 40
#define NLAY 4
#define HE 8
#define GR 16
#define KT 16
#define DKk 16

// ------------------------- scratch (device globals; no allocations) ---------
__device__ float g_xall[Nn * 5 * Cc];   // x_all levels 0..4
__device__ float g_q[Nn * Cc];          // PERMUTED head layout (see qkv)
__device__ float g_k[Nn * 4 * Cc];      // PERMUTED, levels 0..3
__device__ float g_v[Nn * 4 * Cc];      // PERMUTED
__device__ int   g_cnt[Nn];             // in-degree incl self loop
__device__ float g_dinv[Nn];
__device__ float g_norm[ETOT];
__device__ int   g_off[Nn + 1];
__device__ int   g_cur[Nn];
__device__ int   g_eid[ETOT];
__device__ float g_en[Nn * Cc];
__device__ float g_plc[Nn * NCc];
__device__ float g_tval[Nn * KT];
__device__ int   g_tidx[Nn * KT];

// ------------------------- 1) h0 = relu(x @ W1 + b1) ------------------------
__global__ __launch_bounds__(256) void gemm1_relu_kernel(
    const float* __restrict__ x, const float* __restrict__ W1,
    const float* __restrict__ b1) {
  __shared__ float xs[32][65];    // xs[k][m], 64 rows
  __shared__ float ws[32][128];
  int m0 = blockIdx.x * 64;
  int tid = threadIdx.x;
  int tc = tid & 15;   // 16 col-groups of 8
  int tr = tid >> 4;   // 16 row-groups of 4
  float acc[4][8];
#pragma unroll
  for (int r = 0; r < 4; r++)
#pragma unroll
    for (int c = 0; c < 8; c++) acc[r][c] = 0.f;

  for (int k0 = 0; k0 < IND; k0 += 32) {
    for (int i = tid; i < 64 * 32; i += 256) {
      int m = i >> 5, k = i & 31;
      int row = m0 + m;
      xs[k][m] = (row < Nn) ? x[row * IND + k0 + k] : 0.f;
    }
    for (int i = tid; i < 32 * 128; i += 256) {
      int k = i >> 7, c = i & 127;
      ws[k][c] = W1[(k0 + k) * Cc + c];
    }
    __syncthreads();
#pragma unroll
    for (int k = 0; k < 32; k++) {
      float xv[4], wv[8];
#pragma unroll
      for (int r = 0; r < 4; r++) xv[r] = xs[k][tr * 4 + r];
#pragma unroll
      for (int c = 0; c < 8; c++) wv[c] = ws[k][tc * 8 + c];
#pragma unroll
      for (int r = 0; r < 4; r++)
#pragma unroll
        for (int c = 0; c < 8; c++) acc[r][c] = fmaf(xv[r], wv[c], acc[r][c]);
    }
    __syncthreads();
  }
#pragma unroll
  for (int r = 0; r < 4; r++) {
    int row = m0 + tr * 4 + r;
    if (row < Nn) {
#pragma unroll
      for (int c = 0; c < 8; c++) {
        int col = tc * 8 + c;
        float v = acc[r][c] + b1[col];
        g_xall[row * 5 * Cc + col] = v > 0.f ? v : 0.f;   // level 0
      }
    }
  }
}

// ------------------------- 2) gcn_norm + CSR build (deterministic) ----------
__global__ void count_kernel(const int* __restrict__ coli) {
  int e = blockIdx.x * blockDim.x + threadIdx.x;
  if (e >= ETOT) return;
  int c = (e < Ee) ? coli[e] : (e - Ee);
  atomicAdd(&g_cnt[c], 1);
}

__global__ void dinv_kernel() {
  int n = blockIdx.x * blockDim.x + threadIdx.x;
  if (n < Nn) g_dinv[n] = 1.0f / sqrtf((float)g_cnt[n]);
}

__global__ void norm_kernel(const int* __restrict__ rowi,
                            const int* __restrict__ coli) {
  int e = blockIdx.x * blockDim.x + threadIdx.x;
  if (e >= ETOT) return;
  if (e < Ee) g_norm[e] = g_dinv[rowi[e]] * g_dinv[coli[e]];
  else { float d = g_dinv[e - Ee]; g_norm[e] = d * d; }
}

// single-block exclusive scan of g_cnt -> g_off (1024 threads, 10 elems each)
__global__ __launch_bounds__(1024) void scan_kernel() {
  __shared__ int ssum[1024];
  int t = threadIdx.x;
  int base = t * 10;
  int loc[10];
  int s = 0;
#pragma unroll
  for (int i = 0; i < 10; i++) {
    int idx = base + i;
    int v = (idx < Nn) ? g_cnt[idx] : 0;
    loc[i] = s;
    s += v;
  }
  ssum[t] = s;
  __syncthreads();
  for (int off = 1; off < 1024; off <<= 1) {
    int v = (t >= off) ? ssum[t - off] : 0;
    __syncthreads();
    ssum[t] += v;
    __syncthreads();
  }
  int pre = (t > 0) ? ssum[t - 1] : 0;
#pragma unroll
  for (int i = 0; i < 10; i++) {
    int idx = base + i;
    if (idx < Nn) g_off[idx] = pre + loc[i];
  }
  if (t == 1023) g_off[Nn] = ssum[1023];
}

__global__ void place_kernel(const int* __restrict__ coli) {
  int e = blockIdx.x * blockDim.x + threadIdx.x;
  if (e >= ETOT) return;
  int c = (e < Ee) ? coli[e] : (e - Ee);
  int pos = atomicAdd(&g_cur[c], 1);
  g_eid[g_off[c] + pos] = e;
}

// canonicalize bucket order: insertion-sort each bucket ascending by edge id.
#define SB(i) sbuf[(i) * 128 + tid]
__global__ __launch_bounds__(128) void sort_bucket_kernel() {
  __shared__ int sbuf[64 * 128];
  int tid = threadIdx.x;
  int n = blockIdx.x * 128 + tid;
  if (n >= Nn) return;
  int s = g_off[n], e2 = g_off[n + 1];
  int len = e2 - s;
  if (len <= 64) {
    for (int i = 0; i < len; i++) SB(i) = g_eid[s + i];
    for (int i = 1; i < len; i++) {
      int key = SB(i);
      int j = i - 1;
      while (j >= 0) {
        int v = SB(j);
        if (v <= key) break;
        SB(j + 1) = v;
        j--;
      }
      SB(j + 1) = key;
    }
    for (int i = 0; i < len; i++) g_eid[s + i] = SB(i);
  } else {
    for (int i = s + 1; i < e2; i++) {
      int key = g_eid[i];
      int j = i - 1;
      while (j >= s && g_eid[j] > key) { g_eid[j + 1] = g_eid[j]; j--; }
      g_eid[j + 1] = key;
    }
  }
}

// ------------------------- 3a) grouped q/k/v per layer ---------------------
// Stores q/k/v in PERMUTED head layout: within head h, dim d (= d&3 + 4*(d>>2))
// goes to position h*16 + (d&3)*4 + (d>>2), so attention lanes can LDG.128
// dims {g, g+4, g+8, g+12}. Values and compute order unchanged.
__global__ __launch_bounds__(128) void qkv_kernel(
    const float* __restrict__ Wq, const float* __restrict__ bq,
    const float* __restrict__ Wk, const float* __restrict__ bk,
    const float* __restrict__ Wv, const float* __restrict__ bv, int l) {
  int n = blockIdx.x;
  int c = threadIdx.x;
  int g = c >> 3, o = c & 7;
  __shared__ float xs[Cc];
  float wq[8], wk[8], wv[8];
  int base = ((l * GR + g) * 8) * 8 + o;
#pragma unroll
  for (int i = 0; i < 8; i++) {
    wq[i] = Wq[base + i * 8];
    wk[i] = Wk[base + i * 8];
    wv[i] = Wv[base + i * 8];
  }
  // permuted output index for this thread's channel
  int hh = c >> 4, dd = c & 15;
  int pidx = hh * 16 + (dd & 3) * 4 + (dd >> 2);
  float bqv = bq[l * Cc + c], bkv = bk[l * Cc + c], bvv = bv[l * Cc + c];
  for (int lev = 0; lev <= l; lev++) {
    __syncthreads();
    xs[c] = g_xall[(n * 5 + lev) * Cc + c];
    __syncthreads();
    float xg[8];
#pragma unroll
    for (int i = 0; i < 8; i++) xg[i] = xs[g * 8 + i];
    float sk = bkv, sv = bvv;
#pragma unroll
    for (int i = 0; i < 8; i++) {
      sk = fmaf(xg[i], wk[i], sk);
      sv = fmaf(xg[i], wv[i], sv);
    }
    g_k[(n * 4 + lev) * Cc + pidx] = sk;
    g_v[(n * 4 + lev) * Cc + pidx] = sv;
    if (lev == l) {
      float sq = bqv;
#pragma unroll
      for (int i = 0; i < 8; i++) sq = fmaf(xg[i], wq[i], sq);
      g_q[n * Cc + pidx] = sq;
    }
  }
}

// ------------------------- 3b) deterministic attention gather --------------
// One WARP per node; lane = h*4+g holds dims {g, g+4, g+8, g+12} of head h via
// float4 loads from the permuted q/k/v. The in-lane sum B=(tx+tz)+(ty+tw)
// replicates the original xor8+xor4 butterfly sums exactly (commutative-
// symmetric), then xor2/xor1 shfls complete the identical reduction tree.
// Per-dim fma chains in strict edge/level order -> bit-identical output.
template <int NLEV>
__device__ __forceinline__ float edge_weight_v(int r, int e, float4 q4,
                                               int lane,
                                               float* __restrict__ sc) {
  const unsigned FULL = 0xffffffffu;
  float nrm = g_norm[e];
  float mx = -1e30f;
#pragma unroll
  for (int lev = 0; lev < NLEV; lev++) {
    float4 k4 = ((const float4*)g_k)[(r * 4 + lev) * (Cc / 4) + lane];
    float tx = q4.x * k4.x, ty = q4.y * k4.y;
    float tz = q4.z * k4.z, tw = q4.w * k4.w;
    float B = (tx + tz) + (ty + tw);
    float C = B + __shfl_xor_sync(FULL, B, 2);
    float D = C + __shfl_xor_sync(FULL, C, 1);
    D *= 0.25f;   // 1/sqrt(DK)
    sc[lev] = D;
    mx = fmaxf(mx, D);
  }
  float den = 0.f;
#pragma unroll
  for (int lev = 0; lev < NLEV; lev++) {
    sc[lev] = expf(sc[lev] - mx);
    den += sc[lev];
  }
  return nrm / den;
}

template <int NLEV>
__global__ __launch_bounds__(128) void attn_gather_kernel(
    const int* __restrict__ rowi, int l) {
  int warp = threadIdx.x >> 5, lane = threadIdx.x & 31;
  int c = blockIdx.x * 4 + warp;
  if (c >= Nn) return;
  float4 q4 = ((const float4*)g_q)[c * (Cc / 4) + lane];
  int s = g_off[c], e2 = g_off[c + 1];
  float4 acc = make_float4(0.f, 0.f, 0.f, 0.f);
  int p = s;
  for (; p + 1 < e2; p += 2) {
    int ea = g_eid[p];
    int eb = g_eid[p + 1];
    int ra = (ea < Ee) ? rowi[ea] : (ea - Ee);
    int rb = (eb < Ee) ? rowi[eb] : (eb - Ee);
    float4 va[NLEV], vb[NLEV];
#pragma unroll
    for (int lev = 0; lev < NLEV; lev++) {
      va[lev] = ((const float4*)g_v)[(ra * 4 + lev) * (Cc / 4) + lane];
      vb[lev] = ((const float4*)g_v)[(rb * 4 + lev) * (Cc / 4) + lane];
    }
    float sca[NLEV], scb[NLEV];
    float wa = edge_weight_v<NLEV>(ra, ea, q4, lane, sca);
    float wb = edge_weight_v<NLEV>(rb, eb, q4, lane, scb);
#pragma unroll
    for (int lev = 0; lev < NLEV; lev++) {
      float wl = sca[lev] * wa;
      acc.x = fmaf(wl, va[lev].x, acc.x);
      acc.y = fmaf(wl, va[lev].y, acc.y);
      acc.z = fmaf(wl, va[lev].z, acc.z);
      acc.w = fmaf(wl, va[lev].w, acc.w);
    }
#pragma unroll
    for (int lev = 0; lev < NLEV; lev++) {
      float wl = scb[lev] * wb;
      acc.x = fmaf(wl, vb[lev].x, acc.x);
      acc.y = fmaf(wl, vb[lev].y, acc.y);
      acc.z = fmaf(wl, vb[lev].z, acc.z);
      acc.w = fmaf(wl, vb[lev].w, acc.w);
    }
  }
  if (p < e2) {
    int e = g_eid[p];
    int r = (e < Ee) ? rowi[e] : (e - Ee);
    float4 vv[NLEV];
#pragma unroll
    for (int lev = 0; lev < NLEV; lev++)
      vv[lev] = ((const float4*)g_v)[(r * 4 + lev) * (Cc / 4) + lane];
    float sc[NLEV];
    float w = edge_weight_v<NLEV>(r, e, q4, lane, sc);
#pragma unroll
    for (int lev = 0; lev < NLEV; lev++) {
      float wl = sc[lev] * w;
      acc.x = fmaf(wl, vv[lev].x, acc.x);
      acc.y = fmaf(wl, vv[lev].y, acc.y);
      acc.z = fmaf(wl, vv[lev].z, acc.z);
      acc.w = fmaf(wl, vv[lev].w, acc.w);
    }
  }
  // un-permute on store: component j holds dim g+4j of head h
  int h = lane >> 2, g = lane & 3;
  float* out = g_xall + (size_t)(c * 5 + l + 1) * Cc + h * 16 + g;
  out[0]  = acc.x > 0.f ? acc.x : 0.f;
  out[4]  = acc.y > 0.f ? acc.y : 0.f;
  out[8]  = acc.z > 0.f ? acc.z : 0.f;
  out[12] = acc.w > 0.f ? acc.w : 0.f;
}

// ------------------------- 4) emb out + L2 normalize -----------------------
__global__ __launch_bounds__(128) void emb_norm_kernel(float* __restrict__ out_emb) {
  int n = blockIdx.x;
  int c = threadIdx.x;
  float v = g_xall[(n * 5 + 4) * Cc + c];
  out_emb[n * Cc + c] = v;
  float ss = v * v;
#pragma unroll
  for (int off = 16; off; off >>= 1) ss += __shfl_down_sync(0xffffffffu, ss, off);
  __shared__ float ws[4];
  if ((c & 31) == 0) ws[c >> 5] = ss;
  __syncthreads();
  float tot = ws[0] + ws[1] + ws[2] + ws[3];
  float nrm = fmaxf(sqrtf(tot), 1e-8f);
  g_en[n * Cc + c] = v / nrm;
}

// ------------------------- 5) p_lc = log_softmax(emb@W2+b2) ----------------
__global__ __launch_bounds__(128) void plc_kernel(const float* __restrict__ W2,
                                                  const float* __restrict__ b2) {
  int n = blockIdx.x;
  int t = threadIdx.x;
  __shared__ float xr[Cc];
  __shared__ float lg[NCc];
  __shared__ float red[2];
  xr[t] = g_xall[(n * 5 + 4) * Cc + t];
  __syncthreads();
  if (t < NCc) {
    float s = b2[t];
    for (int k = 0; k < Cc; k++) s = fmaf(xr[k], W2[k * NCc + t], s);
    lg[t] = s;
  }
  __syncthreads();
  if (t == 0) {
    float mx = lg[0];
    for (int i = 1; i < NCc; i++) mx = fmaxf(mx, lg[i]);
    float s = 0.f;
    for (int i = 0; i < NCc; i++) s += expf(lg[i] - mx);
    red[0] = mx;
    red[1] = logf(s);
  }
  __syncthreads();
  if (t < NCc) g_plc[n * NCc + t] = lg[t] - red[0] - red[1];
}

// ------------------------- 6) fused sim = en@en^T + top-16 -----------------
// v7 (current best): 512 thr, SROWS=80, grid=125 single wave, ascending tiles,
// rowmax-guard collect. Exact + deterministic.
#define SROWS 80     // rows per block (16 warps x 5 rows)
#define RPW 5
#define SGRID 125    // 125 * 80 = 10000 exactly; single wave on 148 SMs
#define STHREADS 512
#define SCOLS 256
#define CPAD 258
#define CAP 80
#define SIM_SMEM ((128 * CPAD + SROWS * Cc + SROWS * CAP) * 4 + SROWS * CAP * 4 + SROWS * 8)

// exact tie-aware top-16 selection of buf[0..n) into buf[0..15]; updates thr/cnt
__device__ __noinline__ void refresh_row(float* __restrict__ v,
                                         int* __restrict__ ix,
                                         float* __restrict__ thr,
                                         int* __restrict__ cnt,
                                         int rl, int lane) {
  const unsigned FULL = 0xffffffffu;
  int n = cnt[rl];
#pragma unroll 1
  for (int pick = 0; pick < KT; pick++) {
    float mv = -3.4e38f; int mi = 0x7fffffff; int mp = pick;
    for (int s = pick + lane; s < n; s += 32) {
      float vv = v[s]; int ii = ix[s];
      if (vv > mv || (vv == mv && ii < mi)) { mv = vv; mi = ii; mp = s; }
    }
#pragma unroll
    for (int off = 16; off; off >>= 1) {
      float ov = __shfl_down_sync(FULL, mv, off);
      int oi = __shfl_down_sync(FULL, mi, off);
      int op = __shfl_down_sync(FULL, mp, off);
      if (ov > mv || (ov == mv && oi < mi)) { mv = ov; mi = oi; mp = op; }
    }
    mp = __shfl_sync(FULL, mp, 0);
    mv = __shfl_sync(FULL, mv, 0);
    mi = __shfl_sync(FULL, mi, 0);
    if (lane == 0 && mp != pick) {
      float tv = v[pick]; int ti = ix[pick];
      v[pick] = mv; ix[pick] = mi;
      v[mp] = tv; ix[mp] = ti;
    }
    __syncwarp();
  }
  if (lane == 0) { thr[rl] = v[KT - 1]; cnt[rl] = KT; }
  __syncwarp();
}

// one ballot-insert step for a single scalar candidate
#define COLLECT_ONE(val, colofs)                                          \
  do {                                                                    \
    float v_ = (val);                                                     \
    int colx_ = j0 + (colofs) + lane * 2;                                 \
    bool p_ = (colx_ < Nn) && (v_ >= thr_r);                              \
    unsigned mask_ = __ballot_sync(0xffffffffu, p_);                      \
    if (mask_) {                                                          \
      int base_ = cnt[rl];                                                \
      if (p_) {                                                           \
        int pos_ = base_ + __popc(mask_ & ((1u << lane) - 1u));           \
        bv[pos_] = v_;                                                    \
        bi[pos_] = colx_;                                                 \
      }                                                                   \
      int nb_ = base_ + __popc(mask_);                                    \
      if (lane == 0) cnt[rl] = nb_;                                       \
      __syncwarp();                                                       \
      if (nb_ >= CAP - 32) {                                              \
        refresh_row(bv, bi, thr, cnt, rl, lane);                          \
        thr_r = thr[rl];                                                  \
      }                                                                   \
    }                                                                     \
  } while (0)

// candidates for one row: 8 scalars = (c2,t) pairs, values passed by register.
// rowmax guard: skip all 8 ballots when every candidate is below threshold
// (exactly equivalent to 8 empty-mask COLLECT_ONEs).
__device__ __noinline__ void collect_row(int rl, int j0, int lane,
                                         float4 va, float4 vb,
                                         float* __restrict__ bv,
                                         int* __restrict__ bi,
                                         float* __restrict__ thr,
                                         int* __restrict__ cnt) {
  float thr_r = thr[rl];
  float m0 = fmaxf(fmaxf(va.x, va.y), fmaxf(va.z, va.w));
  float m1 = fmaxf(fmaxf(vb.x, vb.y), fmaxf(vb.z, vb.w));
  float rmax = fmaxf(m0, m1);
  unsigned any = __ballot_sync(0xffffffffu, rmax >= thr_r);
  if (!any) return;
  COLLECT_ONE(va.x, 0);        // c2=0, t=0
  COLLECT_ONE(va.y, 1);        // c2=0, t=1
  COLLECT_ONE(va.z, 64);       // c2=1, t=0
  COLLECT_ONE(va.w, 65);       // c2=1, t=1
  COLLECT_ONE(vb.x, 128);      // c2=2, t=0
  COLLECT_ONE(vb.y, 129);      // c2=2, t=1
  COLLECT_ONE(vb.z, 192);      // c2=3, t=0
  COLLECT_ONE(vb.w, 193);      // c2=3, t=1
}

__global__ __launch_bounds__(STHREADS) void sim_topk_kernel() {
  extern __shared__ float sm[];
  float* colsT = sm;                              // [128][CPAD]
  float* rows  = sm + 128 * CPAD;                 // [SROWS][128]
  float* bufv  = rows + SROWS * Cc;               // [SROWS][CAP]
  int*   bufi  = (int*)(bufv + SROWS * CAP);      // [SROWS][CAP]
  float* thr   = (float*)(bufi + SROWS * CAP);    // [SROWS]
  int*   cnt   = (int*)(thr + SROWS);             // [SROWS]

  int r0 = blockIdx.x * SROWS;
  int tid = threadIdx.x;
  int warp = tid >> 5, lane = tid & 31;
  int rlbase = warp * RPW;

  for (int i = tid; i < SROWS * Cc; i += STHREADS) {
    int row = r0 + (i >> 7);
    rows[i] = (row < Nn) ? g_en[row * Cc + (i & 127)] : 0.f;
  }
  if (tid < SROWS) { thr[tid] = -3.3e38f; cnt[tid] = 0; }
  __syncthreads();

  int rlocal = lane >> 3;   // 0..3 (row within 4-row group of fill)
  int kc = lane & 7;        // 0..7 (16B k-chunk within quarter)

  for (int j0 = 0; j0 < Nn; j0 += SCOLS) {
    // ---- fill colsT[k][j] (transposed, coalesced float4 loads) ----
#pragma unroll 4
    for (int it = 0; it < 16; it++) {
      int u = it * 16 + warp;
      int rowgrp = u >> 2, kq = u & 3;
      int j = rowgrp * 4 + rlocal;    // 0..255
      int k4 = kq * 8 + kc;           // 0..31
      int col = j0 + j;
      float4 val = make_float4(0.f, 0.f, 0.f, 0.f);
      if (col < Nn) val = ((const float4*)g_en)[col * (Cc / 4) + k4];
      colsT[(k4 * 4 + 0) * CPAD + j] = val.x;
      colsT[(k4 * 4 + 1) * CPAD + j] = val.y;
      colsT[(k4 * 4 + 2) * CPAD + j] = val.z;
      colsT[(k4 * 4 + 3) * CPAD + j] = val.w;
    }
    __syncthreads();

    // ---- packed f32x2 GEMM: RPW rows x 8 cols (4 pairs) per lane ----
    unsigned long long acc[RPW][4];
#pragma unroll
    for (int r = 0; r < RPW; r++)
#pragma unroll
      for (int c2 = 0; c2 < 4; c2++) acc[r][c2] = 0ULL;

    const float* rowp = rows + rlbase * Cc;
#pragma unroll 4
    for (int k = 0; k < Cc; k++) {
      unsigned long long cv[4];
      const float* cb = colsT + k * CPAD + lane * 2;
#pragma unroll
      for (int c2 = 0; c2 < 4; c2++)
        cv[c2] = *(const unsigned long long*)(cb + c2 * 64);
#pragma unroll
      for (int r = 0; r < RPW; r++) {
        float rv = rowp[r * Cc + k];
        unsigned long long rv2;
        asm("mov.b64 %0, {%1, %1};" : "=l"(rv2) : "f"(rv));
#pragma unroll
        for (int c2 = 0; c2 < 4; c2++)
          asm("fma.rn.f32x2 %0, %1, %2, %0;"
              : "+l"(acc[r][c2]) : "l"(rv2), "l"(cv[c2]));
      }
    }

    // ---- threshold-buffer candidate collection (acc constant-indexed) ----
#pragma unroll
    for (int r = 0; r < RPW; r++) {
      int rl = rlbase + r;
      float4 va, vb;
      asm("mov.b64 {%0, %1}, %2;" : "=f"(va.x), "=f"(va.y) : "l"(acc[r][0]));
      asm("mov.b64 {%0, %1}, %2;" : "=f"(va.z), "=f"(va.w) : "l"(acc[r][1]));
      asm("mov.b64 {%0, %1}, %2;" : "=f"(vb.x), "=f"(vb.y) : "l"(acc[r][2]));
      asm("mov.b64 {%0, %1}, %2;" : "=f"(vb.z), "=f"(vb.w) : "l"(acc[r][3]));
      collect_row(rl, j0, lane, va, vb,
                  bufv + rl * CAP, bufi + rl * CAP, thr, cnt);
    }
    __syncthreads();
  }

  // ---- final exact selection + output ----
#pragma unroll 1
  for (int r = 0; r < RPW; r++) {
    int rl = rlbase + r;
    int grow = r0 + rl;
    if (grow >= Nn) continue;
    refresh_row(bufv + rl * CAP, bufi + rl * CAP, thr, cnt, rl, lane);
    if (lane < KT) {
      g_tval[grow * KT + lane] = bufv[rl * CAP + lane];
      g_tidx[grow * KT + lane] = bufi[rl * CAP + lane];
    }
  }
}

// ------------------------- 7) p_sim + final combine (deterministic) --------
__global__ __launch_bounds__(64) void psim_final_kernel(
    const int* __restrict__ y, float* __restrict__ out_final) {
  int n = blockIdx.x;
  int t = threadIdx.x;
  __shared__ float ex[KT];
  __shared__ int cls[KT];
  __shared__ float acc[NCc];
  __shared__ float red[2];
  if (t < KT) {
    ex[t] = expf(g_tval[n * KT + t]);
    cls[t] = y[g_tidx[n * KT + t]];
  }
  __syncthreads();
  if (t < NCc) {
    float s = 0.f;
    for (int j = 0; j < KT; j++)
      if (cls[j] == t) s += ex[j];
    acc[t] = s;
  }
  __syncthreads();
  if (t == 0) {
    float mx = acc[0];
    for (int i = 1; i < NCc; i++) mx = fmaxf(mx, acc[i]);
    float s = 0.f;
    for (int i = 0; i < NCc; i++) s += expf(acc[i] - mx);
    red[0] = mx;
    red[1] = logf(s);
  }
  __syncthreads();
  if (t < NCc)
    out_final[n * NCc + t] =
        0.5f * g_plc[n * NCc + t] + 0.5f * (acc[t] - red[0] - red[1]);
}

// ------------------------- host launch --------------------------------------
extern "C" void kernel_launch(void* const* d_in, const int* in_sizes, int n_in,
                              void* d_out, int out_size) {
  (void)in_sizes; (void)n_in; (void)out_size;
  const float* x  = (const float*)d_in[0];
  const float* W1 = (const float*)d_in[1];
  const float* b1 = (const float*)d_in[2];
  const float* Wq = (const float*)d_in[3];
  const float* bq = (const float*)d_in[4];
  const float* Wk = (const float*)d_in[5];
  const float* bk = (const float*)d_in[6];
  const float* Wv = (const float*)d_in[7];
  const float* bv = (const float*)d_in[8];
  const float* W2 = (const float*)d_in[9];
  const float* b2 = (const float*)d_in[10];
  const int* ei   = (const int*)d_in[11];
  const int* y    = (const int*)d_in[12];
  const int* rowi = ei;
  const int* coli = ei + Ee;
  float* out_final = (float*)d_out;
  float* out_emb   = (float*)d_out + (size_t)Nn * NCc;

  void* cntp = 0; cudaGetSymbolAddress(&cntp, g_cnt);
  void* curp = 0; cudaGetSymbolAddress(&curp, g_cur);
  cudaFuncSetAttribute(sim_topk_kernel,
                       cudaFuncAttributeMaxDynamicSharedMemorySize, SIM_SMEM);

  cudaMemsetAsync(cntp, 0, Nn * sizeof(int), 0);
  cudaMemsetAsync(curp, 0, Nn * sizeof(int), 0);
  gemm1_relu_kernel<<<(Nn + 63) / 64, 256>>>(x, W1, b1);
  count_kernel<<<(ETOT + 255) / 256, 256>>>(coli);
  dinv_kernel<<<(Nn + 255) / 256, 256>>>();
  norm_kernel<<<(ETOT + 255) / 256, 256>>>(rowi, coli);
  scan_kernel<<<1, 1024>>>();
  place_kernel<<<(ETOT + 255) / 256, 256>>>(coli);
  sort_bucket_kernel<<<(Nn + 127) / 128, 128>>>();

  for (int l = 0; l < NLAY; l++) {
    qkv_kernel<<<Nn, 128>>>(Wq, bq, Wk, bk, Wv, bv, l);
    switch (l) {
      case 0: attn_gather_kernel<1><<<Nn / 4, 128>>>(rowi, l); break;
      case 1: attn_gather_kernel<2><<<Nn / 4, 128>>>(rowi, l); break;
      case 2: attn_gather_kernel<3><<<Nn / 4, 128>>>(rowi, l); break;
      default: attn_gather_kernel<4><<<Nn / 4, 128>>>(rowi, l); break;
    }
  }

  emb_norm_kernel<<<Nn, 128>>>(out_emb);
  plc_kernel<<<Nn, 128>>>(W2, b2);
  sim_topk_kernel<<<SGRID, STHREADS, SIM_SMEM>>>();
  psim_final_kernel<<<Nn, 64>>>(y, out_final);
}

// round 16
// speedup vs baseline: 2.4479x; 1.0107x over previous
#include <cuda_runtime.h>
#include <math.h>

#define Nn 10000
#define Ee 160000
#define ETOT (Ee + Nn)
#define IND 512
#define Cc 128
#define NCc 40
#define NLAY 4
#define HE 8
#define GR 16
#define KT 16
#define DKk 16

// ------------------------- scratch (device globals; no allocations) ---------
__device__ float g_xall[Nn * 5 * Cc];   // x_all levels 0..4
__device__ float g_q[Nn * Cc];          // PERMUTED head layout (see qkv)
__device__ float g_k[Nn * 4 * Cc];      // PERMUTED, levels 0..3
__device__ float g_v[Nn * 4 * Cc];      // PERMUTED
__device__ int   g_cnt[Nn];             // in-degree incl self loop
__device__ float g_dinv[Nn];
__device__ float g_norm[ETOT];
__device__ int   g_off[Nn + 1];
__device__ int   g_cur[Nn];
__device__ int   g_eid[ETOT];
__device__ float g_en[Nn * Cc];
__device__ float g_plc[Nn * NCc];
__device__ float g_tval[Nn * KT];
__device__ int   g_tidx[Nn * KT];

// ------------------------- 1) h0 = relu(x @ W1 + b1) ------------------------
__global__ __launch_bounds__(256) void gemm1_relu_kernel(
    const float* __restrict__ x, const float* __restrict__ W1,
    const float* __restrict__ b1) {
  __shared__ float xs[32][65];    // xs[k][m], 64 rows
  __shared__ float ws[32][128];
  int m0 = blockIdx.x * 64;
  int tid = threadIdx.x;
  int tc = tid & 15;   // 16 col-groups of 8
  int tr = tid >> 4;   // 16 row-groups of 4
  float acc[4][8];
#pragma unroll
  for (int r = 0; r < 4; r++)
#pragma unroll
    for (int c = 0; c < 8; c++) acc[r][c] = 0.f;

  for (int k0 = 0; k0 < IND; k0 += 32) {
    for (int i = tid; i < 64 * 32; i += 256) {
      int m = i >> 5, k = i & 31;
      int row = m0 + m;
      xs[k][m] = (row < Nn) ? x[row * IND + k0 + k] : 0.f;
    }
    for (int i = tid; i < 32 * 128; i += 256) {
      int k = i >> 7, c = i & 127;
      ws[k][c] = W1[(k0 + k) * Cc + c];
    }
    __syncthreads();
#pragma unroll
    for (int k = 0; k < 32; k++) {
      float xv[4], wv[8];
#pragma unroll
      for (int r = 0; r < 4; r++) xv[r] = xs[k][tr * 4 + r];
#pragma unroll
      for (int c = 0; c < 8; c++) wv[c] = ws[k][tc * 8 + c];
#pragma unroll
      for (int r = 0; r < 4; r++)
#pragma unroll
        for (int c = 0; c < 8; c++) acc[r][c] = fmaf(xv[r], wv[c], acc[r][c]);
    }
    __syncthreads();
  }
#pragma unroll
  for (int r = 0; r < 4; r++) {
    int row = m0 + tr * 4 + r;
    if (row < Nn) {
#pragma unroll
      for (int c = 0; c < 8; c++) {
        int col = tc * 8 + c;
        float v = acc[r][c] + b1[col];
        g_xall[row * 5 * Cc + col] = v > 0.f ? v : 0.f;   // level 0
      }
    }
  }
}

// ------------------------- 2) gcn_norm + CSR build (deterministic) ----------
__global__ void count_kernel(const int* __restrict__ coli) {
  int e = blockIdx.x * blockDim.x + threadIdx.x;
  if (e >= ETOT) return;
  int c = (e < Ee) ? coli[e] : (e - Ee);
  atomicAdd(&g_cnt[c], 1);
}

__global__ void dinv_kernel() {
  int n = blockIdx.x * blockDim.x + threadIdx.x;
  if (n < Nn) g_dinv[n] = 1.0f / sqrtf((float)g_cnt[n]);
}

__global__ void norm_kernel(const int* __restrict__ rowi,
                            const int* __restrict__ coli) {
  int e = blockIdx.x * blockDim.x + threadIdx.x;
  if (e >= ETOT) return;
  if (e < Ee) g_norm[e] = g_dinv[rowi[e]] * g_dinv[coli[e]];
  else { float d = g_dinv[e - Ee]; g_norm[e] = d * d; }
}

// single-block exclusive scan of g_cnt -> g_off (1024 threads, 10 elems each)
__global__ __launch_bounds__(1024) void scan_kernel() {
  __shared__ int ssum[1024];
  int t = threadIdx.x;
  int base = t * 10;
  int loc[10];
  int s = 0;
#pragma unroll
  for (int i = 0; i < 10; i++) {
    int idx = base + i;
    int v = (idx < Nn) ? g_cnt[idx] : 0;
    loc[i] = s;
    s += v;
  }
  ssum[t] = s;
  __syncthreads();
  for (int off = 1; off < 1024; off <<= 1) {
    int v = (t >= off) ? ssum[t - off] : 0;
    __syncthreads();
    ssum[t] += v;
    __syncthreads();
  }
  int pre = (t > 0) ? ssum[t - 1] : 0;
#pragma unroll
  for (int i = 0; i < 10; i++) {
    int idx = base + i;
    if (idx < Nn) g_off[idx] = pre + loc[i];
  }
  if (t == 1023) g_off[Nn] = ssum[1023];
}

__global__ void place_kernel(const int* __restrict__ coli) {
  int e = blockIdx.x * blockDim.x + threadIdx.x;
  if (e >= ETOT) return;
  int c = (e < Ee) ? coli[e] : (e - Ee);
  int pos = atomicAdd(&g_cur[c], 1);
  g_eid[g_off[c] + pos] = e;
}

// canonicalize bucket order: insertion-sort each bucket ascending by edge id.
#define SB(i) sbuf[(i) * 128 + tid]
__global__ __launch_bounds__(128) void sort_bucket_kernel() {
  __shared__ int sbuf[64 * 128];
  int tid = threadIdx.x;
  int n = blockIdx.x * 128 + tid;
  if (n >= Nn) return;
  int s = g_off[n], e2 = g_off[n + 1];
  int len = e2 - s;
  if (len <= 64) {
    for (int i = 0; i < len; i++) SB(i) = g_eid[s + i];
    for (int i = 1; i < len; i++) {
      int key = SB(i);
      int j = i - 1;
      while (j >= 0) {
        int v = SB(j);
        if (v <= key) break;
        SB(j + 1) = v;
        j--;
      }
      SB(j + 1) = key;
    }
    for (int i = 0; i < len; i++) g_eid[s + i] = SB(i);
  } else {
    for (int i = s + 1; i < e2; i++) {
      int key = g_eid[i];
      int j = i - 1;
      while (j >= s && g_eid[j] > key) { g_eid[j + 1] = g_eid[j]; j--; }
      g_eid[j + 1] = key;
    }
  }
}

// ------------------------- 3a) grouped q/k/v per layer ---------------------
// PERMUTED head layout stores (see attn). 4 nodes per block: weights/biases
// loaded into registers once, reused across nodes. Per-node compute and
// order identical to the 1-node version -> bit-identical values.
__global__ __launch_bounds__(128) void qkv_kernel(
    const float* __restrict__ Wq, const float* __restrict__ bq,
    const float* __restrict__ Wk, const float* __restrict__ bk,
    const float* __restrict__ Wv, const float* __restrict__ bv, int l) {
  int n0 = blockIdx.x * 4;
  int c = threadIdx.x;
  int g = c >> 3, o = c & 7;
  __shared__ float xs[Cc];
  float wq[8], wk[8], wv[8];
  int base = ((l * GR + g) * 8) * 8 + o;
#pragma unroll
  for (int i = 0; i < 8; i++) {
    wq[i] = Wq[base + i * 8];
    wk[i] = Wk[base + i * 8];
    wv[i] = Wv[base + i * 8];
  }
  int hh = c >> 4, dd = c & 15;
  int pidx = hh * 16 + (dd & 3) * 4 + (dd >> 2);
  float bqv = bq[l * Cc + c], bkv = bk[l * Cc + c], bvv = bv[l * Cc + c];
#pragma unroll 1
  for (int ni = 0; ni < 4; ni++) {
    int n = n0 + ni;
    if (n >= Nn) break;
    for (int lev = 0; lev <= l; lev++) {
      __syncthreads();
      xs[c] = g_xall[(n * 5 + lev) * Cc + c];
      __syncthreads();
      float xg[8];
#pragma unroll
      for (int i = 0; i < 8; i++) xg[i] = xs[g * 8 + i];
      float sk = bkv, sv = bvv;
#pragma unroll
      for (int i = 0; i < 8; i++) {
        sk = fmaf(xg[i], wk[i], sk);
        sv = fmaf(xg[i], wv[i], sv);
      }
      g_k[(n * 4 + lev) * Cc + pidx] = sk;
      g_v[(n * 4 + lev) * Cc + pidx] = sv;
      if (lev == l) {
        float sq = bqv;
#pragma unroll
        for (int i = 0; i < 8; i++) sq = fmaf(xg[i], wq[i], sq);
        g_q[n * Cc + pidx] = sq;
      }
    }
  }
}

// ------------------------- 3b) deterministic attention gather --------------
// One WARP per node; float4 permuted q/k/v; shfl tree bit-identical to the
// original xor8/4/2/1 butterfly (commutative-symmetric in-lane presum).
template <int NLEV>
__device__ __forceinline__ float edge_weight_v(int r, int e, float4 q4,
                                               int lane,
                                               float* __restrict__ sc) {
  const unsigned FULL = 0xffffffffu;
  float nrm = g_norm[e];
  float mx = -1e30f;
#pragma unroll
  for (int lev = 0; lev < NLEV; lev++) {
    float4 k4 = ((const float4*)g_k)[(r * 4 + lev) * (Cc / 4) + lane];
    float tx = q4.x * k4.x, ty = q4.y * k4.y;
    float tz = q4.z * k4.z, tw = q4.w * k4.w;
    float B = (tx + tz) + (ty + tw);
    float C = B + __shfl_xor_sync(FULL, B, 2);
    float D = C + __shfl_xor_sync(FULL, C, 1);
    D *= 0.25f;   // 1/sqrt(DK)
    sc[lev] = D;
    mx = fmaxf(mx, D);
  }
  float den = 0.f;
#pragma unroll
  for (int lev = 0; lev < NLEV; lev++) {
    sc[lev] = expf(sc[lev] - mx);
    den += sc[lev];
  }
  return nrm / den;
}

template <int NLEV>
__global__ __launch_bounds__(128) void attn_gather_kernel(
    const int* __restrict__ rowi, int l) {
  int warp = threadIdx.x >> 5, lane = threadIdx.x & 31;
  int c = blockIdx.x * 4 + warp;
  if (c >= Nn) return;
  float4 q4 = ((const float4*)g_q)[c * (Cc / 4) + lane];
  int s = g_off[c], e2 = g_off[c + 1];
  float4 acc = make_float4(0.f, 0.f, 0.f, 0.f);
  int p = s;
  for (; p + 1 < e2; p += 2) {
    int ea = g_eid[p];
    int eb = g_eid[p + 1];
    int ra = (ea < Ee) ? rowi[ea] : (ea - Ee);
    int rb = (eb < Ee) ? rowi[eb] : (eb - Ee);
    float4 va[NLEV], vb[NLEV];
#pragma unroll
    for (int lev = 0; lev < NLEV; lev++) {
      va[lev] = ((const float4*)g_v)[(ra * 4 + lev) * (Cc / 4) + lane];
      vb[lev] = ((const float4*)g_v)[(rb * 4 + lev) * (Cc / 4) + lane];
    }
    float sca[NLEV], scb[NLEV];
    float wa = edge_weight_v<NLEV>(ra, ea, q4, lane, sca);
    float wb = edge_weight_v<NLEV>(rb, eb, q4, lane, scb);
#pragma unroll
    for (int lev = 0; lev < NLEV; lev++) {
      float wl = sca[lev] * wa;
      acc.x = fmaf(wl, va[lev].x, acc.x);
      acc.y = fmaf(wl, va[lev].y, acc.y);
      acc.z = fmaf(wl, va[lev].z, acc.z);
      acc.w = fmaf(wl, va[lev].w, acc.w);
    }
#pragma unroll
    for (int lev = 0; lev < NLEV; lev++) {
      float wl = scb[lev] * wb;
      acc.x = fmaf(wl, vb[lev].x, acc.x);
      acc.y = fmaf(wl, vb[lev].y, acc.y);
      acc.z = fmaf(wl, vb[lev].z, acc.z);
      acc.w = fmaf(wl, vb[lev].w, acc.w);
    }
  }
  if (p < e2) {
    int e = g_eid[p];
    int r = (e < Ee) ? rowi[e] : (e - Ee);
    float4 vv[NLEV];
#pragma unroll
    for (int lev = 0; lev < NLEV; lev++)
      vv[lev] = ((const float4*)g_v)[(r * 4 + lev) * (Cc / 4) + lane];
    float sc[NLEV];
    float w = edge_weight_v<NLEV>(r, e, q4, lane, sc);
#pragma unroll
    for (int lev = 0; lev < NLEV; lev++) {
      float wl = sc[lev] * w;
      acc.x = fmaf(wl, vv[lev].x, acc.x);
      acc.y = fmaf(wl, vv[lev].y, acc.y);
      acc.z = fmaf(wl, vv[lev].z, acc.z);
      acc.w = fmaf(wl, vv[lev].w, acc.w);
    }
  }
  int h = lane >> 2, g = lane & 3;
  float* out = g_xall + (size_t)(c * 5 + l + 1) * Cc + h * 16 + g;
  out[0]  = acc.x > 0.f ? acc.x : 0.f;
  out[4]  = acc.y > 0.f ? acc.y : 0.f;
  out[8]  = acc.z > 0.f ? acc.z : 0.f;
  out[12] = acc.w > 0.f ? acc.w : 0.f;
}

// ------------------------- 4) emb out + L2 normalize -----------------------
__global__ __launch_bounds__(128) void emb_norm_kernel(float* __restrict__ out_emb) {
  int n = blockIdx.x;
  int c = threadIdx.x;
  float v = g_xall[(n * 5 + 4) * Cc + c];
  out_emb[n * Cc + c] = v;
  float ss = v * v;
#pragma unroll
  for (int off = 16; off; off >>= 1) ss += __shfl_down_sync(0xffffffffu, ss, off);
  __shared__ float ws[4];
  if ((c & 31) == 0) ws[c >> 5] = ss;
  __syncthreads();
  float tot = ws[0] + ws[1] + ws[2] + ws[3];
  float nrm = fmaxf(sqrtf(tot), 1e-8f);
  g_en[n * Cc + c] = v / nrm;
}

// ------------------------- 5) p_lc = log_softmax(emb@W2+b2) ----------------
__global__ __launch_bounds__(128) void plc_kernel(const float* __restrict__ W2,
                                                  const float* __restrict__ b2) {
  int n = blockIdx.x;
  int t = threadIdx.x;
  __shared__ float xr[Cc];
  __shared__ float lg[NCc];
  __shared__ float red[2];
  xr[t] = g_xall[(n * 5 + 4) * Cc + t];
  __syncthreads();
  if (t < NCc) {
    float s = b2[t];
    for (int k = 0; k < Cc; k++) s = fmaf(xr[k], W2[k * NCc + t], s);
    lg[t] = s;
  }
  __syncthreads();
  if (t == 0) {
    float mx = lg[0];
    for (int i = 1; i < NCc; i++) mx = fmaxf(mx, lg[i]);
    float s = 0.f;
    for (int i = 0; i < NCc; i++) s += expf(lg[i] - mx);
    red[0] = mx;
    red[1] = logf(s);
  }
  __syncthreads();
  if (t < NCc) g_plc[n * NCc + t] = lg[t] - red[0] - red[1];
}

// ------------------------- 6) fused sim = en@en^T + top-16 -----------------
// v8: v7 + k-chunked row loads (float4 per 4 k's; replaces 20 LDS.32 with
// 5 LDS.128 per chunk). Same k order, same FMA order -> bit-identical.
#define SROWS 80     // rows per block (16 warps x 5 rows)
#define RPW 5
#define SGRID 125    // 125 * 80 = 10000 exactly; single wave on 148 SMs
#define STHREADS 512
#define SCOLS 256
#define CPAD 258
#define CAP 80
#define SIM_SMEM ((128 * CPAD + SROWS * Cc + SROWS * CAP) * 4 + SROWS * CAP * 4 + SROWS * 8)

// exact tie-aware top-16 selection of buf[0..n) into buf[0..15]; updates thr/cnt
__device__ __noinline__ void refresh_row(float* __restrict__ v,
                                         int* __restrict__ ix,
                                         float* __restrict__ thr,
                                         int* __restrict__ cnt,
                                         int rl, int lane) {
  const unsigned FULL = 0xffffffffu;
  int n = cnt[rl];
#pragma unroll 1
  for (int pick = 0; pick < KT; pick++) {
    float mv = -3.4e38f; int mi = 0x7fffffff; int mp = pick;
    for (int s = pick + lane; s < n; s += 32) {
      float vv = v[s]; int ii = ix[s];
      if (vv > mv || (vv == mv && ii < mi)) { mv = vv; mi = ii; mp = s; }
    }
#pragma unroll
    for (int off = 16; off; off >>= 1) {
      float ov = __shfl_down_sync(FULL, mv, off);
      int oi = __shfl_down_sync(FULL, mi, off);
      int op = __shfl_down_sync(FULL, mp, off);
      if (ov > mv || (ov == mv && oi < mi)) { mv = ov; mi = oi; mp = op; }
    }
    mp = __shfl_sync(FULL, mp, 0);
    mv = __shfl_sync(FULL, mv, 0);
    mi = __shfl_sync(FULL, mi, 0);
    if (lane == 0 && mp != pick) {
      float tv = v[pick]; int ti = ix[pick];
      v[pick] = mv; ix[pick] = mi;
      v[mp] = tv; ix[mp] = ti;
    }
    __syncwarp();
  }
  if (lane == 0) { thr[rl] = v[KT - 1]; cnt[rl] = KT; }
  __syncwarp();
}

// one ballot-insert step for a single scalar candidate
#define COLLECT_ONE(val, colofs)                                          \
  do {                                                                    \
    float v_ = (val);                                                     \
    int colx_ = j0 + (colofs) + lane * 2;                                 \
    bool p_ = (colx_ < Nn) && (v_ >= thr_r);                              \
    unsigned mask_ = __ballot_sync(0xffffffffu, p_);                      \
    if (mask_) {                                                          \
      int base_ = cnt[rl];                                                \
      if (p_) {                                                           \
        int pos_ = base_ + __popc(mask_ & ((1u << lane) - 1u));           \
        bv[pos_] = v_;                                                    \
        bi[pos_] = colx_;                                                 \
      }                                                                   \
      int nb_ = base_ + __popc(mask_);                                    \
      if (lane == 0) cnt[rl] = nb_;                                       \
      __syncwarp();                                                       \
      if (nb_ >= CAP - 32) {                                              \
        refresh_row(bv, bi, thr, cnt, rl, lane);                          \
        thr_r = thr[rl];                                                  \
      }                                                                   \
    }                                                                     \
  } while (0)

// candidates for one row; rowmax guard (bit-identical fast path)
__device__ __noinline__ void collect_row(int rl, int j0, int lane,
                                         float4 va, float4 vb,
                                         float* __restrict__ bv,
                                         int* __restrict__ bi,
                                         float* __restrict__ thr,
                                         int* __restrict__ cnt) {
  float thr_r = thr[rl];
  float m0 = fmaxf(fmaxf(va.x, va.y), fmaxf(va.z, va.w));
  float m1 = fmaxf(fmaxf(vb.x, vb.y), fmaxf(vb.z, vb.w));
  float rmax = fmaxf(m0, m1);
  unsigned any = __ballot_sync(0xffffffffu, rmax >= thr_r);
  if (!any) return;
  COLLECT_ONE(va.x, 0);
  COLLECT_ONE(va.y, 1);
  COLLECT_ONE(va.z, 64);
  COLLECT_ONE(va.w, 65);
  COLLECT_ONE(vb.x, 128);
  COLLECT_ONE(vb.y, 129);
  COLLECT_ONE(vb.z, 192);
  COLLECT_ONE(vb.w, 193);
}

__global__ __launch_bounds__(STHREADS) void sim_topk_kernel() {
  extern __shared__ float sm[];
  float* colsT = sm;                              // [128][CPAD]
  float* rows  = sm + 128 * CPAD;                 // [SROWS][128]
  float* bufv  = rows + SROWS * Cc;               // [SROWS][CAP]
  int*   bufi  = (int*)(bufv + SROWS * CAP);      // [SROWS][CAP]
  float* thr   = (float*)(bufi + SROWS * CAP);    // [SROWS]
  int*   cnt   = (int*)(thr + SROWS);             // [SROWS]

  int r0 = blockIdx.x * SROWS;
  int tid = threadIdx.x;
  int warp = tid >> 5, lane = tid & 31;
  int rlbase = warp * RPW;

  for (int i = tid; i < SROWS * Cc; i += STHREADS) {
    int row = r0 + (i >> 7);
    rows[i] = (row < Nn) ? g_en[row * Cc + (i & 127)] : 0.f;
  }
  if (tid < SROWS) { thr[tid] = -3.3e38f; cnt[tid] = 0; }
  __syncthreads();

  int rlocal = lane >> 3;   // 0..3
  int kc = lane & 7;        // 0..7

  for (int j0 = 0; j0 < Nn; j0 += SCOLS) {
    // ---- fill colsT[k][j] (transposed, coalesced float4 loads) ----
#pragma unroll 4
    for (int it = 0; it < 16; it++) {
      int u = it * 16 + warp;
      int rowgrp = u >> 2, kq = u & 3;
      int j = rowgrp * 4 + rlocal;    // 0..255
      int k4 = kq * 8 + kc;           // 0..31
      int col = j0 + j;
      float4 val = make_float4(0.f, 0.f, 0.f, 0.f);
      if (col < Nn) val = ((const float4*)g_en)[col * (Cc / 4) + k4];
      colsT[(k4 * 4 + 0) * CPAD + j] = val.x;
      colsT[(k4 * 4 + 1) * CPAD + j] = val.y;
      colsT[(k4 * 4 + 2) * CPAD + j] = val.z;
      colsT[(k4 * 4 + 3) * CPAD + j] = val.w;
    }
    __syncthreads();

    // ---- packed f32x2 GEMM, k-chunked row loads ----
    unsigned long long acc[RPW][4];
#pragma unroll
    for (int r = 0; r < RPW; r++)
#pragma unroll
      for (int c2 = 0; c2 < 4; c2++) acc[r][c2] = 0ULL;

    const float* rowp = rows + rlbase * Cc;
#pragma unroll 2
    for (int k0 = 0; k0 < Cc; k0 += 4) {
      float4 rv4[RPW];
#pragma unroll
      for (int r = 0; r < RPW; r++)
        rv4[r] = *(const float4*)(rowp + r * Cc + k0);
#pragma unroll
      for (int kk = 0; kk < 4; kk++) {
        int k = k0 + kk;
        unsigned long long cv[4];
        const float* cb = colsT + k * CPAD + lane * 2;
#pragma unroll
        for (int c2 = 0; c2 < 4; c2++)
          cv[c2] = *(const unsigned long long*)(cb + c2 * 64);
#pragma unroll
        for (int r = 0; r < RPW; r++) {
          float rv = (kk == 0) ? rv4[r].x
                   : (kk == 1) ? rv4[r].y
                   : (kk == 2) ? rv4[r].z : rv4[r].w;
          unsigned long long rv2;
          asm("mov.b64 %0, {%1, %1};" : "=l"(rv2) : "f"(rv));
#pragma unroll
          for (int c2 = 0; c2 < 4; c2++)
            asm("fma.rn.f32x2 %0, %1, %2, %0;"
                : "+l"(acc[r][c2]) : "l"(rv2), "l"(cv[c2]));
        }
      }
    }

    // ---- threshold-buffer candidate collection (acc constant-indexed) ----
#pragma unroll
    for (int r = 0; r < RPW; r++) {
      int rl = rlbase + r;
      float4 va, vb;
      asm("mov.b64 {%0, %1}, %2;" : "=f"(va.x), "=f"(va.y) : "l"(acc[r][0]));
      asm("mov.b64 {%0, %1}, %2;" : "=f"(va.z), "=f"(va.w) : "l"(acc[r][1]));
      asm("mov.b64 {%0, %1}, %2;" : "=f"(vb.x), "=f"(vb.y) : "l"(acc[r][2]));
      asm("mov.b64 {%0, %1}, %2;" : "=f"(vb.z), "=f"(vb.w) : "l"(acc[r][3]));
      collect_row(rl, j0, lane, va, vb,
                  bufv + rl * CAP, bufi + rl * CAP, thr, cnt);
    }
    __syncthreads();
  }

  // ---- final exact selection + output ----
#pragma unroll 1
  for (int r = 0; r < RPW; r++) {
    int rl = rlbase + r;
    int grow = r0 + rl;
    if (grow >= Nn) continue;
    refresh_row(bufv + rl * CAP, bufi + rl * CAP, thr, cnt, rl, lane);
    if (lane < KT) {
      g_tval[grow * KT + lane] = bufv[rl * CAP + lane];
      g_tidx[grow * KT + lane] = bufi[rl * CAP + lane];
    }
  }
}

// ------------------------- 7) p_sim + final combine (deterministic) --------
__global__ __launch_bounds__(64) void psim_final_kernel(
    const int* __restrict__ y, float* __restrict__ out_final) {
  int n = blockIdx.x;
  int t = threadIdx.x;
  __shared__ float ex[KT];
  __shared__ int cls[KT];
  __shared__ float acc[NCc];
  __shared__ float red[2];
  if (t < KT) {
    ex[t] = expf(g_tval[n * KT + t]);
    cls[t] = y[g_tidx[n * KT + t]];
  }
  __syncthreads();
  if (t < NCc) {
    float s = 0.f;
    for (int j = 0; j < KT; j++)
      if (cls[j] == t) s += ex[j];
    acc[t] = s;
  }
  __syncthreads();
  if (t == 0) {
    float mx = acc[0];
    for (int i = 1; i < NCc; i++) mx = fmaxf(mx, acc[i]);
    float s = 0.f;
    for (int i = 0; i < NCc; i++) s += expf(acc[i] - mx);
    red[0] = mx;
    red[1] = logf(s);
  }
  __syncthreads();
  if (t < NCc)
    out_final[n * NCc + t] =
        0.5f * g_plc[n * NCc + t] + 0.5f * (acc[t] - red[0] - red[1]);
}

// ------------------------- host launch --------------------------------------
extern "C" void kernel_launch(void* const* d_in, const int* in_sizes, int n_in,
                              void* d_out, int out_size) {
  (void)in_sizes; (void)n_in; (void)out_size;
  const float* x  = (const float*)d_in[0];
  const float* W1 = (const float*)d_in[1];
  const float* b1 = (const float*)d_in[2];
  const float* Wq = (const float*)d_in[3];
  const float* bq = (const float*)d_in[4];
  const float* Wk = (const float*)d_in[5];
  const float* bk = (const float*)d_in[6];
  const float* Wv = (const float*)d_in[7];
  const float* bv = (const float*)d_in[8];
  const float* W2 = (const float*)d_in[9];
  const float* b2 = (const float*)d_in[10];
  const int* ei   = (const int*)d_in[11];
  const int* y    = (const int*)d_in[12];
  const int* rowi = ei;
  const int* coli = ei + Ee;
  float* out_final = (float*)d_out;
  float* out_emb   = (float*)d_out + (size_t)Nn * NCc;

  void* cntp = 0; cudaGetSymbolAddress(&cntp, g_cnt);
  void* curp = 0; cudaGetSymbolAddress(&curp, g_cur);
  cudaFuncSetAttribute(sim_topk_kernel,
                       cudaFuncAttributeMaxDynamicSharedMemorySize, SIM_SMEM);

  cudaMemsetAsync(cntp, 0, Nn * sizeof(int), 0);
  cudaMemsetAsync(curp, 0, Nn * sizeof(int), 0);
  gemm1_relu_kernel<<<(Nn + 63) / 64, 256>>>(x, W1, b1);
  count_kernel<<<(ETOT + 255) / 256, 256>>>(coli);
  dinv_kernel<<<(Nn + 255) / 256, 256>>>();
  norm_kernel<<<(ETOT + 255) / 256, 256>>>(rowi, coli);
  scan_kernel<<<1, 1024>>>();
  place_kernel<<<(ETOT + 255) / 256, 256>>>(coli);
  sort_bucket_kernel<<<(Nn + 127) / 128, 128>>>();

  for (int l = 0; l < NLAY; l++) {
    qkv_kernel<<<(Nn + 3) / 4, 128>>>(Wq, bq, Wk, bk, Wv, bv, l);
    switch (l) {
      case 0: attn_gather_kernel<1><<<Nn / 4, 128>>>(rowi, l); break;
      case 1: attn_gather_kernel<2><<<Nn / 4, 128>>>(rowi, l); break;
      case 2: attn_gather_kernel<3><<<Nn / 4, 128>>>(rowi, l); break;
      default: attn_gather_kernel<4><<<Nn / 4, 128>>>(rowi, l); break;
    }
  }

  emb_norm_kernel<<<Nn, 128>>>(out_emb);
  plc_kernel<<<Nn, 128>>>(W2, b2);
  sim_topk_kernel<<<SGRID, STHREADS, SIM_SMEM>>>();
  psim_final_kernel<<<Nn, 64>>>(y, out_final);
}